// round 1
// baseline (speedup 1.0000x reference)
#include <cuda_runtime.h>
#include <math.h>

#define N_EMBD   1024
#define N_HEAD   16
#define HEAD_DIM 64
#define BATCH    2
#define SEQ      2048
#define M_TOT    (BATCH * SEQ)

// ---------------- scratch (device globals: allocation-free) ----------------
__device__ float g_q[(size_t)M_TOT * N_EMBD];
__device__ float g_k[(size_t)M_TOT * N_EMBD];
__device__ float g_v[(size_t)M_TOT * N_EMBD];
__device__ float g_att[(size_t)M_TOT * N_EMBD];

// ---------------- GEMM: C[M,N] = A[M,K] @ B[N,K]^T + bias[N] ----------------
#define BM 64
#define BN 64
#define BK 16

__global__ __launch_bounds__(256) void gemm_bias_kernel(
    const float* __restrict__ A, const float* __restrict__ B,
    const float* __restrict__ bias, float* __restrict__ C,
    int M, int N, int K)
{
    __shared__ __align__(16) float As[BK][BM];
    __shared__ __align__(16) float Bs[BK][BN];

    const int tid = threadIdx.x;
    const int tx = tid & 15;        // 0..15 -> n sub-tile
    const int ty = tid >> 4;        // 0..15 -> m sub-tile
    const int m0 = blockIdx.y * BM;
    const int n0 = blockIdx.x * BN;

    float acc[4][4] = {};

    for (int k0 = 0; k0 < K; k0 += BK) {
        // cooperative load: 64x16 A tile + 64x16 B tile, coalesced along K
        #pragma unroll
        for (int i = tid; i < BM * BK; i += 256) {
            int c = i & (BK - 1);
            int r = i >> 4;
            As[c][r] = A[(size_t)(m0 + r) * K + k0 + c];
            Bs[c][r] = B[(size_t)(n0 + r) * K + k0 + c];
        }
        __syncthreads();

        #pragma unroll
        for (int kk = 0; kk < BK; kk++) {
            float4 a4 = *(const float4*)&As[kk][ty * 4];
            float4 b4 = *(const float4*)&Bs[kk][tx * 4];
            float a[4] = {a4.x, a4.y, a4.z, a4.w};
            float b[4] = {b4.x, b4.y, b4.z, b4.w};
            #pragma unroll
            for (int i = 0; i < 4; i++)
                #pragma unroll
                for (int j = 0; j < 4; j++)
                    acc[i][j] += a[i] * b[j];
        }
        __syncthreads();
    }

    #pragma unroll
    for (int i = 0; i < 4; i++) {
        #pragma unroll
        for (int j = 0; j < 4; j++) {
            int n = n0 + tx * 4 + j;
            C[(size_t)(m0 + ty * 4 + i) * N + n] = acc[i][j] + bias[n];
        }
    }
}

// ---------------- causal flash attention ----------------
// 1 thread = 1 query row. q-row + accumulator in registers, K/V tiles in smem
// (broadcast float4 LDS), online softmax.
#define QROWS 128
#define KT 32

__global__ __launch_bounds__(128) void attn_kernel(
    const float* __restrict__ q, const float* __restrict__ k,
    const float* __restrict__ v, float* __restrict__ o)
{
    __shared__ __align__(16) float ks[KT * HEAD_DIM];
    __shared__ __align__(16) float vs[KT * HEAD_DIM];

    const int tid   = threadIdx.x;
    const int qbase = blockIdx.x * QROWS;
    const int qi    = qbase + tid;
    const int bh    = blockIdx.y;
    const int b     = bh / N_HEAD;
    const int h     = bh % N_HEAD;

    const float* qrow = q + ((size_t)(b * SEQ + qi)) * N_EMBD + h * HEAD_DIM;
    float qr[HEAD_DIM];
    #pragma unroll
    for (int i4 = 0; i4 < HEAD_DIM / 4; i4++) {
        float4 t = *(const float4*)&qrow[i4 * 4];
        qr[i4 * 4 + 0] = t.x * 0.125f;   // 1/sqrt(64)
        qr[i4 * 4 + 1] = t.y * 0.125f;
        qr[i4 * 4 + 2] = t.z * 0.125f;
        qr[i4 * 4 + 3] = t.w * 0.125f;
    }

    float acc[HEAD_DIM] = {};
    float m = -INFINITY, l = 0.f;

    const int ntiles = (qbase + QROWS - 1) / KT + 1;
    for (int t = 0; t < ntiles; t++) {
        const int j0 = t * KT;

        // cooperative K/V tile load (float4, coalesced)
        #pragma unroll
        for (int i4 = tid; i4 < KT * HEAD_DIM / 4; i4 += 128) {
            int jr = i4 / (HEAD_DIM / 4);
            int dd = i4 % (HEAD_DIM / 4);
            size_t base = ((size_t)(b * SEQ + j0 + jr)) * N_EMBD + h * HEAD_DIM + dd * 4;
            ((float4*)ks)[i4] = *(const float4*)&k[base];
            ((float4*)vs)[i4] = *(const float4*)&v[base];
        }
        __syncthreads();

        if (j0 <= qi) {
            float s[KT];
            float tm = m;
            #pragma unroll
            for (int j = 0; j < KT; j++) {
                float sj = 0.f;
                #pragma unroll
                for (int i4 = 0; i4 < HEAD_DIM / 4; i4++) {
                    float4 k4 = *(const float4*)&ks[j * HEAD_DIM + i4 * 4];
                    sj += qr[i4 * 4 + 0] * k4.x;
                    sj += qr[i4 * 4 + 1] * k4.y;
                    sj += qr[i4 * 4 + 2] * k4.z;
                    sj += qr[i4 * 4 + 3] * k4.w;
                }
                sj = (j0 + j <= qi) ? sj : -INFINITY;
                s[j] = sj;
                tm = fmaxf(tm, sj);
            }

            float scale = __expf(m - tm);   // exp(-inf - finite) = 0 on first tile
            l *= scale;
            #pragma unroll
            for (int d = 0; d < HEAD_DIM; d++) acc[d] *= scale;

            #pragma unroll
            for (int j = 0; j < KT; j++) {
                float p = __expf(s[j] - tm);  // masked lanes -> exp(-inf)=0
                l += p;
                #pragma unroll
                for (int d4 = 0; d4 < HEAD_DIM / 4; d4++) {
                    float4 v4 = *(const float4*)&vs[j * HEAD_DIM + d4 * 4];
                    acc[d4 * 4 + 0] += p * v4.x;
                    acc[d4 * 4 + 1] += p * v4.y;
                    acc[d4 * 4 + 2] += p * v4.z;
                    acc[d4 * 4 + 3] += p * v4.w;
                }
            }
            m = tm;
        }
        __syncthreads();
    }

    const float inv = 1.f / l;
    float* op = o + ((size_t)(b * SEQ + qi)) * N_EMBD + h * HEAD_DIM;
    #pragma unroll
    for (int d = 0; d < HEAD_DIM; d++) op[d] = acc[d] * inv;
}

// ---------------- launch ----------------
extern "C" void kernel_launch(void* const* d_in, const int* in_sizes, int n_in,
                              void* d_out, int out_size)
{
    const float* x  = (const float*)d_in[0];
    const float* Wq = (const float*)d_in[1];
    const float* bq = (const float*)d_in[2];
    const float* Wk = (const float*)d_in[3];
    const float* bk = (const float*)d_in[4];
    const float* Wv = (const float*)d_in[5];
    const float* bv = (const float*)d_in[6];
    const float* Wo = (const float*)d_in[7];
    const float* bo = (const float*)d_in[8];
    float* out = (float*)d_out;

    float *qp, *kp, *vp, *ap;
    cudaGetSymbolAddress((void**)&qp, g_q);
    cudaGetSymbolAddress((void**)&kp, g_k);
    cudaGetSymbolAddress((void**)&vp, g_v);
    cudaGetSymbolAddress((void**)&ap, g_att);

    dim3 ggrid(N_EMBD / BN, M_TOT / BM);   // (16, 64)

    gemm_bias_kernel<<<ggrid, 256>>>(x, Wq, bq, qp, M_TOT, N_EMBD, N_EMBD);
    gemm_bias_kernel<<<ggrid, 256>>>(x, Wk, bk, kp, M_TOT, N_EMBD, N_EMBD);
    gemm_bias_kernel<<<ggrid, 256>>>(x, Wv, bv, vp, M_TOT, N_EMBD, N_EMBD);

    dim3 agrid(SEQ / QROWS, BATCH * N_HEAD);  // (16, 32)
    attn_kernel<<<agrid, 128>>>(qp, kp, vp, ap);

    gemm_bias_kernel<<<ggrid, 256>>>(ap, Wo, bo, out, M_TOT, N_EMBD, N_EMBD);
}

// round 2
// speedup vs baseline: 1.1463x; 1.1463x over previous
#include <cuda_runtime.h>
#include <math.h>

#define N_EMBD   1024
#define N_HEAD   16
#define HEAD_DIM 64
#define BATCH    2
#define SEQ      2048
#define M_TOT    (BATCH * SEQ)

// ---------------- scratch (device globals: allocation-free) ----------------
__device__ float g_q[(size_t)M_TOT * N_EMBD];
__device__ float g_k[(size_t)M_TOT * N_EMBD];
__device__ float g_v[(size_t)M_TOT * N_EMBD];
__device__ float g_att[(size_t)M_TOT * N_EMBD];

// ================= GEMM: C[M,N] = A[M,K] @ B[N,K]^T + bias[N] ==============
// 128x128 tile, BK=16, 256 threads, 8x8 per thread, double-buffered smem.
#define GBM 128
#define GBN 128
#define GBK 16
#define GPAD 4

__global__ __launch_bounds__(256) void gemm_bias_kernel(
    const float* __restrict__ A, const float* __restrict__ B,
    const float* __restrict__ bias, float* __restrict__ C,
    int M, int N, int K)
{
    __shared__ __align__(16) float As[2][GBK][GBM + GPAD];
    __shared__ __align__(16) float Bs[2][GBK][GBN + GPAD];

    const int tid = threadIdx.x;
    const int m0 = blockIdx.y * GBM;
    const int n0 = blockIdx.x * GBN;

    // load mapping: thread covers rows (lr, lr+64) at cols lc..lc+3 of the 16-wide K slab
    const int lr = tid >> 2;         // 0..63
    const int lc = (tid & 3) * 4;    // 0,4,8,12

    const float* Aptr = A + (size_t)(m0 + lr) * K + lc;
    const float* Bptr = B + (size_t)(n0 + lr) * K + lc;
    const size_t rowK64 = (size_t)64 * K;

    float4 a0, a1, b0, b1;

    // prologue: load k-slab 0
    a0 = *(const float4*)(Aptr);
    a1 = *(const float4*)(Aptr + rowK64);
    b0 = *(const float4*)(Bptr);
    b1 = *(const float4*)(Bptr + rowK64);

    {
        float av0[4] = {a0.x, a0.y, a0.z, a0.w};
        float av1[4] = {a1.x, a1.y, a1.z, a1.w};
        float bv0[4] = {b0.x, b0.y, b0.z, b0.w};
        float bv1[4] = {b1.x, b1.y, b1.z, b1.w};
        #pragma unroll
        for (int w = 0; w < 4; w++) {
            As[0][lc + w][lr]      = av0[w];
            As[0][lc + w][lr + 64] = av1[w];
            Bs[0][lc + w][lr]      = bv0[w];
            Bs[0][lc + w][lr + 64] = bv1[w];
        }
    }
    __syncthreads();

    const int ty = tid >> 4;   // 0..15
    const int tx = tid & 15;   // 0..15

    float acc[8][8] = {};

    const int nt = K / GBK;
    for (int kt = 0; kt < nt; kt++) {
        const int cur = kt & 1;

        if (kt + 1 < nt) {
            const float* Ap = Aptr + (size_t)(kt + 1) * GBK;
            const float* Bp = Bptr + (size_t)(kt + 1) * GBK;
            a0 = *(const float4*)(Ap);
            a1 = *(const float4*)(Ap + rowK64);
            b0 = *(const float4*)(Bp);
            b1 = *(const float4*)(Bp + rowK64);
        }

        #pragma unroll
        for (int kk = 0; kk < GBK; kk++) {
            float4 av0 = *(const float4*)&As[cur][kk][ty * 4];
            float4 av1 = *(const float4*)&As[cur][kk][ty * 4 + 64];
            float4 bv0 = *(const float4*)&Bs[cur][kk][tx * 4];
            float4 bv1 = *(const float4*)&Bs[cur][kk][tx * 4 + 64];
            float a[8] = {av0.x, av0.y, av0.z, av0.w, av1.x, av1.y, av1.z, av1.w};
            float b[8] = {bv0.x, bv0.y, bv0.z, bv0.w, bv1.x, bv1.y, bv1.z, bv1.w};
            #pragma unroll
            for (int i = 0; i < 8; i++)
                #pragma unroll
                for (int j = 0; j < 8; j++)
                    acc[i][j] += a[i] * b[j];
        }

        if (kt + 1 < nt) {
            const int nxt = cur ^ 1;
            float av0[4] = {a0.x, a0.y, a0.z, a0.w};
            float av1[4] = {a1.x, a1.y, a1.z, a1.w};
            float bv0[4] = {b0.x, b0.y, b0.z, b0.w};
            float bv1[4] = {b1.x, b1.y, b1.z, b1.w};
            #pragma unroll
            for (int w = 0; w < 4; w++) {
                As[nxt][lc + w][lr]      = av0[w];
                As[nxt][lc + w][lr + 64] = av1[w];
                Bs[nxt][lc + w][lr]      = bv0[w];
                Bs[nxt][lc + w][lr + 64] = bv1[w];
            }
            __syncthreads();
        }
    }

    // epilogue: bias + vectorized stores
    float bj[8];
    #pragma unroll
    for (int j = 0; j < 8; j++) {
        int n = n0 + tx * 4 + ((j < 4) ? j : 64 + (j - 4));
        bj[j] = bias[n];
    }
    #pragma unroll
    for (int i = 0; i < 8; i++) {
        int row = m0 + ty * 4 + ((i < 4) ? i : 64 + (i - 4));
        float4 lo = make_float4(acc[i][0] + bj[0], acc[i][1] + bj[1],
                                acc[i][2] + bj[2], acc[i][3] + bj[3]);
        float4 hi = make_float4(acc[i][4] + bj[4], acc[i][5] + bj[5],
                                acc[i][6] + bj[6], acc[i][7] + bj[7]);
        *(float4*)&C[(size_t)row * N + n0 + tx * 4]      = lo;
        *(float4*)&C[(size_t)row * N + n0 + tx * 4 + 64] = hi;
    }
}

// ================= causal flash attention ==================================
// 256 threads/block, 128 queries/block: each query handled by a lane PAIR,
// each lane owning 32 of the 64 dims as interleaved float4 chunks
// (chunk c = 2*i + half, i=0..7) so pair LDS addresses are 16B apart
// (one 128B wavefront, conflict-free). Score = partial dot + shfl_xor(1).
#define AQ  128
#define AKT 32

__global__ __launch_bounds__(256) void attn_kernel(
    const float* __restrict__ q, const float* __restrict__ k,
    const float* __restrict__ v, float* __restrict__ o)
{
    __shared__ __align__(16) float ks[AKT * HEAD_DIM];
    __shared__ __align__(16) float vs[AKT * HEAD_DIM];

    const int tid   = threadIdx.x;
    const int half  = tid & 1;
    const int ql    = tid >> 1;
    const int qbase = blockIdx.x * AQ;
    const int qi    = qbase + ql;
    const int bh    = blockIdx.y;
    const int b     = bh / N_HEAD;
    const int h     = bh % N_HEAD;

    // load this lane's 32 dims of q (8 interleaved float4 chunks), pre-scaled
    const float* qrow = q + ((size_t)(b * SEQ + qi)) * N_EMBD + h * HEAD_DIM;
    float qr[32];
    #pragma unroll
    for (int i = 0; i < 8; i++) {
        float4 t = *(const float4*)&qrow[(2 * i + half) * 4];
        qr[i * 4 + 0] = t.x * 0.125f;
        qr[i * 4 + 1] = t.y * 0.125f;
        qr[i * 4 + 2] = t.z * 0.125f;
        qr[i * 4 + 3] = t.w * 0.125f;
    }

    float acc[32] = {};
    float m = -1e30f, l = 0.f;

    const int ntiles = qbase / AKT + AQ / AKT;   // covers j <= qbase+127
    for (int t = 0; t < ntiles; t++) {
        const int j0 = t * AKT;

        // cooperative K/V tile load (512 float4 each / 256 threads)
        #pragma unroll
        for (int i4 = tid; i4 < AKT * HEAD_DIM / 4; i4 += 256) {
            int jr = i4 >> 4;
            int dd = i4 & 15;
            size_t base = ((size_t)(b * SEQ + j0 + jr)) * N_EMBD + h * HEAD_DIM + dd * 4;
            ((float4*)ks)[i4] = *(const float4*)&k[base];
            ((float4*)vs)[i4] = *(const float4*)&v[base];
        }
        __syncthreads();

        float s[AKT];
        float tm = m;
        #pragma unroll
        for (int j = 0; j < AKT; j++) {
            float p0 = 0.f, p1 = 0.f, p2 = 0.f, p3 = 0.f;
            #pragma unroll
            for (int i = 0; i < 8; i += 4) {
                float4 k0 = *(const float4*)&ks[j * HEAD_DIM + (2 * (i + 0) + half) * 4];
                float4 k1 = *(const float4*)&ks[j * HEAD_DIM + (2 * (i + 1) + half) * 4];
                float4 k2 = *(const float4*)&ks[j * HEAD_DIM + (2 * (i + 2) + half) * 4];
                float4 k3 = *(const float4*)&ks[j * HEAD_DIM + (2 * (i + 3) + half) * 4];
                p0 += qr[(i+0)*4+0]*k0.x + qr[(i+0)*4+1]*k0.y + qr[(i+0)*4+2]*k0.z + qr[(i+0)*4+3]*k0.w;
                p1 += qr[(i+1)*4+0]*k1.x + qr[(i+1)*4+1]*k1.y + qr[(i+1)*4+2]*k1.z + qr[(i+1)*4+3]*k1.w;
                p2 += qr[(i+2)*4+0]*k2.x + qr[(i+2)*4+1]*k2.y + qr[(i+2)*4+2]*k2.z + qr[(i+2)*4+3]*k2.w;
                p3 += qr[(i+3)*4+0]*k3.x + qr[(i+3)*4+1]*k3.y + qr[(i+3)*4+2]*k3.z + qr[(i+3)*4+3]*k3.w;
            }
            float sj = (p0 + p1) + (p2 + p3);
            sj += __shfl_xor_sync(0xffffffffu, sj, 1);   // pair-sum over dims
            sj = (j0 + j <= qi) ? sj : -INFINITY;        // causal mask
            s[j] = sj;
            tm = fmaxf(tm, sj);
        }

        float scale = __expf(m - tm);    // m,tm finite: no NaN path
        l *= scale;
        #pragma unroll
        for (int d = 0; d < 32; d++) acc[d] *= scale;

        #pragma unroll
        for (int j = 0; j < AKT; j++) {
            float p = __expf(s[j] - tm); // masked -> exp(-inf)=0
            l += p;
            #pragma unroll
            for (int i = 0; i < 8; i++) {
                float4 v4 = *(const float4*)&vs[j * HEAD_DIM + (2 * i + half) * 4];
                acc[i * 4 + 0] += p * v4.x;
                acc[i * 4 + 1] += p * v4.y;
                acc[i * 4 + 2] += p * v4.z;
                acc[i * 4 + 3] += p * v4.w;
            }
        }
        m = tm;
        __syncthreads();
    }

    const float inv = 1.f / l;
    float* op = o + ((size_t)(b * SEQ + qi)) * N_EMBD + h * HEAD_DIM;
    #pragma unroll
    for (int i = 0; i < 8; i++) {
        float4 r = make_float4(acc[i*4+0] * inv, acc[i*4+1] * inv,
                               acc[i*4+2] * inv, acc[i*4+3] * inv);
        *(float4*)&op[(2 * i + half) * 4] = r;
    }
}

// ---------------- launch ----------------
extern "C" void kernel_launch(void* const* d_in, const int* in_sizes, int n_in,
                              void* d_out, int out_size)
{
    const float* x  = (const float*)d_in[0];
    const float* Wq = (const float*)d_in[1];
    const float* bq = (const float*)d_in[2];
    const float* Wk = (const float*)d_in[3];
    const float* bk = (const float*)d_in[4];
    const float* Wv = (const float*)d_in[5];
    const float* bv = (const float*)d_in[6];
    const float* Wo = (const float*)d_in[7];
    const float* bo = (const float*)d_in[8];
    float* out = (float*)d_out;

    float *qp, *kp, *vp, *ap;
    cudaGetSymbolAddress((void**)&qp, g_q);
    cudaGetSymbolAddress((void**)&kp, g_k);
    cudaGetSymbolAddress((void**)&vp, g_v);
    cudaGetSymbolAddress((void**)&ap, g_att);

    dim3 ggrid(N_EMBD / GBN, M_TOT / GBM);   // (8, 32)

    gemm_bias_kernel<<<ggrid, 256>>>(x, Wq, bq, qp, M_TOT, N_EMBD, N_EMBD);
    gemm_bias_kernel<<<ggrid, 256>>>(x, Wk, bk, kp, M_TOT, N_EMBD, N_EMBD);
    gemm_bias_kernel<<<ggrid, 256>>>(x, Wv, bv, vp, M_TOT, N_EMBD, N_EMBD);

    dim3 agrid(SEQ / AQ, BATCH * N_HEAD);    // (16, 32)
    attn_kernel<<<agrid, 256>>>(qp, kp, vp, ap);

    gemm_bias_kernel<<<ggrid, 256>>>(ap, Wo, bo, out, M_TOT, N_EMBD, N_EMBD);
}

// round 3
// speedup vs baseline: 2.1591x; 1.8836x over previous
#include <cuda_runtime.h>
#include <math.h>

#define N_EMBD   1024
#define N_HEAD   16
#define HEAD_DIM 64
#define BATCH    2
#define SEQ      2048
#define M_TOT    (BATCH * SEQ)

typedef unsigned long long u64;

// ---------------- packed f32x2 helpers (sm_103a) ----------------
__device__ __forceinline__ u64 pack2(float x, float y) {
    u64 d; asm("mov.b64 %0, {%1, %2};" : "=l"(d) : "f"(x), "f"(y)); return d;
}
__device__ __forceinline__ u64 splat2(float x) {
    u64 d; asm("mov.b64 %0, {%1, %1};" : "=l"(d) : "f"(x)); return d;
}
__device__ __forceinline__ void unpack2(u64 v, float& x, float& y) {
    asm("mov.b64 {%0, %1}, %2;" : "=f"(x), "=f"(y) : "l"(v));
}
__device__ __forceinline__ u64 fma2(u64 a, u64 b, u64 c) {
    u64 d; asm("fma.rn.f32x2 %0, %1, %2, %3;" : "=l"(d) : "l"(a), "l"(b), "l"(c)); return d;
}
__device__ __forceinline__ u64 add2(u64 a, u64 b) {
    u64 d; asm("add.rn.f32x2 %0, %1, %2;" : "=l"(d) : "l"(a), "l"(b)); return d;
}
__device__ __forceinline__ u64 mul2(u64 a, u64 b) {
    u64 d; asm("mul.rn.f32x2 %0, %1, %2;" : "=l"(d) : "l"(a), "l"(b)); return d;
}

// ---------------- scratch (device globals: allocation-free) ----------------
__device__ float g_q[(size_t)M_TOT * N_EMBD];
__device__ float g_k[(size_t)M_TOT * N_EMBD];
__device__ float g_v[(size_t)M_TOT * N_EMBD];
__device__ float g_att[(size_t)M_TOT * N_EMBD];

// ================= GEMM: C[M,N] = A[M,K] @ B[N,K]^T + bias[N] ==============
// 128x128 tile, BK=16, 256 threads, 8x8 per thread, double-buffered smem,
// packed f32x2 inner product (32 FFMA2 + 8 splats per kk instead of 64 FFMA).
#define GBM 128
#define GBN 128
#define GBK 16
#define GPAD 4

__global__ __launch_bounds__(256) void gemm_bias_kernel(
    const float* __restrict__ A, const float* __restrict__ B,
    const float* __restrict__ bias, float* __restrict__ C,
    int M, int N, int K)
{
    __shared__ __align__(16) float As[2][GBK][GBM + GPAD];
    __shared__ __align__(16) float Bs[2][GBK][GBN + GPAD];

    const int tid = threadIdx.x;
    const int m0 = blockIdx.y * GBM;
    const int n0 = blockIdx.x * GBN;

    const int lr = tid >> 2;         // 0..63
    const int lc = (tid & 3) * 4;    // 0,4,8,12

    const float* Aptr = A + (size_t)(m0 + lr) * K + lc;
    const float* Bptr = B + (size_t)(n0 + lr) * K + lc;
    const size_t rowK64 = (size_t)64 * K;

    float4 a0, a1, b0, b1;

    a0 = *(const float4*)(Aptr);
    a1 = *(const float4*)(Aptr + rowK64);
    b0 = *(const float4*)(Bptr);
    b1 = *(const float4*)(Bptr + rowK64);

    {
        float av0[4] = {a0.x, a0.y, a0.z, a0.w};
        float av1[4] = {a1.x, a1.y, a1.z, a1.w};
        float bv0[4] = {b0.x, b0.y, b0.z, b0.w};
        float bv1[4] = {b1.x, b1.y, b1.z, b1.w};
        #pragma unroll
        for (int w = 0; w < 4; w++) {
            As[0][lc + w][lr]      = av0[w];
            As[0][lc + w][lr + 64] = av1[w];
            Bs[0][lc + w][lr]      = bv0[w];
            Bs[0][lc + w][lr + 64] = bv1[w];
        }
    }
    __syncthreads();

    const int ty = tid >> 4;   // 0..15
    const int tx = tid & 15;   // 0..15

    u64 acc2[8][4];
    #pragma unroll
    for (int i = 0; i < 8; i++)
        #pragma unroll
        for (int j = 0; j < 4; j++) acc2[i][j] = 0ULL;

    const int nt = K / GBK;
    for (int kt = 0; kt < nt; kt++) {
        const int cur = kt & 1;

        if (kt + 1 < nt) {
            const float* Ap = Aptr + (size_t)(kt + 1) * GBK;
            const float* Bp = Bptr + (size_t)(kt + 1) * GBK;
            a0 = *(const float4*)(Ap);
            a1 = *(const float4*)(Ap + rowK64);
            b0 = *(const float4*)(Bp);
            b1 = *(const float4*)(Bp + rowK64);
        }

        #pragma unroll
        for (int kk = 0; kk < GBK; kk++) {
            float4 av0 = *(const float4*)&As[cur][kk][ty * 4];
            float4 av1 = *(const float4*)&As[cur][kk][ty * 4 + 64];
            ulonglong2 bl0 = *(const ulonglong2*)&Bs[cur][kk][tx * 4];
            ulonglong2 bl1 = *(const ulonglong2*)&Bs[cur][kk][tx * 4 + 64];
            u64 bp[4] = {bl0.x, bl0.y, bl1.x, bl1.y};
            float a[8] = {av0.x, av0.y, av0.z, av0.w, av1.x, av1.y, av1.z, av1.w};
            #pragma unroll
            for (int i = 0; i < 8; i++) {
                u64 ai = splat2(a[i]);
                #pragma unroll
                for (int j = 0; j < 4; j++)
                    acc2[i][j] = fma2(ai, bp[j], acc2[i][j]);
            }
        }

        if (kt + 1 < nt) {
            const int nxt = cur ^ 1;
            float av0[4] = {a0.x, a0.y, a0.z, a0.w};
            float av1[4] = {a1.x, a1.y, a1.z, a1.w};
            float bv0[4] = {b0.x, b0.y, b0.z, b0.w};
            float bv1[4] = {b1.x, b1.y, b1.z, b1.w};
            #pragma unroll
            for (int w = 0; w < 4; w++) {
                As[nxt][lc + w][lr]      = av0[w];
                As[nxt][lc + w][lr + 64] = av1[w];
                Bs[nxt][lc + w][lr]      = bv0[w];
                Bs[nxt][lc + w][lr + 64] = bv1[w];
            }
            __syncthreads();
        }
    }

    // epilogue: unpack, bias, vectorized stores
    float bj[8];
    #pragma unroll
    for (int j = 0; j < 8; j++) {
        int n = n0 + tx * 4 + ((j < 4) ? j : 64 + (j - 4));
        bj[j] = bias[n];
    }
    #pragma unroll
    for (int i = 0; i < 8; i++) {
        int row = m0 + ty * 4 + ((i < 4) ? i : 64 + (i - 4));
        float c[8];
        unpack2(acc2[i][0], c[0], c[1]);
        unpack2(acc2[i][1], c[2], c[3]);
        unpack2(acc2[i][2], c[4], c[5]);
        unpack2(acc2[i][3], c[6], c[7]);
        float4 lo = make_float4(c[0] + bj[0], c[1] + bj[1], c[2] + bj[2], c[3] + bj[3]);
        float4 hi = make_float4(c[4] + bj[4], c[5] + bj[5], c[6] + bj[6], c[7] + bj[7]);
        *(float4*)&C[(size_t)row * N + n0 + tx * 4]      = lo;
        *(float4*)&C[(size_t)row * N + n0 + tx * 4 + 64] = hi;
    }
}

// ================= causal flash attention ==================================
// 128 threads/block, 128 queries/block. Each lane PAIR handles 2 adjacent
// queries; each lane owns 32 of 64 dims (interleaved float4 chunks 2i+half).
// Every k4/v4 smem load (read as packed f32x2 pairs) serves both queries;
// all accumulation in fma.rn.f32x2. Score = packed dot + horiz add + shfl(1).
#define AQ  128
#define ATH 128
#define KT  16

__global__ __launch_bounds__(128) void attn_kernel(
    const float* __restrict__ q, const float* __restrict__ k,
    const float* __restrict__ v, float* __restrict__ o)
{
    __shared__ __align__(16) float ks[KT * HEAD_DIM];
    __shared__ __align__(16) float vs[KT * HEAD_DIM];

    const int tid   = threadIdx.x;
    const int half  = tid & 1;
    const int ql    = tid >> 1;            // 0..63
    const int qbase = blockIdx.x * AQ;
    const int q0    = qbase + 2 * ql;
    const int q1    = q0 + 1;
    const int bh    = blockIdx.y;
    const int b     = bh / N_HEAD;
    const int h     = bh % N_HEAD;

    // load q rows for both queries: this lane's 32 dims as 16 packed f32x2
    u64 qr2[2][16];
    #pragma unroll
    for (int qq = 0; qq < 2; qq++) {
        const float* qrow = q + ((size_t)(b * SEQ + q0 + qq)) * N_EMBD + h * HEAD_DIM;
        #pragma unroll
        for (int i = 0; i < 8; i++) {
            ulonglong2 t = *(const ulonglong2*)&qrow[(2 * i + half) * 4];
            qr2[qq][2 * i]     = t.x;
            qr2[qq][2 * i + 1] = t.y;
        }
    }

    u64 acc2[2][16];
    #pragma unroll
    for (int qq = 0; qq < 2; qq++)
        #pragma unroll
        for (int i = 0; i < 16; i++) acc2[qq][i] = 0ULL;

    float m0 = -1e30f, m1 = -1e30f, l0 = 0.f, l1 = 0.f;

    const int ntiles = qbase / KT + AQ / KT;
    for (int t = 0; t < ntiles; t++) {
        const int j0 = t * KT;

        // cooperative K/V tile load: 256 float4 each / 128 threads
        #pragma unroll
        for (int i4 = tid; i4 < KT * HEAD_DIM / 4; i4 += ATH) {
            int jr = i4 >> 4;
            int dd = i4 & 15;
            size_t base = ((size_t)(b * SEQ + j0 + jr)) * N_EMBD + h * HEAD_DIM + dd * 4;
            ((float4*)ks)[i4] = *(const float4*)&k[base];
            ((float4*)vs)[i4] = *(const float4*)&v[base];
        }
        __syncthreads();

        float s[2][KT];
        float tm0 = m0, tm1 = m1;
        #pragma unroll
        for (int j = 0; j < KT; j++) {
            // this lane's 32 dims of k[j] as 16 packed f32x2 (direct smem reinterpret)
            u64 k2[16];
            #pragma unroll
            for (int i = 0; i < 8; i++) {
                ulonglong2 t = *(const ulonglong2*)&ks[j * HEAD_DIM + (2 * i + half) * 4];
                k2[2 * i]     = t.x;
                k2[2 * i + 1] = t.y;
            }
            #pragma unroll
            for (int qq = 0; qq < 2; qq++) {
                u64 p0 = 0ULL, p1 = 0ULL, p2 = 0ULL, p3 = 0ULL;
                #pragma unroll
                for (int i = 0; i < 4; i++) {
                    p0 = fma2(qr2[qq][4 * i + 0], k2[4 * i + 0], p0);
                    p1 = fma2(qr2[qq][4 * i + 1], k2[4 * i + 1], p1);
                    p2 = fma2(qr2[qq][4 * i + 2], k2[4 * i + 2], p2);
                    p3 = fma2(qr2[qq][4 * i + 3], k2[4 * i + 3], p3);
                }
                u64 ps = add2(add2(p0, p1), add2(p2, p3));
                float lo, hi;
                unpack2(ps, lo, hi);
                float sj = lo + hi;
                sj += __shfl_xor_sync(0xffffffffu, sj, 1);   // pair-sum over dims
                sj *= 0.125f;                                 // 1/sqrt(64)
                int qi = (qq == 0) ? q0 : q1;
                sj = (j0 + j <= qi) ? sj : -INFINITY;
                s[qq][j] = sj;
                if (qq == 0) tm0 = fmaxf(tm0, sj); else tm1 = fmaxf(tm1, sj);
            }
        }

        // rescale previous accumulators
        {
            float e0 = __expf(m0 - tm0);
            float e1 = __expf(m1 - tm1);
            l0 *= e0; l1 *= e1;
            u64 e0p = splat2(e0), e1p = splat2(e1);
            #pragma unroll
            for (int i = 0; i < 16; i++) {
                acc2[0][i] = mul2(acc2[0][i], e0p);
                acc2[1][i] = mul2(acc2[1][i], e1p);
            }
        }

        #pragma unroll
        for (int j = 0; j < KT; j++) {
            float p0 = __expf(s[0][j] - tm0);
            float p1 = __expf(s[1][j] - tm1);
            l0 += p0; l1 += p1;
            u64 p0p = splat2(p0), p1p = splat2(p1);
            #pragma unroll
            for (int i = 0; i < 8; i++) {
                ulonglong2 t = *(const ulonglong2*)&vs[j * HEAD_DIM + (2 * i + half) * 4];
                acc2[0][2 * i]     = fma2(p0p, t.x, acc2[0][2 * i]);
                acc2[0][2 * i + 1] = fma2(p0p, t.y, acc2[0][2 * i + 1]);
                acc2[1][2 * i]     = fma2(p1p, t.x, acc2[1][2 * i]);
                acc2[1][2 * i + 1] = fma2(p1p, t.y, acc2[1][2 * i + 1]);
            }
        }
        m0 = tm0; m1 = tm1;
        __syncthreads();
    }

    // final normalize + store
    #pragma unroll
    for (int qq = 0; qq < 2; qq++) {
        float inv = 1.f / ((qq == 0) ? l0 : l1);
        float* op = o + ((size_t)(b * SEQ + q0 + qq)) * N_EMBD + h * HEAD_DIM;
        #pragma unroll
        for (int i = 0; i < 8; i++) {
            float x0, x1, x2, x3;
            unpack2(acc2[qq][2 * i],     x0, x1);
            unpack2(acc2[qq][2 * i + 1], x2, x3);
            float4 r = make_float4(x0 * inv, x1 * inv, x2 * inv, x3 * inv);
            *(float4*)&op[(2 * i + half) * 4] = r;
        }
    }
}

// ---------------- launch ----------------
extern "C" void kernel_launch(void* const* d_in, const int* in_sizes, int n_in,
                              void* d_out, int out_size)
{
    const float* x  = (const float*)d_in[0];
    const float* Wq = (const float*)d_in[1];
    const float* bq = (const float*)d_in[2];
    const float* Wk = (const float*)d_in[3];
    const float* bk = (const float*)d_in[4];
    const float* Wv = (const float*)d_in[5];
    const float* bv = (const float*)d_in[6];
    const float* Wo = (const float*)d_in[7];
    const float* bo = (const float*)d_in[8];
    float* out = (float*)d_out;

    float *qp, *kp, *vp, *ap;
    cudaGetSymbolAddress((void**)&qp, g_q);
    cudaGetSymbolAddress((void**)&kp, g_k);
    cudaGetSymbolAddress((void**)&vp, g_v);
    cudaGetSymbolAddress((void**)&ap, g_att);

    dim3 ggrid(N_EMBD / GBN, M_TOT / GBM);   // (8, 32)

    gemm_bias_kernel<<<ggrid, 256>>>(x, Wq, bq, qp, M_TOT, N_EMBD, N_EMBD);
    gemm_bias_kernel<<<ggrid, 256>>>(x, Wk, bk, kp, M_TOT, N_EMBD, N_EMBD);
    gemm_bias_kernel<<<ggrid, 256>>>(x, Wv, bv, vp, M_TOT, N_EMBD, N_EMBD);

    dim3 agrid(SEQ / AQ, BATCH * N_HEAD);    // (16, 32)
    attn_kernel<<<agrid, ATH>>>(qp, kp, vp, ap);

    gemm_bias_kernel<<<ggrid, 256>>>(ap, Wo, bo, out, M_TOT, N_EMBD, N_EMBD);
}

// round 6
// speedup vs baseline: 3.1746x; 1.4703x over previous
#include <cuda_runtime.h>
#include <cuda_bf16.h>
#include <math.h>
#include <stdint.h>

#define N_EMBD   1024
#define N_HEAD   16
#define HEAD_DIM 64
#define BATCH    2
#define SEQ      2048
#define M_TOT    (BATCH * SEQ)

typedef unsigned long long u64;

// ---------------- packed f32x2 helpers (sm_103a) ----------------
__device__ __forceinline__ u64 splat2(float x) {
    u64 d; asm("mov.b64 %0, {%1, %1};" : "=l"(d) : "f"(x)); return d;
}
__device__ __forceinline__ void unpack2(u64 v, float& x, float& y) {
    asm("mov.b64 {%0, %1}, %2;" : "=f"(x), "=f"(y) : "l"(v));
}
__device__ __forceinline__ u64 fma2(u64 a, u64 b, u64 c) {
    u64 d; asm("fma.rn.f32x2 %0, %1, %2, %3;" : "=l"(d) : "l"(a), "l"(b), "l"(c)); return d;
}
__device__ __forceinline__ u64 add2(u64 a, u64 b) {
    u64 d; asm("add.rn.f32x2 %0, %1, %2;" : "=l"(d) : "l"(a), "l"(b)); return d;
}
__device__ __forceinline__ u64 mul2(u64 a, u64 b) {
    u64 d; asm("mul.rn.f32x2 %0, %1, %2;" : "=l"(d) : "l"(a), "l"(b)); return d;
}

// ---------------- cp.async helpers ----------------
__device__ __forceinline__ uint32_t smem_u32(const void* p) {
    uint32_t a;
    asm("{ .reg .u64 t; cvta.to.shared.u64 t, %1; cvt.u32.u64 %0, t; }" : "=r"(a) : "l"(p));
    return a;
}
__device__ __forceinline__ void cp16(uint32_t s, const void* g) {
    asm volatile("cp.async.cg.shared.global [%0], [%1], 16;" :: "r"(s), "l"(g));
}
__device__ __forceinline__ void cp_commit() {
    asm volatile("cp.async.commit_group;" ::: "memory");
}

// ---------------- scratch (device globals: allocation-free) ----------------
__device__ float g_q[(size_t)M_TOT * N_EMBD];
__device__ float g_k[(size_t)M_TOT * N_EMBD];
__device__ float g_v[(size_t)M_TOT * N_EMBD];
__device__ float g_att[(size_t)M_TOT * N_EMBD];
__device__ uint32_t g_xt[(size_t)M_TOT * N_EMBD];   // tf32 activations
__device__ uint32_t g_wt[(size_t)N_EMBD * N_EMBD];  // tf32 weights

// ---------------- fp32 -> tf32 (rna) pre-pass ----------------
__global__ __launch_bounds__(256) void tf32_cvt_kernel(
    const float* __restrict__ src, uint32_t* __restrict__ dst, int n4)
{
    int i = blockIdx.x * blockDim.x + threadIdx.x;
    if (i >= n4) return;
    float4 v = ((const float4*)src)[i];
    uint4 o;
    asm("cvt.rna.tf32.f32 %0, %1;" : "=r"(o.x) : "f"(v.x));
    asm("cvt.rna.tf32.f32 %0, %1;" : "=r"(o.y) : "f"(v.y));
    asm("cvt.rna.tf32.f32 %0, %1;" : "=r"(o.z) : "f"(v.z));
    asm("cvt.rna.tf32.f32 %0, %1;" : "=r"(o.w) : "f"(v.w));
    ((uint4*)dst)[i] = o;
}

// ================= tf32 mma.sync GEMM: C[M,N] = A@B^T + bias ==============
// CTA 128x128, BK=32, 256 threads = 8 warps (4m x 2n), warp tile 32x64.
// XOR-swizzled smem: word = row*32 + (k ^ 4*(row&7)) -> conflict-free
// float4 stores and fragment LDS.32 reads. Double-buffered cp.async.
#define CTM 128
#define CTN 128
#define CBK 32
#define NCH (N_EMBD / CBK)          // 32
#define STW 4096                    // words per operand tile (128*32)
#define GSMEM (4 * STW * 4)         // 65536 bytes: A0,A1,B0,B1

__device__ __forceinline__ void mma_tf32(float* c, const uint32_t* a,
                                         uint32_t b0, uint32_t b1) {
    asm volatile(
        "mma.sync.aligned.m16n8k8.row.col.f32.tf32.tf32.f32 "
        "{%0,%1,%2,%3}, {%4,%5,%6,%7}, {%8,%9}, {%0,%1,%2,%3};"
        : "+f"(c[0]), "+f"(c[1]), "+f"(c[2]), "+f"(c[3])
        : "r"(a[0]), "r"(a[1]), "r"(a[2]), "r"(a[3]), "r"(b0), "r"(b1));
}

__device__ __forceinline__ void load_op(const uint32_t* __restrict__ g,
                                        int rowbase, int kc,
                                        uint32_t sm_t, int tid)
{
    // 1024 float4 / 256 threads = 4 each
    #pragma unroll
    for (int j = 0; j < 4; j++) {
        int idx = tid + 256 * j;
        int row = idx >> 3;          // 0..127
        int k4  = idx & 7;           // 0..7
        const void* gp = g + (size_t)(rowbase + row) * N_EMBD + kc * CBK + k4 * 4;
        uint32_t w = row * 32 + ((k4 * 4) ^ ((row & 7) * 4));
        cp16(sm_t + w * 4, gp);
    }
}

__global__ __launch_bounds__(256) void gemm_tc_kernel(
    const uint32_t* __restrict__ A,   // [M][K] tf32
    const uint32_t* __restrict__ B,   // [N][K] tf32
    const float* __restrict__ bias, float* __restrict__ C,
    int M, int N)
{
    extern __shared__ __align__(16) uint32_t smem[];
    const uint32_t sb = smem_u32(smem);
    const int tid  = threadIdx.x;
    const int wid  = tid >> 5;
    const int lane = tid & 31;
    const int g  = lane >> 2;       // 0..7
    const int tg = lane & 3;        // 0..3
    const int wm = wid >> 1;        // 0..3
    const int wn = wid & 1;         // 0..1
    const int m0 = blockIdx.y * CTM;
    const int n0 = blockIdx.x * CTN;
    const int xr = 4 * g;           // row-XOR (row&7 == g for all fragment rows)

    // stage s: A at smem + s*STW, B at smem + 2*STW + s*STW
    uint32_t sA[2] = {sb, sb + STW * 4};
    uint32_t sB[2] = {sb + 2 * STW * 4, sb + 3 * STW * 4};

    // prologue: chunks 0,1
    #pragma unroll
    for (int c = 0; c < 2; c++) {
        load_op(A, m0, c, sA[c], tid);
        load_op(B, n0, c, sB[c], tid);
        cp_commit();
    }

    float acc[2][8][4];
    #pragma unroll
    for (int mi = 0; mi < 2; mi++)
        #pragma unroll
        for (int ni = 0; ni < 8; ni++)
            #pragma unroll
            for (int r = 0; r < 4; r++) acc[mi][ni][r] = 0.f;

    for (int c = 0; c < NCH; c++) {
        const int s = c & 1;
        if (c == NCH - 1) asm volatile("cp.async.wait_group 0;" ::: "memory");
        else              asm volatile("cp.async.wait_group 1;" ::: "memory");
        __syncthreads();

        const uint32_t* As = (const uint32_t*)(smem) + (sA[s] - sb) / 4;
        const uint32_t* Bs = (const uint32_t*)(smem) + (sB[s] - sb) / 4;

        #pragma unroll
        for (int kk = 0; kk < 4; kk++) {
            const int k = kk * 8;
            const int x0 = (k + tg) ^ xr;
            const int x1 = (k + tg + 4) ^ xr;

            uint32_t a[2][4];
            #pragma unroll
            for (int mi = 0; mi < 2; mi++) {
                const uint32_t* base = As + (wm * 32 + mi * 16 + g) * 32;
                a[mi][0] = base[x0];
                a[mi][1] = base[256 + x0];   // +8 rows
                a[mi][2] = base[x1];
                a[mi][3] = base[256 + x1];
            }
            #pragma unroll
            for (int ni = 0; ni < 8; ni++) {
                const uint32_t* bb = Bs + (wn * 64 + ni * 8 + g) * 32;
                uint32_t b0 = bb[x0];
                uint32_t b1 = bb[x1];
                mma_tf32(acc[0][ni], a[0], b0, b1);
                mma_tf32(acc[1][ni], a[1], b0, b1);
            }
        }
        __syncthreads();

        if (c + 2 < NCH) {
            load_op(A, m0, c + 2, sA[s], tid);
            load_op(B, n0, c + 2, sB[s], tid);
            cp_commit();
        }
    }

    // epilogue: c0/c1 at (row, 2tg), c2/c3 at (row+8, 2tg)
    #pragma unroll
    for (int mi = 0; mi < 2; mi++) {
        const int r0 = m0 + wm * 32 + mi * 16 + g;
        #pragma unroll
        for (int ni = 0; ni < 8; ni++) {
            const int col = n0 + wn * 64 + ni * 8 + 2 * tg;
            float b0v = bias[col], b1v = bias[col + 1];
            float2 lo = make_float2(acc[mi][ni][0] + b0v, acc[mi][ni][1] + b1v);
            float2 hi = make_float2(acc[mi][ni][2] + b0v, acc[mi][ni][3] + b1v);
            *(float2*)&C[(size_t)r0 * N + col]       = lo;
            *(float2*)&C[(size_t)(r0 + 8) * N + col] = hi;
        }
    }
}

// ================= causal flash attention (round-3, unchanged) =============
#define AQ  128
#define ATH 128
#define KT  16

__global__ __launch_bounds__(128) void attn_kernel(
    const float* __restrict__ q, const float* __restrict__ k,
    const float* __restrict__ v, float* __restrict__ o)
{
    __shared__ __align__(16) float ks[KT * HEAD_DIM];
    __shared__ __align__(16) float vs[KT * HEAD_DIM];

    const int tid   = threadIdx.x;
    const int half  = tid & 1;
    const int ql    = tid >> 1;
    const int qbase = blockIdx.x * AQ;
    const int q0    = qbase + 2 * ql;
    const int q1    = q0 + 1;
    const int bh    = blockIdx.y;
    const int b     = bh / N_HEAD;
    const int h     = bh % N_HEAD;

    u64 qr2[2][16];
    #pragma unroll
    for (int qq = 0; qq < 2; qq++) {
        const float* qrow = q + ((size_t)(b * SEQ + q0 + qq)) * N_EMBD + h * HEAD_DIM;
        #pragma unroll
        for (int i = 0; i < 8; i++) {
            ulonglong2 t = *(const ulonglong2*)&qrow[(2 * i + half) * 4];
            qr2[qq][2 * i]     = t.x;
            qr2[qq][2 * i + 1] = t.y;
        }
    }

    u64 acc2[2][16];
    #pragma unroll
    for (int qq = 0; qq < 2; qq++)
        #pragma unroll
        for (int i = 0; i < 16; i++) acc2[qq][i] = 0ULL;

    float m0 = -1e30f, m1 = -1e30f, l0 = 0.f, l1 = 0.f;

    const int ntiles = qbase / KT + AQ / KT;
    for (int t = 0; t < ntiles; t++) {
        const int j0 = t * KT;

        #pragma unroll
        for (int i4 = tid; i4 < KT * HEAD_DIM / 4; i4 += ATH) {
            int jr = i4 >> 4;
            int dd = i4 & 15;
            size_t base = ((size_t)(b * SEQ + j0 + jr)) * N_EMBD + h * HEAD_DIM + dd * 4;
            ((float4*)ks)[i4] = *(const float4*)&k[base];
            ((float4*)vs)[i4] = *(const float4*)&v[base];
        }
        __syncthreads();

        float s[2][KT];
        float tm0 = m0, tm1 = m1;
        #pragma unroll
        for (int j = 0; j < KT; j++) {
            u64 k2[16];
            #pragma unroll
            for (int i = 0; i < 8; i++) {
                ulonglong2 t2 = *(const ulonglong2*)&ks[j * HEAD_DIM + (2 * i + half) * 4];
                k2[2 * i]     = t2.x;
                k2[2 * i + 1] = t2.y;
            }
            #pragma unroll
            for (int qq = 0; qq < 2; qq++) {
                u64 p0 = 0ULL, p1 = 0ULL, p2 = 0ULL, p3 = 0ULL;
                #pragma unroll
                for (int i = 0; i < 4; i++) {
                    p0 = fma2(qr2[qq][4 * i + 0], k2[4 * i + 0], p0);
                    p1 = fma2(qr2[qq][4 * i + 1], k2[4 * i + 1], p1);
                    p2 = fma2(qr2[qq][4 * i + 2], k2[4 * i + 2], p2);
                    p3 = fma2(qr2[qq][4 * i + 3], k2[4 * i + 3], p3);
                }
                u64 ps = add2(add2(p0, p1), add2(p2, p3));
                float lo, hi;
                unpack2(ps, lo, hi);
                float sj = lo + hi;
                sj += __shfl_xor_sync(0xffffffffu, sj, 1);
                sj *= 0.125f;
                int qi = (qq == 0) ? q0 : q1;
                sj = (j0 + j <= qi) ? sj : -INFINITY;
                s[qq][j] = sj;
                if (qq == 0) tm0 = fmaxf(tm0, sj); else tm1 = fmaxf(tm1, sj);
            }
        }

        {
            float e0 = __expf(m0 - tm0);
            float e1 = __expf(m1 - tm1);
            l0 *= e0; l1 *= e1;
            u64 e0p = splat2(e0), e1p = splat2(e1);
            #pragma unroll
            for (int i = 0; i < 16; i++) {
                acc2[0][i] = mul2(acc2[0][i], e0p);
                acc2[1][i] = mul2(acc2[1][i], e1p);
            }
        }

        #pragma unroll
        for (int j = 0; j < KT; j++) {
            float p0 = __expf(s[0][j] - tm0);
            float p1 = __expf(s[1][j] - tm1);
            l0 += p0; l1 += p1;
            u64 p0p = splat2(p0), p1p = splat2(p1);
            #pragma unroll
            for (int i = 0; i < 8; i++) {
                ulonglong2 t2 = *(const ulonglong2*)&vs[j * HEAD_DIM + (2 * i + half) * 4];
                acc2[0][2 * i]     = fma2(p0p, t2.x, acc2[0][2 * i]);
                acc2[0][2 * i + 1] = fma2(p0p, t2.y, acc2[0][2 * i + 1]);
                acc2[1][2 * i]     = fma2(p1p, t2.x, acc2[1][2 * i]);
                acc2[1][2 * i + 1] = fma2(p1p, t2.y, acc2[1][2 * i + 1]);
            }
        }
        m0 = tm0; m1 = tm1;
        __syncthreads();
    }

    #pragma unroll
    for (int qq = 0; qq < 2; qq++) {
        float inv = 1.f / ((qq == 0) ? l0 : l1);
        float* op = o + ((size_t)(b * SEQ + q0 + qq)) * N_EMBD + h * HEAD_DIM;
        #pragma unroll
        for (int i = 0; i < 8; i++) {
            float x0, x1, x2, x3;
            unpack2(acc2[qq][2 * i],     x0, x1);
            unpack2(acc2[qq][2 * i + 1], x2, x3);
            float4 r = make_float4(x0 * inv, x1 * inv, x2 * inv, x3 * inv);
            *(float4*)&op[(2 * i + half) * 4] = r;
        }
    }
}

// ---------------- launch ----------------
extern "C" void kernel_launch(void* const* d_in, const int* in_sizes, int n_in,
                              void* d_out, int out_size)
{
    const float* x  = (const float*)d_in[0];
    const float* Wq = (const float*)d_in[1];
    const float* bq = (const float*)d_in[2];
    const float* Wk = (const float*)d_in[3];
    const float* bk = (const float*)d_in[4];
    const float* Wv = (const float*)d_in[5];
    const float* bv = (const float*)d_in[6];
    const float* Wo = (const float*)d_in[7];
    const float* bo = (const float*)d_in[8];
    float* out = (float*)d_out;

    float *qp, *kp, *vp, *ap;
    uint32_t *xt, *wt;
    cudaGetSymbolAddress((void**)&qp, g_q);
    cudaGetSymbolAddress((void**)&kp, g_k);
    cudaGetSymbolAddress((void**)&vp, g_v);
    cudaGetSymbolAddress((void**)&ap, g_att);
    cudaGetSymbolAddress((void**)&xt, g_xt);
    cudaGetSymbolAddress((void**)&wt, g_wt);

    cudaFuncSetAttribute(gemm_tc_kernel, cudaFuncAttributeMaxDynamicSharedMemorySize, GSMEM);

    const int nx4 = M_TOT * N_EMBD / 4;      // 1048576
    const int nw4 = N_EMBD * N_EMBD / 4;     // 262144

    dim3 ggrid(N_EMBD / CTN, M_TOT / CTM);   // (8, 32)

    tf32_cvt_kernel<<<nx4 / 256, 256>>>(x, xt, nx4);

    tf32_cvt_kernel<<<nw4 / 256, 256>>>(Wq, wt, nw4);
    gemm_tc_kernel<<<ggrid, 256, GSMEM>>>(xt, wt, bq, qp, M_TOT, N_EMBD);

    tf32_cvt_kernel<<<nw4 / 256, 256>>>(Wk, wt, nw4);
    gemm_tc_kernel<<<ggrid, 256, GSMEM>>>(xt, wt, bk, kp, M_TOT, N_EMBD);

    tf32_cvt_kernel<<<nw4 / 256, 256>>>(Wv, wt, nw4);
    gemm_tc_kernel<<<ggrid, 256, GSMEM>>>(xt, wt, bv, vp, M_TOT, N_EMBD);

    dim3 agrid(SEQ / AQ, BATCH * N_HEAD);    // (16, 32)
    attn_kernel<<<agrid, ATH>>>(qp, kp, vp, ap);

    tf32_cvt_kernel<<<nx4 / 256, 256>>>(ap, xt, nx4);
    tf32_cvt_kernel<<<nw4 / 256, 256>>>(Wo, wt, nw4);
    gemm_tc_kernel<<<ggrid, 256, GSMEM>>>(xt, wt, bo, out, M_TOT, N_EMBD);
}

// round 8
// speedup vs baseline: 4.4258x; 1.3941x over previous
#include <cuda_runtime.h>
#include <cuda_bf16.h>
#include <math.h>
#include <stdint.h>

#define N_EMBD   1024
#define N_HEAD   16
#define HEAD_DIM 64
#define BATCH    2
#define SEQ      2048
#define M_TOT    (BATCH * SEQ)

typedef unsigned long long u64;

// ---------------- cp.async helpers ----------------
__device__ __forceinline__ uint32_t smem_u32(const void* p) {
    uint32_t a;
    asm("{ .reg .u64 t; cvta.to.shared.u64 t, %1; cvt.u32.u64 %0, t; }" : "=r"(a) : "l"(p));
    return a;
}
__device__ __forceinline__ void cp16(uint32_t s, const void* g) {
    asm volatile("cp.async.cg.shared.global [%0], [%1], 16;" :: "r"(s), "l"(g));
}
__device__ __forceinline__ void cp_commit() {
    asm volatile("cp.async.commit_group;" ::: "memory");
}

// ---------------- bf16 split/pack ----------------
__device__ __forceinline__ void split_pack(float x0, float x1, uint32_t& hi, uint32_t& lo) {
    __nv_bfloat16 h0 = __float2bfloat16_rn(x0), h1 = __float2bfloat16_rn(x1);
    __nv_bfloat16 l0 = __float2bfloat16_rn(x0 - __bfloat162float(h0));
    __nv_bfloat16 l1 = __float2bfloat16_rn(x1 - __bfloat162float(h1));
    hi = (uint32_t)__bfloat16_as_ushort(h0) | ((uint32_t)__bfloat16_as_ushort(h1) << 16);
    lo = (uint32_t)__bfloat16_as_ushort(l0) | ((uint32_t)__bfloat16_as_ushort(l1) << 16);
}

// ---------------- scratch (device globals: allocation-free) ----------------
__device__ float g_q[(size_t)M_TOT * N_EMBD];
__device__ float g_k[(size_t)M_TOT * N_EMBD];
__device__ float g_v[(size_t)M_TOT * N_EMBD];
__device__ float g_att[(size_t)M_TOT * N_EMBD];
__device__ uint32_t g_xt[(size_t)M_TOT * N_EMBD];   // tf32 activations
__device__ uint32_t g_wt[(size_t)N_EMBD * N_EMBD];  // tf32 weights

// ---------------- fp32 -> tf32 (rna) pre-pass ----------------
__global__ __launch_bounds__(256) void tf32_cvt_kernel(
    const float* __restrict__ src, uint32_t* __restrict__ dst, int n4)
{
    int i = blockIdx.x * blockDim.x + threadIdx.x;
    if (i >= n4) return;
    float4 v = ((const float4*)src)[i];
    uint4 o;
    asm("cvt.rna.tf32.f32 %0, %1;" : "=r"(o.x) : "f"(v.x));
    asm("cvt.rna.tf32.f32 %0, %1;" : "=r"(o.y) : "f"(v.y));
    asm("cvt.rna.tf32.f32 %0, %1;" : "=r"(o.z) : "f"(v.z));
    asm("cvt.rna.tf32.f32 %0, %1;" : "=r"(o.w) : "f"(v.w));
    ((uint4*)dst)[i] = o;
}

// ================= tf32 mma.sync GEMM (round-6, passing) ===================
#define CTM 128
#define CTN 128
#define CBK 32
#define NCH (N_EMBD / CBK)
#define STW 4096
#define GSMEM (4 * STW * 4)

__device__ __forceinline__ void mma_tf32(float* c, const uint32_t* a,
                                         uint32_t b0, uint32_t b1) {
    asm volatile(
        "mma.sync.aligned.m16n8k8.row.col.f32.tf32.tf32.f32 "
        "{%0,%1,%2,%3}, {%4,%5,%6,%7}, {%8,%9}, {%0,%1,%2,%3};"
        : "+f"(c[0]), "+f"(c[1]), "+f"(c[2]), "+f"(c[3])
        : "r"(a[0]), "r"(a[1]), "r"(a[2]), "r"(a[3]), "r"(b0), "r"(b1));
}

__device__ __forceinline__ void load_op(const uint32_t* __restrict__ g,
                                        int rowbase, int kc,
                                        uint32_t sm_t, int tid)
{
    #pragma unroll
    for (int j = 0; j < 4; j++) {
        int idx = tid + 256 * j;
        int row = idx >> 3;
        int k4  = idx & 7;
        const void* gp = g + (size_t)(rowbase + row) * N_EMBD + kc * CBK + k4 * 4;
        uint32_t w = row * 32 + ((k4 * 4) ^ ((row & 7) * 4));
        cp16(sm_t + w * 4, gp);
    }
}

__global__ __launch_bounds__(256) void gemm_tc_kernel(
    const uint32_t* __restrict__ A, const uint32_t* __restrict__ B,
    const float* __restrict__ bias, float* __restrict__ C,
    int M, int N)
{
    extern __shared__ __align__(16) uint32_t gsm[];
    const uint32_t sb = smem_u32(gsm);
    const int tid  = threadIdx.x;
    const int wid  = tid >> 5;
    const int lane = tid & 31;
    const int g  = lane >> 2;
    const int tg = lane & 3;
    const int wm = wid >> 1;
    const int wn = wid & 1;
    const int m0 = blockIdx.y * CTM;
    const int n0 = blockIdx.x * CTN;
    const int xr = 4 * g;

    uint32_t sA[2] = {sb, sb + STW * 4};
    uint32_t sB[2] = {sb + 2 * STW * 4, sb + 3 * STW * 4};

    #pragma unroll
    for (int c = 0; c < 2; c++) {
        load_op(A, m0, c, sA[c], tid);
        load_op(B, n0, c, sB[c], tid);
        cp_commit();
    }

    float acc[2][8][4];
    #pragma unroll
    for (int mi = 0; mi < 2; mi++)
        #pragma unroll
        for (int ni = 0; ni < 8; ni++)
            #pragma unroll
            for (int r = 0; r < 4; r++) acc[mi][ni][r] = 0.f;

    for (int c = 0; c < NCH; c++) {
        const int s = c & 1;
        if (c == NCH - 1) asm volatile("cp.async.wait_group 0;" ::: "memory");
        else              asm volatile("cp.async.wait_group 1;" ::: "memory");
        __syncthreads();

        const uint32_t* As = gsm + (sA[s] - sb) / 4;
        const uint32_t* Bs = gsm + (sB[s] - sb) / 4;

        #pragma unroll
        for (int kk = 0; kk < 4; kk++) {
            const int k = kk * 8;
            const int x0 = (k + tg) ^ xr;
            const int x1 = (k + tg + 4) ^ xr;

            uint32_t a[2][4];
            #pragma unroll
            for (int mi = 0; mi < 2; mi++) {
                const uint32_t* base = As + (wm * 32 + mi * 16 + g) * 32;
                a[mi][0] = base[x0];
                a[mi][1] = base[256 + x0];
                a[mi][2] = base[x1];
                a[mi][3] = base[256 + x1];
            }
            #pragma unroll
            for (int ni = 0; ni < 8; ni++) {
                const uint32_t* bb = Bs + (wn * 64 + ni * 8 + g) * 32;
                uint32_t b0 = bb[x0];
                uint32_t b1 = bb[x1];
                mma_tf32(acc[0][ni], a[0], b0, b1);
                mma_tf32(acc[1][ni], a[1], b0, b1);
            }
        }
        __syncthreads();

        if (c + 2 < NCH) {
            load_op(A, m0, c + 2, sA[s], tid);
            load_op(B, n0, c + 2, sB[s], tid);
            cp_commit();
        }
    }

    #pragma unroll
    for (int mi = 0; mi < 2; mi++) {
        const int r0 = m0 + wm * 32 + mi * 16 + g;
        #pragma unroll
        for (int ni = 0; ni < 8; ni++) {
            const int col = n0 + wn * 64 + ni * 8 + 2 * tg;
            float b0v = bias[col], b1v = bias[col + 1];
            float2 lo = make_float2(acc[mi][ni][0] + b0v, acc[mi][ni][1] + b1v);
            float2 hi = make_float2(acc[mi][ni][2] + b0v, acc[mi][ni][3] + b1v);
            *(float2*)&C[(size_t)r0 * N + col]       = lo;
            *(float2*)&C[(size_t)(r0 + 8) * N + col] = hi;
        }
    }
}

// ================= tensor-core causal flash attention ======================
// CTA: 64 queries x one (b,h); 4 warps x m16 rows; key tiles of 64.
// bf16 3-term split (hi*hi + hi*lo + lo*hi) for QK^T and P*V.
// K bf16 [key][dim], V bf16 transposed [dim][key], rows padded to 72 bf16
// -> B-frag LDS.32 banks (4g+tg+8kk)%32 all distinct (conflict-free).
// P stays in registers: score C-frag layout == PV A-operand layout.
#define ATM 64
#define ATN 64
#define KROW 72                       // padded bf16 row stride (144 B)
#define STG_OFF(s) ((s) * 32768)      // f32 staging: K at +0, V at +16384
#define KHI_OFF  65536
#define KLO_OFF  74752
#define VTHI_OFF 83968
#define VTLO_OFF 93184
#define ASMEM    102400

__device__ __forceinline__ void mma_bf16(float* c, const uint32_t* a,
                                         uint32_t b0, uint32_t b1) {
    asm volatile(
        "mma.sync.aligned.m16n8k16.row.col.f32.bf16.bf16.f32 "
        "{%0,%1,%2,%3}, {%4,%5,%6,%7}, {%8,%9}, {%0,%1,%2,%3};"
        : "+f"(c[0]), "+f"(c[1]), "+f"(c[2]), "+f"(c[3])
        : "r"(a[0]), "r"(a[1]), "r"(a[2]), "r"(a[3]), "r"(b0), "r"(b1));
}

__global__ __launch_bounds__(128) void attn_tc_kernel(
    const float* __restrict__ qg, const float* __restrict__ kg,
    const float* __restrict__ vg, float* __restrict__ og)
{
    extern __shared__ __align__(16) char asmem[];
    const uint32_t sb = smem_u32(asmem);
    const int tid  = threadIdx.x;
    const int wm   = tid >> 5;
    const int lane = tid & 31;
    const int g    = lane >> 2;
    const int tg   = lane & 3;
    const int q0   = blockIdx.x * ATM;
    const int bh   = blockIdx.y;
    const int b    = bh >> 4;
    const int h    = bh & 15;

    const size_t bt = (size_t)b * SEQ;
    const int hc = h * HEAD_DIM;

    // --- Q fragments (pre-scaled by 1/sqrt(D)), bf16 hi/lo split, in regs ---
    uint32_t qhi[4][4], qlo[4][4];
    {
        const float* qr0 = qg + (bt + q0 + wm * 16 + g) * N_EMBD + hc;
        const float* qr1 = qr0 + 8 * N_EMBD;
        #pragma unroll
        for (int kk = 0; kk < 4; kk++) {
            float2 e[4];
            e[0] = *(const float2*)(qr0 + kk * 16 + 2 * tg);
            e[1] = *(const float2*)(qr1 + kk * 16 + 2 * tg);
            e[2] = *(const float2*)(qr0 + kk * 16 + 2 * tg + 8);
            e[3] = *(const float2*)(qr1 + kk * 16 + 2 * tg + 8);
            #pragma unroll
            for (int i = 0; i < 4; i++)
                split_pack(e[i].x * 0.125f, e[i].y * 0.125f, qhi[kk][i], qlo[kk][i]);
        }
    }

    float o_[8][4];
    #pragma unroll
    for (int ni = 0; ni < 8; ni++)
        #pragma unroll
        for (int r = 0; r < 4; r++) o_[ni][r] = 0.f;
    float m0 = -1e30f, m1 = -1e30f, l0 = 0.f, l1 = 0.f;

    const int nt = q0 / ATN + 1;

    // staging loader: K,V f32 64x64 tiles
    auto stage_kv = [&](int j0, uint32_t dst) {
        #pragma unroll
        for (int i = 0; i < 8; i++) {
            int idx = tid + 128 * i;
            int r  = idx >> 4;
            int c4 = idx & 15;
            size_t base = (bt + j0 + r) * N_EMBD + hc + c4 * 4;
            cp16(dst + r * 256 + c4 * 16, kg + base);
            cp16(dst + 16384 + r * 256 + c4 * 16, vg + base);
        }
        cp_commit();
    };

    stage_kv(0, sb + STG_OFF(0));

    const int cr = tid >> 1;            // conversion row 0..63
    const int ch = (tid & 1) * 32;      // col half

    for (int t = 0; t < nt; t++) {
        const int s = t & 1;
        const int j0 = t * ATN;
        if (t + 1 < nt) {
            stage_kv(j0 + ATN, sb + STG_OFF(s ^ 1));
            asm volatile("cp.async.wait_group 1;" ::: "memory");
        } else {
            asm volatile("cp.async.wait_group 0;" ::: "memory");
        }
        __syncthreads();

        // --- convert stage s -> bf16 tiles ---
        {
            const float* srcK = (const float*)(asmem + STG_OFF(s)) + cr * 64 + ch;
            const float* srcV = (const float*)(asmem + STG_OFF(s) + 16384) + cr * 64 + ch;
            uint32_t hw[16], lw[16];
            #pragma unroll
            for (int i = 0; i < 8; i++) {
                float4 vv = ((const float4*)srcK)[i];
                split_pack(vv.x, vv.y, hw[2 * i], lw[2 * i]);
                split_pack(vv.z, vv.w, hw[2 * i + 1], lw[2 * i + 1]);
            }
            uint32_t* dKh = (uint32_t*)(asmem + KHI_OFF + cr * 144 + ch * 2);
            uint32_t* dKl = (uint32_t*)(asmem + KLO_OFF + cr * 144 + ch * 2);
            #pragma unroll
            for (int i = 0; i < 16; i++) { dKh[i] = hw[i]; dKl[i] = lw[i]; }

            __nv_bfloat16* dVh = (__nv_bfloat16*)(asmem + VTHI_OFF);
            __nv_bfloat16* dVl = (__nv_bfloat16*)(asmem + VTLO_OFF);
            #pragma unroll
            for (int i = 0; i < 8; i++) {
                float4 vv = ((const float4*)srcV)[i];
                float e[4] = {vv.x, vv.y, vv.z, vv.w};
                #pragma unroll
                for (int j = 0; j < 4; j++) {
                    int c = ch + i * 4 + j;
                    __nv_bfloat16 hb = __float2bfloat16_rn(e[j]);
                    dVh[c * KROW + cr] = hb;
                    dVl[c * KROW + cr] = __float2bfloat16_rn(e[j] - __bfloat162float(hb));
                }
            }
        }
        __syncthreads();

        // --- scores: S = Qhi*Khi + Qlo*Khi + Qhi*Klo ---
        float sc[8][4];
        #pragma unroll
        for (int ni = 0; ni < 8; ni++)
            #pragma unroll
            for (int r = 0; r < 4; r++) sc[ni][r] = 0.f;

        #pragma unroll
        for (int kk = 0; kk < 4; kk++) {
            #pragma unroll
            for (int ni = 0; ni < 8; ni++) {
                uint32_t off = (uint32_t)((ni * 8 + g) * 144 + kk * 32 + tg * 4);
                uint32_t h0 = *(const uint32_t*)(asmem + KHI_OFF + off);
                uint32_t h1 = *(const uint32_t*)(asmem + KHI_OFF + off + 16);
                uint32_t l0r = *(const uint32_t*)(asmem + KLO_OFF + off);
                uint32_t l1r = *(const uint32_t*)(asmem + KLO_OFF + off + 16);
                mma_bf16(sc[ni], qhi[kk], h0, h1);
                mma_bf16(sc[ni], qlo[kk], h0, h1);
                mma_bf16(sc[ni], qhi[kk], l0r, l1r);
            }
        }

        // causal mask (only the diagonal tile needs it)
        const int row0 = q0 + wm * 16 + g;
        if (j0 == q0) {
            #pragma unroll
            for (int ni = 0; ni < 8; ni++) {
                #pragma unroll
                for (int e = 0; e < 2; e++) {
                    int col = j0 + ni * 8 + 2 * tg + e;
                    if (col > row0)     sc[ni][e]     = -1e30f;
                    if (col > row0 + 8) sc[ni][2 + e] = -1e30f;
                }
            }
        }

        // --- online softmax update ---
        float mt0 = -1e30f, mt1 = -1e30f;
        #pragma unroll
        for (int ni = 0; ni < 8; ni++) {
            mt0 = fmaxf(mt0, fmaxf(sc[ni][0], sc[ni][1]));
            mt1 = fmaxf(mt1, fmaxf(sc[ni][2], sc[ni][3]));
        }
        mt0 = fmaxf(mt0, __shfl_xor_sync(0xffffffffu, mt0, 1));
        mt0 = fmaxf(mt0, __shfl_xor_sync(0xffffffffu, mt0, 2));
        mt1 = fmaxf(mt1, __shfl_xor_sync(0xffffffffu, mt1, 1));
        mt1 = fmaxf(mt1, __shfl_xor_sync(0xffffffffu, mt1, 2));
        const float mn0 = fmaxf(m0, mt0), mn1 = fmaxf(m1, mt1);
        const float r0f = __expf(m0 - mn0), r1f = __expf(m1 - mn1);

        float s0 = 0.f, s1 = 0.f;
        #pragma unroll
        for (int ni = 0; ni < 8; ni++) {
            sc[ni][0] = __expf(sc[ni][0] - mn0); s0 += sc[ni][0];
            sc[ni][1] = __expf(sc[ni][1] - mn0); s0 += sc[ni][1];
            sc[ni][2] = __expf(sc[ni][2] - mn1); s1 += sc[ni][2];
            sc[ni][3] = __expf(sc[ni][3] - mn1); s1 += sc[ni][3];
        }
        s0 += __shfl_xor_sync(0xffffffffu, s0, 1);
        s0 += __shfl_xor_sync(0xffffffffu, s0, 2);
        s1 += __shfl_xor_sync(0xffffffffu, s1, 1);
        s1 += __shfl_xor_sync(0xffffffffu, s1, 2);
        l0 = l0 * r0f + s0;
        l1 = l1 * r1f + s1;
        m0 = mn0; m1 = mn1;

        #pragma unroll
        for (int ni = 0; ni < 8; ni++) {
            o_[ni][0] *= r0f; o_[ni][1] *= r0f;
            o_[ni][2] *= r1f; o_[ni][3] *= r1f;
        }

        // --- P (C-frag) -> A-operand, bf16 hi/lo split, in registers ---
        uint32_t phi[4][4], plo[4][4];
        #pragma unroll
        for (int kk = 0; kk < 4; kk++) {
            split_pack(sc[2 * kk][0],     sc[2 * kk][1],     phi[kk][0], plo[kk][0]);
            split_pack(sc[2 * kk][2],     sc[2 * kk][3],     phi[kk][1], plo[kk][1]);
            split_pack(sc[2 * kk + 1][0], sc[2 * kk + 1][1], phi[kk][2], plo[kk][2]);
            split_pack(sc[2 * kk + 1][2], sc[2 * kk + 1][3], phi[kk][3], plo[kk][3]);
        }

        // --- O += Phi*Vhi + Plo*Vhi + Phi*Vlo ---
        #pragma unroll
        for (int kk = 0; kk < 4; kk++) {
            #pragma unroll
            for (int ni = 0; ni < 8; ni++) {
                uint32_t off = (uint32_t)((ni * 8 + g) * 144 + kk * 32 + tg * 4);
                uint32_t vh0 = *(const uint32_t*)(asmem + VTHI_OFF + off);
                uint32_t vh1 = *(const uint32_t*)(asmem + VTHI_OFF + off + 16);
                uint32_t vl0 = *(const uint32_t*)(asmem + VTLO_OFF + off);
                uint32_t vl1 = *(const uint32_t*)(asmem + VTLO_OFF + off + 16);
                mma_bf16(o_[ni], phi[kk], vh0, vh1);
                mma_bf16(o_[ni], plo[kk], vh0, vh1);
                mma_bf16(o_[ni], phi[kk], vl0, vl1);
            }
        }
        __syncthreads();
    }

    // --- epilogue ---
    const float i0 = 1.f / l0, i1 = 1.f / l1;
    float* op0 = og + (bt + q0 + wm * 16 + g) * N_EMBD + hc;
    float* op1 = op0 + 8 * N_EMBD;
    #pragma unroll
    for (int ni = 0; ni < 8; ni++) {
        *(float2*)(op0 + ni * 8 + 2 * tg) = make_float2(o_[ni][0] * i0, o_[ni][1] * i0);
        *(float2*)(op1 + ni * 8 + 2 * tg) = make_float2(o_[ni][2] * i1, o_[ni][3] * i1);
    }
}

// ---------------- launch ----------------
extern "C" void kernel_launch(void* const* d_in, const int* in_sizes, int n_in,
                              void* d_out, int out_size)
{
    const float* x  = (const float*)d_in[0];
    const float* Wq = (const float*)d_in[1];
    const float* bq = (const float*)d_in[2];
    const float* Wk = (const float*)d_in[3];
    const float* bk = (const float*)d_in[4];
    const float* Wv = (const float*)d_in[5];
    const float* bv = (const float*)d_in[6];
    const float* Wo = (const float*)d_in[7];
    const float* bo = (const float*)d_in[8];
    float* out = (float*)d_out;

    float *qp, *kp, *vp, *ap;
    uint32_t *xt, *wt;
    cudaGetSymbolAddress((void**)&qp, g_q);
    cudaGetSymbolAddress((void**)&kp, g_k);
    cudaGetSymbolAddress((void**)&vp, g_v);
    cudaGetSymbolAddress((void**)&ap, g_att);
    cudaGetSymbolAddress((void**)&xt, g_xt);
    cudaGetSymbolAddress((void**)&wt, g_wt);

    cudaFuncSetAttribute(gemm_tc_kernel, cudaFuncAttributeMaxDynamicSharedMemorySize, GSMEM);
    cudaFuncSetAttribute(attn_tc_kernel, cudaFuncAttributeMaxDynamicSharedMemorySize, ASMEM);

    const int nx4 = M_TOT * N_EMBD / 4;
    const int nw4 = N_EMBD * N_EMBD / 4;

    dim3 ggrid(N_EMBD / CTN, M_TOT / CTM);   // (8, 32)

    tf32_cvt_kernel<<<nx4 / 256, 256>>>(x, xt, nx4);

    tf32_cvt_kernel<<<nw4 / 256, 256>>>(Wq, wt, nw4);
    gemm_tc_kernel<<<ggrid, 256, GSMEM>>>(xt, wt, bq, qp, M_TOT, N_EMBD);

    tf32_cvt_kernel<<<nw4 / 256, 256>>>(Wk, wt, nw4);
    gemm_tc_kernel<<<ggrid, 256, GSMEM>>>(xt, wt, bk, kp, M_TOT, N_EMBD);

    tf32_cvt_kernel<<<nw4 / 256, 256>>>(Wv, wt, nw4);
    gemm_tc_kernel<<<ggrid, 256, GSMEM>>>(xt, wt, bv, vp, M_TOT, N_EMBD);

    dim3 agrid(SEQ / ATM, BATCH * N_HEAD);   // (32, 32)
    attn_tc_kernel<<<agrid, 128, ASMEM>>>(qp, kp, vp, ap);

    tf32_cvt_kernel<<<nx4 / 256, 256>>>(ap, xt, nx4);
    tf32_cvt_kernel<<<nw4 / 256, 256>>>(Wo, wt, nw4);
    gemm_tc_kernel<<<ggrid, 256, GSMEM>>>(xt, wt, bo, out, M_TOT, N_EMBD);
}

// round 9
// speedup vs baseline: 4.9167x; 1.1109x over previous
#include <cuda_runtime.h>
#include <cuda_bf16.h>
#include <math.h>
#include <stdint.h>

#define N_EMBD   1024
#define N_HEAD   16
#define HEAD_DIM 64
#define BATCH    2
#define SEQ      2048
#define M_TOT    (BATCH * SEQ)

typedef unsigned long long u64;

// ---------------- cp.async helpers ----------------
__device__ __forceinline__ uint32_t smem_u32(const void* p) {
    uint32_t a;
    asm("{ .reg .u64 t; cvta.to.shared.u64 t, %1; cvt.u32.u64 %0, t; }" : "=r"(a) : "l"(p));
    return a;
}
__device__ __forceinline__ void cp16(uint32_t s, const void* g) {
    asm volatile("cp.async.cg.shared.global [%0], [%1], 16;" :: "r"(s), "l"(g));
}
__device__ __forceinline__ void cp_commit() {
    asm volatile("cp.async.commit_group;" ::: "memory");
}

// ---------------- bf16 split/pack ----------------
__device__ __forceinline__ void split_pack(float x0, float x1, uint32_t& hi, uint32_t& lo) {
    __nv_bfloat16 h0 = __float2bfloat16_rn(x0), h1 = __float2bfloat16_rn(x1);
    __nv_bfloat16 l0 = __float2bfloat16_rn(x0 - __bfloat162float(h0));
    __nv_bfloat16 l1 = __float2bfloat16_rn(x1 - __bfloat162float(h1));
    hi = (uint32_t)__bfloat16_as_ushort(h0) | ((uint32_t)__bfloat16_as_ushort(h1) << 16);
    lo = (uint32_t)__bfloat16_as_ushort(l0) | ((uint32_t)__bfloat16_as_ushort(l1) << 16);
}

// ---------------- scratch (device globals: allocation-free) ----------------
__device__ float g_q[(size_t)M_TOT * N_EMBD];
__device__ float g_k[(size_t)M_TOT * N_EMBD];
__device__ float g_v[(size_t)M_TOT * N_EMBD];
__device__ float g_att[(size_t)M_TOT * N_EMBD];
__device__ uint32_t g_xt[(size_t)M_TOT * N_EMBD];   // tf32 activations
__device__ uint32_t g_wt[(size_t)N_EMBD * N_EMBD];  // tf32 weights

// ---------------- fp32 -> tf32 (rna) pre-pass ----------------
__global__ __launch_bounds__(256) void tf32_cvt_kernel(
    const float* __restrict__ src, uint32_t* __restrict__ dst, int n4)
{
    int i = blockIdx.x * blockDim.x + threadIdx.x;
    if (i >= n4) return;
    float4 v = ((const float4*)src)[i];
    uint4 o;
    asm("cvt.rna.tf32.f32 %0, %1;" : "=r"(o.x) : "f"(v.x));
    asm("cvt.rna.tf32.f32 %0, %1;" : "=r"(o.y) : "f"(v.y));
    asm("cvt.rna.tf32.f32 %0, %1;" : "=r"(o.z) : "f"(v.z));
    asm("cvt.rna.tf32.f32 %0, %1;" : "=r"(o.w) : "f"(v.w));
    ((uint4*)dst)[i] = o;
}

// ================= tf32 mma.sync GEMM (round-6, passing) ===================
#define CTM 128
#define CTN 128
#define CBK 32
#define NCH (N_EMBD / CBK)
#define STW 4096
#define GSMEM (4 * STW * 4)

__device__ __forceinline__ void mma_tf32(float* c, const uint32_t* a,
                                         uint32_t b0, uint32_t b1) {
    asm volatile(
        "mma.sync.aligned.m16n8k8.row.col.f32.tf32.tf32.f32 "
        "{%0,%1,%2,%3}, {%4,%5,%6,%7}, {%8,%9}, {%0,%1,%2,%3};"
        : "+f"(c[0]), "+f"(c[1]), "+f"(c[2]), "+f"(c[3])
        : "r"(a[0]), "r"(a[1]), "r"(a[2]), "r"(a[3]), "r"(b0), "r"(b1));
}

__device__ __forceinline__ void load_op(const uint32_t* __restrict__ g,
                                        int rowbase, int kc,
                                        uint32_t sm_t, int tid)
{
    #pragma unroll
    for (int j = 0; j < 4; j++) {
        int idx = tid + 256 * j;
        int row = idx >> 3;
        int k4  = idx & 7;
        const void* gp = g + (size_t)(rowbase + row) * N_EMBD + kc * CBK + k4 * 4;
        uint32_t w = row * 32 + ((k4 * 4) ^ ((row & 7) * 4));
        cp16(sm_t + w * 4, gp);
    }
}

__global__ __launch_bounds__(256) void gemm_tc_kernel(
    const uint32_t* __restrict__ A, const uint32_t* __restrict__ B,
    const float* __restrict__ bias, float* __restrict__ C,
    int M, int N)
{
    extern __shared__ __align__(16) uint32_t gsm[];
    const uint32_t sb = smem_u32(gsm);
    const int tid  = threadIdx.x;
    const int wid  = tid >> 5;
    const int lane = tid & 31;
    const int g  = lane >> 2;
    const int tg = lane & 3;
    const int wm = wid >> 1;
    const int wn = wid & 1;
    const int m0 = blockIdx.y * CTM;
    const int n0 = blockIdx.x * CTN;
    const int xr = 4 * g;

    uint32_t sA[2] = {sb, sb + STW * 4};
    uint32_t sB[2] = {sb + 2 * STW * 4, sb + 3 * STW * 4};

    #pragma unroll
    for (int c = 0; c < 2; c++) {
        load_op(A, m0, c, sA[c], tid);
        load_op(B, n0, c, sB[c], tid);
        cp_commit();
    }

    float acc[2][8][4];
    #pragma unroll
    for (int mi = 0; mi < 2; mi++)
        #pragma unroll
        for (int ni = 0; ni < 8; ni++)
            #pragma unroll
            for (int r = 0; r < 4; r++) acc[mi][ni][r] = 0.f;

    for (int c = 0; c < NCH; c++) {
        const int s = c & 1;
        if (c == NCH - 1) asm volatile("cp.async.wait_group 0;" ::: "memory");
        else              asm volatile("cp.async.wait_group 1;" ::: "memory");
        __syncthreads();

        const uint32_t* As = gsm + (sA[s] - sb) / 4;
        const uint32_t* Bs = gsm + (sB[s] - sb) / 4;

        #pragma unroll
        for (int kk = 0; kk < 4; kk++) {
            const int k = kk * 8;
            const int x0 = (k + tg) ^ xr;
            const int x1 = (k + tg + 4) ^ xr;

            uint32_t a[2][4];
            #pragma unroll
            for (int mi = 0; mi < 2; mi++) {
                const uint32_t* base = As + (wm * 32 + mi * 16 + g) * 32;
                a[mi][0] = base[x0];
                a[mi][1] = base[256 + x0];
                a[mi][2] = base[x1];
                a[mi][3] = base[256 + x1];
            }
            #pragma unroll
            for (int ni = 0; ni < 8; ni++) {
                const uint32_t* bb = Bs + (wn * 64 + ni * 8 + g) * 32;
                uint32_t b0 = bb[x0];
                uint32_t b1 = bb[x1];
                mma_tf32(acc[0][ni], a[0], b0, b1);
                mma_tf32(acc[1][ni], a[1], b0, b1);
            }
        }
        __syncthreads();

        if (c + 2 < NCH) {
            load_op(A, m0, c + 2, sA[s], tid);
            load_op(B, n0, c + 2, sB[s], tid);
            cp_commit();
        }
    }

    #pragma unroll
    for (int mi = 0; mi < 2; mi++) {
        const int r0 = m0 + wm * 32 + mi * 16 + g;
        #pragma unroll
        for (int ni = 0; ni < 8; ni++) {
            const int col = n0 + wn * 64 + ni * 8 + 2 * tg;
            float b0v = bias[col], b1v = bias[col + 1];
            float2 lo = make_float2(acc[mi][ni][0] + b0v, acc[mi][ni][1] + b1v);
            float2 hi = make_float2(acc[mi][ni][2] + b0v, acc[mi][ni][3] + b1v);
            *(float2*)&C[(size_t)r0 * N + col]       = lo;
            *(float2*)&C[(size_t)(r0 + 8) * N + col] = hi;
        }
    }
}

// ================= tensor-core causal flash attention ======================
// CTA: 128 queries x one (b,h); 8 warps x m16 rows; key tiles of 64; 256 thr.
// bf16 3-term split (hi*hi + hi*lo + lo*hi) for QK^T and P*V.
// K bf16 [key][dim] rows padded to 144 B  -> mma B-loads conflict-free.
// V bf16 transposed [dim][key] rows padded to 176 B -> (12g+tg)%32 is a
// permutation: mma B-loads conflict-free; transpose writes are packed u32.
#define ATM 128
#define ATN 64
#define STG_OFF(s) ((s) * 32768)      // f32 staging: K at +0, V at +16384
#define KHI_OFF  65536
#define KLO_OFF  74752
#define VTHI_OFF 83968
#define VTLO_OFF 95232
#define ASMEM    106496

__device__ __forceinline__ void mma_bf16(float* c, const uint32_t* a,
                                         uint32_t b0, uint32_t b1) {
    asm volatile(
        "mma.sync.aligned.m16n8k16.row.col.f32.bf16.bf16.f32 "
        "{%0,%1,%2,%3}, {%4,%5,%6,%7}, {%8,%9}, {%0,%1,%2,%3};"
        : "+f"(c[0]), "+f"(c[1]), "+f"(c[2]), "+f"(c[3])
        : "r"(a[0]), "r"(a[1]), "r"(a[2]), "r"(a[3]), "r"(b0), "r"(b1));
}

__global__ __launch_bounds__(256) void attn_tc_kernel(
    const float* __restrict__ qg, const float* __restrict__ kg,
    const float* __restrict__ vg, float* __restrict__ og)
{
    extern __shared__ __align__(16) char asmem[];
    const uint32_t sb = smem_u32(asmem);
    const int tid  = threadIdx.x;
    const int wm   = tid >> 5;          // 0..7
    const int lane = tid & 31;
    const int g    = lane >> 2;
    const int tg   = lane & 3;
    const int q0   = blockIdx.x * ATM;
    const int bh   = blockIdx.y;
    const int b    = bh >> 4;
    const int h    = bh & 15;

    const size_t bt = (size_t)b * SEQ;
    const int hc = h * HEAD_DIM;

    // --- Q fragments (pre-scaled by 1/sqrt(D)), bf16 hi/lo split, in regs ---
    uint32_t qhi[4][4], qlo[4][4];
    {
        const float* qr0 = qg + (bt + q0 + wm * 16 + g) * N_EMBD + hc;
        const float* qr1 = qr0 + 8 * N_EMBD;
        #pragma unroll
        for (int kk = 0; kk < 4; kk++) {
            float2 e[4];
            e[0] = *(const float2*)(qr0 + kk * 16 + 2 * tg);
            e[1] = *(const float2*)(qr1 + kk * 16 + 2 * tg);
            e[2] = *(const float2*)(qr0 + kk * 16 + 2 * tg + 8);
            e[3] = *(const float2*)(qr1 + kk * 16 + 2 * tg + 8);
            #pragma unroll
            for (int i = 0; i < 4; i++)
                split_pack(e[i].x * 0.125f, e[i].y * 0.125f, qhi[kk][i], qlo[kk][i]);
        }
    }

    float o_[8][4];
    #pragma unroll
    for (int ni = 0; ni < 8; ni++)
        #pragma unroll
        for (int r = 0; r < 4; r++) o_[ni][r] = 0.f;
    float m0 = -1e30f, m1 = -1e30f, l0 = 0.f, l1 = 0.f;

    const int nt = (q0 + ATM) / ATN;    // q0/64 + 2

    // staging loader: K,V f32 64x64 tiles (8 cp16 per thread)
    auto stage_kv = [&](int j0, uint32_t dst) {
        #pragma unroll
        for (int i = 0; i < 4; i++) {
            int idx = tid + 256 * i;     // 0..1023
            int r  = idx >> 4;
            int c4 = idx & 15;
            size_t base = (bt + j0 + r) * N_EMBD + hc + c4 * 4;
            cp16(dst + r * 256 + c4 * 16, kg + base);
            cp16(dst + 16384 + r * 256 + c4 * 16, vg + base);
        }
        cp_commit();
    };

    stage_kv(0, sb + STG_OFF(0));

    const int row0  = q0 + wm * 16 + g;
    const int rmax  = q0 + wm * 16 + 15;

    for (int t = 0; t < nt; t++) {
        const int s = t & 1;
        const int j0 = t * ATN;
        if (t + 1 < nt) {
            stage_kv(j0 + ATN, sb + STG_OFF(s ^ 1));
            asm volatile("cp.async.wait_group 1;" ::: "memory");
        } else {
            asm volatile("cp.async.wait_group 0;" ::: "memory");
        }
        __syncthreads();

        // --- convert stage s -> bf16 planes (all 256 threads) ---
        if (tid < 128) {
            // K: [key][dim], 144 B rows; thread = (row, col-half)
            const int r  = tid >> 1;
            const int ch = (tid & 1) * 32;
            const float* srcK = (const float*)(asmem + STG_OFF(s)) + r * 64 + ch;
            uint32_t* dKh = (uint32_t*)(asmem + KHI_OFF + r * 144 + ch * 2);
            uint32_t* dKl = (uint32_t*)(asmem + KLO_OFF + r * 144 + ch * 2);
            #pragma unroll
            for (int i = 0; i < 8; i++) {
                float4 vv = ((const float4*)srcK)[i];
                uint32_t h0, l0w, h1, l1w;
                split_pack(vv.x, vv.y, h0, l0w);
                split_pack(vv.z, vv.w, h1, l1w);
                dKh[2 * i] = h0; dKh[2 * i + 1] = h1;
                dKl[2 * i] = l0w; dKl[2 * i + 1] = l1w;
            }
        } else {
            // V transpose: [dim][key-pairs], 176 B rows; thread = (dim, kp half)
            const int t2  = tid - 128;
            const int d   = t2 >> 1;           // 0..63
            const int kp0 = (t2 & 1) * 16;     // key-pair base
            const float* srcV = (const float*)(asmem + STG_OFF(s) + 16384);
            uint32_t* dVh = (uint32_t*)(asmem + VTHI_OFF + d * 176);
            uint32_t* dVl = (uint32_t*)(asmem + VTLO_OFF + d * 176);
            #pragma unroll
            for (int i = 0; i < 16; i++) {
                int kp = kp0 + i;
                float x0 = srcV[(2 * kp) * 64 + d];
                float x1 = srcV[(2 * kp + 1) * 64 + d];
                uint32_t hv, lv;
                split_pack(x0, x1, hv, lv);
                dVh[kp] = hv; dVl[kp] = lv;
            }
        }
        __syncthreads();

        if (j0 <= rmax) {   // warp has at least one unmasked column
            // --- scores: S = Qhi*Khi + Qlo*Khi + Qhi*Klo ---
            float sc[8][4];
            #pragma unroll
            for (int ni = 0; ni < 8; ni++)
                #pragma unroll
                for (int r = 0; r < 4; r++) sc[ni][r] = 0.f;

            #pragma unroll
            for (int kk = 0; kk < 4; kk++) {
                #pragma unroll
                for (int ni = 0; ni < 8; ni++) {
                    uint32_t off = (uint32_t)((ni * 8 + g) * 144 + kk * 32 + tg * 4);
                    uint32_t h0 = *(const uint32_t*)(asmem + KHI_OFF + off);
                    uint32_t h1 = *(const uint32_t*)(asmem + KHI_OFF + off + 16);
                    uint32_t l0r = *(const uint32_t*)(asmem + KLO_OFF + off);
                    uint32_t l1r = *(const uint32_t*)(asmem + KLO_OFF + off + 16);
                    mma_bf16(sc[ni], qhi[kk], h0, h1);
                    mma_bf16(sc[ni], qlo[kk], h0, h1);
                    mma_bf16(sc[ni], qhi[kk], l0r, l1r);
                }
            }

            // causal mask (tiles overlapping the diagonal for this warp)
            if (j0 + 63 > row0) {
                #pragma unroll
                for (int ni = 0; ni < 8; ni++) {
                    #pragma unroll
                    for (int e = 0; e < 2; e++) {
                        int col = j0 + ni * 8 + 2 * tg + e;
                        if (col > row0)     sc[ni][e]     = -1e30f;
                        if (col > row0 + 8) sc[ni][2 + e] = -1e30f;
                    }
                }
            }

            // --- online softmax update ---
            float mt0 = -1e30f, mt1 = -1e30f;
            #pragma unroll
            for (int ni = 0; ni < 8; ni++) {
                mt0 = fmaxf(mt0, fmaxf(sc[ni][0], sc[ni][1]));
                mt1 = fmaxf(mt1, fmaxf(sc[ni][2], sc[ni][3]));
            }
            mt0 = fmaxf(mt0, __shfl_xor_sync(0xffffffffu, mt0, 1));
            mt0 = fmaxf(mt0, __shfl_xor_sync(0xffffffffu, mt0, 2));
            mt1 = fmaxf(mt1, __shfl_xor_sync(0xffffffffu, mt1, 1));
            mt1 = fmaxf(mt1, __shfl_xor_sync(0xffffffffu, mt1, 2));
            const float mn0 = fmaxf(m0, mt0), mn1 = fmaxf(m1, mt1);
            const float r0f = __expf(m0 - mn0), r1f = __expf(m1 - mn1);

            float s0 = 0.f, s1 = 0.f;
            #pragma unroll
            for (int ni = 0; ni < 8; ni++) {
                sc[ni][0] = __expf(sc[ni][0] - mn0); s0 += sc[ni][0];
                sc[ni][1] = __expf(sc[ni][1] - mn0); s0 += sc[ni][1];
                sc[ni][2] = __expf(sc[ni][2] - mn1); s1 += sc[ni][2];
                sc[ni][3] = __expf(sc[ni][3] - mn1); s1 += sc[ni][3];
            }
            s0 += __shfl_xor_sync(0xffffffffu, s0, 1);
            s0 += __shfl_xor_sync(0xffffffffu, s0, 2);
            s1 += __shfl_xor_sync(0xffffffffu, s1, 1);
            s1 += __shfl_xor_sync(0xffffffffu, s1, 2);
            l0 = l0 * r0f + s0;
            l1 = l1 * r1f + s1;
            m0 = mn0; m1 = mn1;

            #pragma unroll
            for (int ni = 0; ni < 8; ni++) {
                o_[ni][0] *= r0f; o_[ni][1] *= r0f;
                o_[ni][2] *= r1f; o_[ni][3] *= r1f;
            }

            // --- P (C-frag) -> A-operand, bf16 hi/lo split, in registers ---
            uint32_t phi[4][4], plo[4][4];
            #pragma unroll
            for (int kk = 0; kk < 4; kk++) {
                split_pack(sc[2 * kk][0],     sc[2 * kk][1],     phi[kk][0], plo[kk][0]);
                split_pack(sc[2 * kk][2],     sc[2 * kk][3],     phi[kk][1], plo[kk][1]);
                split_pack(sc[2 * kk + 1][0], sc[2 * kk + 1][1], phi[kk][2], plo[kk][2]);
                split_pack(sc[2 * kk + 1][2], sc[2 * kk + 1][3], phi[kk][3], plo[kk][3]);
            }

            // --- O += Phi*Vhi + Plo*Vhi + Phi*Vlo ---
            #pragma unroll
            for (int kk = 0; kk < 4; kk++) {
                #pragma unroll
                for (int ni = 0; ni < 8; ni++) {
                    uint32_t off = (uint32_t)((ni * 8 + g) * 176 + kk * 32 + tg * 4);
                    uint32_t vh0 = *(const uint32_t*)(asmem + VTHI_OFF + off);
                    uint32_t vh1 = *(const uint32_t*)(asmem + VTHI_OFF + off + 16);
                    uint32_t vl0 = *(const uint32_t*)(asmem + VTLO_OFF + off);
                    uint32_t vl1 = *(const uint32_t*)(asmem + VTLO_OFF + off + 16);
                    mma_bf16(o_[ni], phi[kk], vh0, vh1);
                    mma_bf16(o_[ni], plo[kk], vh0, vh1);
                    mma_bf16(o_[ni], phi[kk], vl0, vl1);
                }
            }
        }
        __syncthreads();
    }

    // --- epilogue ---
    const float i0 = 1.f / l0, i1 = 1.f / l1;
    float* op0 = og + (bt + q0 + wm * 16 + g) * N_EMBD + hc;
    float* op1 = op0 + 8 * N_EMBD;
    #pragma unroll
    for (int ni = 0; ni < 8; ni++) {
        *(float2*)(op0 + ni * 8 + 2 * tg) = make_float2(o_[ni][0] * i0, o_[ni][1] * i0);
        *(float2*)(op1 + ni * 8 + 2 * tg) = make_float2(o_[ni][2] * i1, o_[ni][3] * i1);
    }
}

// ---------------- launch ----------------
extern "C" void kernel_launch(void* const* d_in, const int* in_sizes, int n_in,
                              void* d_out, int out_size)
{
    const float* x  = (const float*)d_in[0];
    const float* Wq = (const float*)d_in[1];
    const float* bq = (const float*)d_in[2];
    const float* Wk = (const float*)d_in[3];
    const float* bk = (const float*)d_in[4];
    const float* Wv = (const float*)d_in[5];
    const float* bv = (const float*)d_in[6];
    const float* Wo = (const float*)d_in[7];
    const float* bo = (const float*)d_in[8];
    float* out = (float*)d_out;

    float *qp, *kp, *vp, *ap;
    uint32_t *xt, *wt;
    cudaGetSymbolAddress((void**)&qp, g_q);
    cudaGetSymbolAddress((void**)&kp, g_k);
    cudaGetSymbolAddress((void**)&vp, g_v);
    cudaGetSymbolAddress((void**)&ap, g_att);
    cudaGetSymbolAddress((void**)&xt, g_xt);
    cudaGetSymbolAddress((void**)&wt, g_wt);

    cudaFuncSetAttribute(gemm_tc_kernel, cudaFuncAttributeMaxDynamicSharedMemorySize, GSMEM);
    cudaFuncSetAttribute(attn_tc_kernel, cudaFuncAttributeMaxDynamicSharedMemorySize, ASMEM);

    const int nx4 = M_TOT * N_EMBD / 4;
    const int nw4 = N_EMBD * N_EMBD / 4;

    dim3 ggrid(N_EMBD / CTN, M_TOT / CTM);   // (8, 32)

    tf32_cvt_kernel<<<nx4 / 256, 256>>>(x, xt, nx4);

    tf32_cvt_kernel<<<nw4 / 256, 256>>>(Wq, wt, nw4);
    gemm_tc_kernel<<<ggrid, 256, GSMEM>>>(xt, wt, bq, qp, M_TOT, N_EMBD);

    tf32_cvt_kernel<<<nw4 / 256, 256>>>(Wk, wt, nw4);
    gemm_tc_kernel<<<ggrid, 256, GSMEM>>>(xt, wt, bk, kp, M_TOT, N_EMBD);

    tf32_cvt_kernel<<<nw4 / 256, 256>>>(Wv, wt, nw4);
    gemm_tc_kernel<<<ggrid, 256, GSMEM>>>(xt, wt, bv, vp, M_TOT, N_EMBD);

    dim3 agrid(SEQ / ATM, BATCH * N_HEAD);   // (16, 32)
    attn_tc_kernel<<<agrid, 256, ASMEM>>>(qp, kp, vp, ap);

    tf32_cvt_kernel<<<nx4 / 256, 256>>>(ap, xt, nx4);
    tf32_cvt_kernel<<<nw4 / 256, 256>>>(Wo, wt, nw4);
    gemm_tc_kernel<<<ggrid, 256, GSMEM>>>(xt, wt, bo, out, M_TOT, N_EMBD);
}

// round 11
// speedup vs baseline: 5.6388x; 1.1469x over previous
#include <cuda_runtime.h>
#include <cuda_bf16.h>
#include <math.h>
#include <stdint.h>

#define N_EMBD   1024
#define N_HEAD   16
#define HEAD_DIM 64
#define BATCH    2
#define SEQ      2048
#define M_TOT    (BATCH * SEQ)

typedef unsigned long long u64;

// ---------------- cp.async helpers ----------------
__device__ __forceinline__ uint32_t smem_u32(const void* p) {
    uint32_t a;
    asm("{ .reg .u64 t; cvta.to.shared.u64 t, %1; cvt.u32.u64 %0, t; }" : "=r"(a) : "l"(p));
    return a;
}
__device__ __forceinline__ void cp16(uint32_t s, const void* g) {
    asm volatile("cp.async.cg.shared.global [%0], [%1], 16;" :: "r"(s), "l"(g));
}
__device__ __forceinline__ void cp_commit() {
    asm volatile("cp.async.commit_group;" ::: "memory");
}

// ---------------- bf16 split/pack ----------------
__device__ __forceinline__ void split_pack(float x0, float x1, uint32_t& hi, uint32_t& lo) {
    __nv_bfloat16 h0 = __float2bfloat16_rn(x0), h1 = __float2bfloat16_rn(x1);
    __nv_bfloat16 l0 = __float2bfloat16_rn(x0 - __bfloat162float(h0));
    __nv_bfloat16 l1 = __float2bfloat16_rn(x1 - __bfloat162float(h1));
    hi = (uint32_t)__bfloat16_as_ushort(h0) | ((uint32_t)__bfloat16_as_ushort(h1) << 16);
    lo = (uint32_t)__bfloat16_as_ushort(l0) | ((uint32_t)__bfloat16_as_ushort(l1) << 16);
}

// ---------------- scratch (device globals: allocation-free) ----------------
__device__ float g_q[(size_t)M_TOT * N_EMBD];
__device__ float g_k[(size_t)M_TOT * N_EMBD];
__device__ float g_v[(size_t)M_TOT * N_EMBD];
__device__ float g_att[(size_t)M_TOT * N_EMBD];
__device__ uint32_t g_xt[(size_t)M_TOT * N_EMBD];        // tf32 activations
__device__ uint32_t g_wt[(size_t)N_EMBD * N_EMBD];       // tf32 weights
__device__ __nv_bfloat16 g_khi[(size_t)M_TOT * N_EMBD];  // K hi (layout of k)
__device__ __nv_bfloat16 g_klo[(size_t)M_TOT * N_EMBD];  // K lo
__device__ __nv_bfloat16 g_vthi[(size_t)M_TOT * N_EMBD]; // V^T hi [bh][dim][SEQ]
__device__ __nv_bfloat16 g_vtlo[(size_t)M_TOT * N_EMBD]; // V^T lo

// ---------------- fp32 -> tf32 (rna) pre-pass ----------------
__global__ __launch_bounds__(256) void tf32_cvt_kernel(
    const float* __restrict__ src, uint32_t* __restrict__ dst, int n4)
{
    int i = blockIdx.x * blockDim.x + threadIdx.x;
    if (i >= n4) return;
    float4 v = ((const float4*)src)[i];
    uint4 o;
    asm("cvt.rna.tf32.f32 %0, %1;" : "=r"(o.x) : "f"(v.x));
    asm("cvt.rna.tf32.f32 %0, %1;" : "=r"(o.y) : "f"(v.y));
    asm("cvt.rna.tf32.f32 %0, %1;" : "=r"(o.z) : "f"(v.z));
    asm("cvt.rna.tf32.f32 %0, %1;" : "=r"(o.w) : "f"(v.w));
    ((uint4*)dst)[i] = o;
}

// ---------------- fp32 -> bf16 hi/lo split (streaming) ----------------
__global__ __launch_bounds__(256) void ksplit_kernel(
    const float* __restrict__ src, __nv_bfloat16* __restrict__ hi,
    __nv_bfloat16* __restrict__ lo, int n4)
{
    int i = blockIdx.x * blockDim.x + threadIdx.x;
    if (i >= n4) return;
    float4 v = ((const float4*)src)[i];
    uint2 ph, pl;
    split_pack(v.x, v.y, ph.x, pl.x);
    split_pack(v.z, v.w, ph.y, pl.y);
    ((uint2*)hi)[i] = ph;
    ((uint2*)lo)[i] = pl;
}

// ---------------- V transpose + split: v[b,key,h*64+d] -> vt[bh][d][SEQ] ----
__global__ __launch_bounds__(256) void vtsplit_kernel(
    const float* __restrict__ v, __nv_bfloat16* __restrict__ vthi,
    __nv_bfloat16* __restrict__ vtlo)
{
    __shared__ __align__(16) float tile[64][68];
    const int tid = threadIdx.x;
    const int j0  = blockIdx.x * 64;
    const int bh  = blockIdx.y;
    const int b   = bh >> 4;
    const int h   = bh & 15;

    // load 64 keys x 64 dims (coalesced float4)
    #pragma unroll
    for (int i = 0; i < 4; i++) {
        int idx = tid + 256 * i;
        int r  = idx >> 4;
        int c4 = idx & 15;
        float4 t = *(const float4*)&v[((size_t)b * SEQ + j0 + r) * N_EMBD + h * HEAD_DIM + c4 * 4];
        *(float4*)&tile[r][c4 * 4] = t;
    }
    __syncthreads();

    // write transposed: thread = (dim d, key quarter q), 16 keys each
    const int d = tid >> 2;
    const int q = tid & 3;
    uint4 oh[2], ol[2];
    #pragma unroll
    for (int half = 0; half < 2; half++) {
        uint32_t hw[4], lw[4];
        #pragma unroll
        for (int p = 0; p < 4; p++) {
            int key = q * 16 + half * 8 + p * 2;
            split_pack(tile[key][d], tile[key + 1][d], hw[p], lw[p]);
        }
        oh[half] = make_uint4(hw[0], hw[1], hw[2], hw[3]);
        ol[half] = make_uint4(lw[0], lw[1], lw[2], lw[3]);
    }
    size_t base = ((size_t)bh * HEAD_DIM + d) * SEQ + j0 + q * 16;
    *(uint4*)&vthi[base]     = oh[0];
    *(uint4*)&vthi[base + 8] = oh[1];
    *(uint4*)&vtlo[base]     = ol[0];
    *(uint4*)&vtlo[base + 8] = ol[1];
}

// ================= tf32 mma.sync GEMM (round-6, passing) ===================
#define CTM 128
#define CTN 128
#define CBK 32
#define NCH (N_EMBD / CBK)
#define STW 4096
#define GSMEM (4 * STW * 4)

__device__ __forceinline__ void mma_tf32(float* c, const uint32_t* a,
                                         uint32_t b0, uint32_t b1) {
    asm volatile(
        "mma.sync.aligned.m16n8k8.row.col.f32.tf32.tf32.f32 "
        "{%0,%1,%2,%3}, {%4,%5,%6,%7}, {%8,%9}, {%0,%1,%2,%3};"
        : "+f"(c[0]), "+f"(c[1]), "+f"(c[2]), "+f"(c[3])
        : "r"(a[0]), "r"(a[1]), "r"(a[2]), "r"(a[3]), "r"(b0), "r"(b1));
}

__device__ __forceinline__ void load_op(const uint32_t* __restrict__ g,
                                        int rowbase, int kc,
                                        uint32_t sm_t, int tid)
{
    #pragma unroll
    for (int j = 0; j < 4; j++) {
        int idx = tid + 256 * j;
        int row = idx >> 3;
        int k4  = idx & 7;
        const void* gp = g + (size_t)(rowbase + row) * N_EMBD + kc * CBK + k4 * 4;
        uint32_t w = row * 32 + ((k4 * 4) ^ ((row & 7) * 4));
        cp16(sm_t + w * 4, gp);
    }
}

__global__ __launch_bounds__(256) void gemm_tc_kernel(
    const uint32_t* __restrict__ A, const uint32_t* __restrict__ B,
    const float* __restrict__ bias, float* __restrict__ C,
    int M, int N)
{
    extern __shared__ __align__(16) uint32_t gsm[];
    const uint32_t sb = smem_u32(gsm);
    const int tid  = threadIdx.x;
    const int wid  = tid >> 5;
    const int lane = tid & 31;
    const int g  = lane >> 2;
    const int tg = lane & 3;
    const int wm = wid >> 1;
    const int wn = wid & 1;
    const int m0 = blockIdx.y * CTM;
    const int n0 = blockIdx.x * CTN;
    const int xr = 4 * g;

    uint32_t sA[2] = {sb, sb + STW * 4};
    uint32_t sB[2] = {sb + 2 * STW * 4, sb + 3 * STW * 4};

    #pragma unroll
    for (int c = 0; c < 2; c++) {
        load_op(A, m0, c, sA[c], tid);
        load_op(B, n0, c, sB[c], tid);
        cp_commit();
    }

    float acc[2][8][4];
    #pragma unroll
    for (int mi = 0; mi < 2; mi++)
        #pragma unroll
        for (int ni = 0; ni < 8; ni++)
            #pragma unroll
            for (int r = 0; r < 4; r++) acc[mi][ni][r] = 0.f;

    for (int c = 0; c < NCH; c++) {
        const int s = c & 1;
        if (c == NCH - 1) asm volatile("cp.async.wait_group 0;" ::: "memory");
        else              asm volatile("cp.async.wait_group 1;" ::: "memory");
        __syncthreads();

        const uint32_t* As = gsm + (sA[s] - sb) / 4;
        const uint32_t* Bs = gsm + (sB[s] - sb) / 4;

        #pragma unroll
        for (int kk = 0; kk < 4; kk++) {
            const int k = kk * 8;
            const int x0 = (k + tg) ^ xr;
            const int x1 = (k + tg + 4) ^ xr;

            uint32_t a[2][4];
            #pragma unroll
            for (int mi = 0; mi < 2; mi++) {
                const uint32_t* base = As + (wm * 32 + mi * 16 + g) * 32;
                a[mi][0] = base[x0];
                a[mi][1] = base[256 + x0];
                a[mi][2] = base[x1];
                a[mi][3] = base[256 + x1];
            }
            #pragma unroll
            for (int ni = 0; ni < 8; ni++) {
                const uint32_t* bb = Bs + (wn * 64 + ni * 8 + g) * 32;
                uint32_t b0 = bb[x0];
                uint32_t b1 = bb[x1];
                mma_tf32(acc[0][ni], a[0], b0, b1);
                mma_tf32(acc[1][ni], a[1], b0, b1);
            }
        }
        __syncthreads();

        if (c + 2 < NCH) {
            load_op(A, m0, c + 2, sA[s], tid);
            load_op(B, n0, c + 2, sB[s], tid);
            cp_commit();
        }
    }

    #pragma unroll
    for (int mi = 0; mi < 2; mi++) {
        const int r0 = m0 + wm * 32 + mi * 16 + g;
        #pragma unroll
        for (int ni = 0; ni < 8; ni++) {
            const int col = n0 + wn * 64 + ni * 8 + 2 * tg;
            float b0v = bias[col], b1v = bias[col + 1];
            float2 lo = make_float2(acc[mi][ni][0] + b0v, acc[mi][ni][1] + b1v);
            float2 hi = make_float2(acc[mi][ni][2] + b0v, acc[mi][ni][3] + b1v);
            *(float2*)&C[(size_t)r0 * N + col]       = lo;
            *(float2*)&C[(size_t)(r0 + 8) * N + col] = hi;
        }
    }
}

// ================= tensor-core causal flash attention v3 ===================
// CTA: 128 queries x one (b,h); 8 warps; key tiles of 64; 256 threads.
// K/V already split+laid-out globally: cp.async lands bf16 planes directly
// in mma-ready padded layouts (K rows 144 B, V^T rows 176 B, conflict-free).
// No in-kernel conversion. 2 stages x 40 KB -> 2 CTAs/SM.
#define ATM 128
#define ATN 64
#define SKHI  0
#define SKLO  9216
#define SVHI  18432
#define SVLO  29696
#define SSTG  40960
#define ASMEM (2 * SSTG)   // 81920

__device__ __forceinline__ void mma_bf16(float* c, const uint32_t* a,
                                         uint32_t b0, uint32_t b1) {
    asm volatile(
        "mma.sync.aligned.m16n8k16.row.col.f32.bf16.bf16.f32 "
        "{%0,%1,%2,%3}, {%4,%5,%6,%7}, {%8,%9}, {%0,%1,%2,%3};"
        : "+f"(c[0]), "+f"(c[1]), "+f"(c[2]), "+f"(c[3])
        : "r"(a[0]), "r"(a[1]), "r"(a[2]), "r"(a[3]), "r"(b0), "r"(b1));
}

__global__ __launch_bounds__(256) void attn_tc_kernel(
    const float* __restrict__ qg,
    const __nv_bfloat16* __restrict__ khi, const __nv_bfloat16* __restrict__ klo,
    const __nv_bfloat16* __restrict__ vthi, const __nv_bfloat16* __restrict__ vtlo,
    float* __restrict__ og)
{
    extern __shared__ __align__(16) char asmem[];
    const uint32_t sb = smem_u32(asmem);
    const int tid  = threadIdx.x;
    const int wm   = tid >> 5;
    const int lane = tid & 31;
    const int g    = lane >> 2;
    const int tg   = lane & 3;
    const int q0   = blockIdx.x * ATM;
    const int bh   = blockIdx.y;
    const int b    = bh >> 4;
    const int h    = bh & 15;

    const size_t bt = (size_t)b * SEQ;
    const int hc = h * HEAD_DIM;
    const size_t vtb = (size_t)bh * HEAD_DIM * SEQ;   // V^T base for this head

    // --- Q fragments (pre-scaled), bf16 hi/lo split, in regs ---
    uint32_t qhi[4][4], qlo[4][4];
    {
        const float* qr0 = qg + (bt + q0 + wm * 16 + g) * N_EMBD + hc;
        const float* qr1 = qr0 + 8 * N_EMBD;
        #pragma unroll
        for (int kk = 0; kk < 4; kk++) {
            float2 e[4];
            e[0] = *(const float2*)(qr0 + kk * 16 + 2 * tg);
            e[1] = *(const float2*)(qr1 + kk * 16 + 2 * tg);
            e[2] = *(const float2*)(qr0 + kk * 16 + 2 * tg + 8);
            e[3] = *(const float2*)(qr1 + kk * 16 + 2 * tg + 8);
            #pragma unroll
            for (int i = 0; i < 4; i++)
                split_pack(e[i].x * 0.125f, e[i].y * 0.125f, qhi[kk][i], qlo[kk][i]);
        }
    }

    float o_[8][4];
    #pragma unroll
    for (int ni = 0; ni < 8; ni++)
        #pragma unroll
        for (int r = 0; r < 4; r++) o_[ni][r] = 0.f;
    float m0 = -1e30f, m1 = -1e30f, l0 = 0.f, l1 = 0.f;

    const int nt = (q0 + ATM) / ATN;

    // stage loader: 2048 cp16 / 256 threads = 8 each
    auto stage_kv = [&](int j0, uint32_t dst) {
        // K planes: 64 rows x 8 chunks, 2 planes -> 1024 chunks (threads 0..: 4 each)
        #pragma unroll
        for (int i = 0; i < 2; i++) {
            int idx = tid + 256 * i;        // 0..511
            int r   = idx >> 3;             // 0..63
            int seg = idx & 7;
            const __nv_bfloat16* gk = khi + (bt + j0 + r) * N_EMBD + hc + seg * 8;
            const __nv_bfloat16* gl = klo + (bt + j0 + r) * N_EMBD + hc + seg * 8;
            cp16(dst + SKHI + r * 144 + seg * 16, gk);
            cp16(dst + SKLO + r * 144 + seg * 16, gl);
        }
        // V^T planes: 64 dim-rows x 8 chunks, 2 planes
        #pragma unroll
        for (int i = 0; i < 2; i++) {
            int idx = tid + 256 * i;
            int d   = idx >> 3;
            int seg = idx & 7;
            const __nv_bfloat16* gh = vthi + vtb + (size_t)d * SEQ + j0 + seg * 8;
            const __nv_bfloat16* gl = vtlo + vtb + (size_t)d * SEQ + j0 + seg * 8;
            cp16(dst + SVHI + d * 176 + seg * 16, gh);
            cp16(dst + SVLO + d * 176 + seg * 16, gl);
        }
        cp_commit();
    };

    stage_kv(0, sb);

    const int row0 = q0 + wm * 16 + g;
    const int rmax = q0 + wm * 16 + 15;

    for (int t = 0; t < nt; t++) {
        const int s = t & 1;
        const int j0 = t * ATN;
        if (t + 1 < nt) {
            stage_kv(j0 + ATN, sb + (s ^ 1) * SSTG);
            asm volatile("cp.async.wait_group 1;" ::: "memory");
        } else {
            asm volatile("cp.async.wait_group 0;" ::: "memory");
        }
        __syncthreads();

        const char* stg = asmem + s * SSTG;

        if (j0 <= rmax) {
            // --- scores: S = Qhi*Khi + Qlo*Khi + Qhi*Klo ---
            float sc[8][4];
            #pragma unroll
            for (int ni = 0; ni < 8; ni++)
                #pragma unroll
                for (int r = 0; r < 4; r++) sc[ni][r] = 0.f;

            #pragma unroll
            for (int kk = 0; kk < 4; kk++) {
                #pragma unroll
                for (int ni = 0; ni < 8; ni++) {
                    uint32_t off = (uint32_t)((ni * 8 + g) * 144 + kk * 32 + tg * 4);
                    uint32_t h0 = *(const uint32_t*)(stg + SKHI + off);
                    uint32_t h1 = *(const uint32_t*)(stg + SKHI + off + 16);
                    uint32_t l0r = *(const uint32_t*)(stg + SKLO + off);
                    uint32_t l1r = *(const uint32_t*)(stg + SKLO + off + 16);
                    mma_bf16(sc[ni], qhi[kk], h0, h1);
                    mma_bf16(sc[ni], qlo[kk], h0, h1);
                    mma_bf16(sc[ni], qhi[kk], l0r, l1r);
                }
            }

            // causal mask (warp-local diagonal tiles only)
            if (j0 + 63 > row0) {
                #pragma unroll
                for (int ni = 0; ni < 8; ni++) {
                    #pragma unroll
                    for (int e = 0; e < 2; e++) {
                        int col = j0 + ni * 8 + 2 * tg + e;
                        if (col > row0)     sc[ni][e]     = -1e30f;
                        if (col > row0 + 8) sc[ni][2 + e] = -1e30f;
                    }
                }
            }

            // --- online softmax update ---
            float mt0 = -1e30f, mt1 = -1e30f;
            #pragma unroll
            for (int ni = 0; ni < 8; ni++) {
                mt0 = fmaxf(mt0, fmaxf(sc[ni][0], sc[ni][1]));
                mt1 = fmaxf(mt1, fmaxf(sc[ni][2], sc[ni][3]));
            }
            mt0 = fmaxf(mt0, __shfl_xor_sync(0xffffffffu, mt0, 1));
            mt0 = fmaxf(mt0, __shfl_xor_sync(0xffffffffu, mt0, 2));
            mt1 = fmaxf(mt1, __shfl_xor_sync(0xffffffffu, mt1, 1));
            mt1 = fmaxf(mt1, __shfl_xor_sync(0xffffffffu, mt1, 2));
            const float mn0 = fmaxf(m0, mt0), mn1 = fmaxf(m1, mt1);
            const float r0f = __expf(m0 - mn0), r1f = __expf(m1 - mn1);

            float s0 = 0.f, s1 = 0.f;
            #pragma unroll
            for (int ni = 0; ni < 8; ni++) {
                sc[ni][0] = __expf(sc[ni][0] - mn0); s0 += sc[ni][0];
                sc[ni][1] = __expf(sc[ni][1] - mn0); s0 += sc[ni][1];
                sc[ni][2] = __expf(sc[ni][2] - mn1); s1 += sc[ni][2];
                sc[ni][3] = __expf(sc[ni][3] - mn1); s1 += sc[ni][3];
            }
            s0 += __shfl_xor_sync(0xffffffffu, s0, 1);
            s0 += __shfl_xor_sync(0xffffffffu, s0, 2);
            s1 += __shfl_xor_sync(0xffffffffu, s1, 1);
            s1 += __shfl_xor_sync(0xffffffffu, s1, 2);
            l0 = l0 * r0f + s0;
            l1 = l1 * r1f + s1;
            m0 = mn0; m1 = mn1;

            #pragma unroll
            for (int ni = 0; ni < 8; ni++) {
                o_[ni][0] *= r0f; o_[ni][1] *= r0f;
                o_[ni][2] *= r1f; o_[ni][3] *= r1f;
            }

            // --- P -> A-operand, bf16 hi/lo split, in registers ---
            uint32_t phi[4][4], plo[4][4];
            #pragma unroll
            for (int kk = 0; kk < 4; kk++) {
                split_pack(sc[2 * kk][0],     sc[2 * kk][1],     phi[kk][0], plo[kk][0]);
                split_pack(sc[2 * kk][2],     sc[2 * kk][3],     phi[kk][1], plo[kk][1]);
                split_pack(sc[2 * kk + 1][0], sc[2 * kk + 1][1], phi[kk][2], plo[kk][2]);
                split_pack(sc[2 * kk + 1][2], sc[2 * kk + 1][3], phi[kk][3], plo[kk][3]);
            }

            // --- O += Phi*Vhi + Plo*Vhi + Phi*Vlo ---
            #pragma unroll
            for (int kk = 0; kk < 4; kk++) {
                #pragma unroll
                for (int ni = 0; ni < 8; ni++) {
                    uint32_t off = (uint32_t)((ni * 8 + g) * 176 + kk * 32 + tg * 4);
                    uint32_t vh0 = *(const uint32_t*)(stg + SVHI + off);
                    uint32_t vh1 = *(const uint32_t*)(stg + SVHI + off + 16);
                    uint32_t vl0 = *(const uint32_t*)(stg + SVLO + off);
                    uint32_t vl1 = *(const uint32_t*)(stg + SVLO + off + 16);
                    mma_bf16(o_[ni], phi[kk], vh0, vh1);
                    mma_bf16(o_[ni], plo[kk], vh0, vh1);
                    mma_bf16(o_[ni], phi[kk], vl0, vl1);
                }
            }
        }
        __syncthreads();
    }

    // --- epilogue ---
    const float i0 = 1.f / l0, i1 = 1.f / l1;
    float* op0 = og + (bt + q0 + wm * 16 + g) * N_EMBD + hc;
    float* op1 = op0 + 8 * N_EMBD;
    #pragma unroll
    for (int ni = 0; ni < 8; ni++) {
        *(float2*)(op0 + ni * 8 + 2 * tg) = make_float2(o_[ni][0] * i0, o_[ni][1] * i0);
        *(float2*)(op1 + ni * 8 + 2 * tg) = make_float2(o_[ni][2] * i1, o_[ni][3] * i1);
    }
}

// ---------------- launch ----------------
extern "C" void kernel_launch(void* const* d_in, const int* in_sizes, int n_in,
                              void* d_out, int out_size)
{
    const float* x  = (const float*)d_in[0];
    const float* Wq = (const float*)d_in[1];
    const float* bq = (const float*)d_in[2];
    const float* Wk = (const float*)d_in[3];
    const float* bk = (const float*)d_in[4];
    const float* Wv = (const float*)d_in[5];
    const float* bv = (const float*)d_in[6];
    const float* Wo = (const float*)d_in[7];
    const float* bo = (const float*)d_in[8];
    float* out = (float*)d_out;

    float *qp, *kp, *vp, *ap;
    uint32_t *xt, *wt;
    __nv_bfloat16 *khi, *klo, *vthi, *vtlo;
    cudaGetSymbolAddress((void**)&qp, g_q);
    cudaGetSymbolAddress((void**)&kp, g_k);
    cudaGetSymbolAddress((void**)&vp, g_v);
    cudaGetSymbolAddress((void**)&ap, g_att);
    cudaGetSymbolAddress((void**)&xt, g_xt);
    cudaGetSymbolAddress((void**)&wt, g_wt);
    cudaGetSymbolAddress((void**)&khi, g_khi);
    cudaGetSymbolAddress((void**)&klo, g_klo);
    cudaGetSymbolAddress((void**)&vthi, g_vthi);
    cudaGetSymbolAddress((void**)&vtlo, g_vtlo);

    cudaFuncSetAttribute(gemm_tc_kernel, cudaFuncAttributeMaxDynamicSharedMemorySize, GSMEM);
    cudaFuncSetAttribute(attn_tc_kernel, cudaFuncAttributeMaxDynamicSharedMemorySize, ASMEM);

    const int nx4 = M_TOT * N_EMBD / 4;
    const int nw4 = N_EMBD * N_EMBD / 4;

    dim3 ggrid(N_EMBD / CTN, M_TOT / CTM);   // (8, 32)

    tf32_cvt_kernel<<<nx4 / 256, 256>>>(x, xt, nx4);

    tf32_cvt_kernel<<<nw4 / 256, 256>>>(Wq, wt, nw4);
    gemm_tc_kernel<<<ggrid, 256, GSMEM>>>(xt, wt, bq, qp, M_TOT, N_EMBD);

    tf32_cvt_kernel<<<nw4 / 256, 256>>>(Wk, wt, nw4);
    gemm_tc_kernel<<<ggrid, 256, GSMEM>>>(xt, wt, bk, kp, M_TOT, N_EMBD);

    tf32_cvt_kernel<<<nw4 / 256, 256>>>(Wv, wt, nw4);
    gemm_tc_kernel<<<ggrid, 256, GSMEM>>>(xt, wt, bv, vp, M_TOT, N_EMBD);

    // K split + V transpose/split (bf16 planes for attention)
    ksplit_kernel<<<nx4 / 256, 256>>>(kp, khi, klo, nx4);
    dim3 vtgrid(SEQ / 64, BATCH * N_HEAD);   // (32, 32)
    vtsplit_kernel<<<vtgrid, 256>>>(vp, vthi, vtlo);

    dim3 agrid(SEQ / ATM, BATCH * N_HEAD);   // (16, 32)
    attn_tc_kernel<<<agrid, 256, ASMEM>>>(qp, khi, klo, vthi, vtlo, ap);

    tf32_cvt_kernel<<<nx4 / 256, 256>>>(ap, xt, nx4);
    tf32_cvt_kernel<<<nw4 / 256, 256>>>(Wo, wt, nw4);
    gemm_tc_kernel<<<ggrid, 256, GSMEM>>>(xt, wt, bo, out, M_TOT, N_EMBD);
}

// round 13
// speedup vs baseline: 5.7033x; 1.0114x over previous
#include <cuda_runtime.h>
#include <cuda_bf16.h>
#include <math.h>
#include <stdint.h>

#define N_EMBD   1024
#define N_HEAD   16
#define HEAD_DIM 64
#define BATCH    2
#define SEQ      2048
#define M_TOT    (BATCH * SEQ)

typedef unsigned long long u64;

// ---------------- cp.async helpers ----------------
__device__ __forceinline__ uint32_t smem_u32(const void* p) {
    uint32_t a;
    asm("{ .reg .u64 t; cvta.to.shared.u64 t, %1; cvt.u32.u64 %0, t; }" : "=r"(a) : "l"(p));
    return a;
}
__device__ __forceinline__ void cp16(uint32_t s, const void* g) {
    asm volatile("cp.async.cg.shared.global [%0], [%1], 16;" :: "r"(s), "l"(g));
}
__device__ __forceinline__ void cp_commit() {
    asm volatile("cp.async.commit_group;" ::: "memory");
}

// ---------------- bf16 split/pack ----------------
__device__ __forceinline__ void split_pack(float x0, float x1, uint32_t& hi, uint32_t& lo) {
    __nv_bfloat16 h0 = __float2bfloat16_rn(x0), h1 = __float2bfloat16_rn(x1);
    __nv_bfloat16 l0 = __float2bfloat16_rn(x0 - __bfloat162float(h0));
    __nv_bfloat16 l1 = __float2bfloat16_rn(x1 - __bfloat162float(h1));
    hi = (uint32_t)__bfloat16_as_ushort(h0) | ((uint32_t)__bfloat16_as_ushort(h1) << 16);
    lo = (uint32_t)__bfloat16_as_ushort(l0) | ((uint32_t)__bfloat16_as_ushort(l1) << 16);
}

// ---------------- scratch (device globals: allocation-free) ----------------
__device__ float g_q[(size_t)M_TOT * N_EMBD];
__device__ float g_v[(size_t)M_TOT * N_EMBD];
__device__ uint32_t g_xt[(size_t)M_TOT * N_EMBD];        // tf32 activations
__device__ uint32_t g_wt[(size_t)N_EMBD * N_EMBD];       // tf32 weights
__device__ __nv_bfloat16 g_khi[(size_t)M_TOT * N_EMBD];  // K hi (layout of k)
__device__ __nv_bfloat16 g_klo[(size_t)M_TOT * N_EMBD];  // K lo
__device__ __nv_bfloat16 g_vthi[(size_t)M_TOT * N_EMBD]; // V^T hi [bh][dim][SEQ]
__device__ __nv_bfloat16 g_vtlo[(size_t)M_TOT * N_EMBD]; // V^T lo

// ---------------- fp32 -> tf32 (rna) pre-pass ----------------
__global__ __launch_bounds__(256) void tf32_cvt_kernel(
    const float* __restrict__ src, uint32_t* __restrict__ dst, int n4)
{
    int i = blockIdx.x * blockDim.x + threadIdx.x;
    if (i >= n4) return;
    float4 v = ((const float4*)src)[i];
    uint4 o;
    asm("cvt.rna.tf32.f32 %0, %1;" : "=r"(o.x) : "f"(v.x));
    asm("cvt.rna.tf32.f32 %0, %1;" : "=r"(o.y) : "f"(v.y));
    asm("cvt.rna.tf32.f32 %0, %1;" : "=r"(o.z) : "f"(v.z));
    asm("cvt.rna.tf32.f32 %0, %1;" : "=r"(o.w) : "f"(v.w));
    ((uint4*)dst)[i] = o;
}

// ---------------- V transpose + split: v[b,key,h*64+d] -> vt[bh][d][SEQ] ----
__global__ __launch_bounds__(256) void vtsplit_kernel(
    const float* __restrict__ v, __nv_bfloat16* __restrict__ vthi,
    __nv_bfloat16* __restrict__ vtlo)
{
    __shared__ __align__(16) float tile[64][68];
    const int tid = threadIdx.x;
    const int j0  = blockIdx.x * 64;
    const int bh  = blockIdx.y;
    const int b   = bh >> 4;
    const int h   = bh & 15;

    #pragma unroll
    for (int i = 0; i < 4; i++) {
        int idx = tid + 256 * i;
        int r  = idx >> 4;
        int c4 = idx & 15;
        float4 t = *(const float4*)&v[((size_t)b * SEQ + j0 + r) * N_EMBD + h * HEAD_DIM + c4 * 4];
        *(float4*)&tile[r][c4 * 4] = t;
    }
    __syncthreads();

    const int d = tid >> 2;
    const int q = tid & 3;
    uint4 oh[2], ol[2];
    #pragma unroll
    for (int half = 0; half < 2; half++) {
        uint32_t hw[4], lw[4];
        #pragma unroll
        for (int p = 0; p < 4; p++) {
            int key = q * 16 + half * 8 + p * 2;
            split_pack(tile[key][d], tile[key + 1][d], hw[p], lw[p]);
        }
        oh[half] = make_uint4(hw[0], hw[1], hw[2], hw[3]);
        ol[half] = make_uint4(lw[0], lw[1], lw[2], lw[3]);
    }
    size_t base = ((size_t)bh * HEAD_DIM + d) * SEQ + j0 + q * 16;
    *(uint4*)&vthi[base]     = oh[0];
    *(uint4*)&vthi[base + 8] = oh[1];
    *(uint4*)&vtlo[base]     = ol[0];
    *(uint4*)&vtlo[base + 8] = ol[1];
}

// ================= tf32 mma.sync GEMM ======================================
// Epilogue modes: Chi==null -> f32 C;  Chi!=null -> bf16 hi/lo split planes.
#define CTM 128
#define CTN 128
#define CBK 32
#define NCH (N_EMBD / CBK)
#define STW 4096
#define GSMEM (4 * STW * 4)

__device__ __forceinline__ void mma_tf32(float* c, const uint32_t* a,
                                         uint32_t b0, uint32_t b1) {
    asm volatile(
        "mma.sync.aligned.m16n8k8.row.col.f32.tf32.tf32.f32 "
        "{%0,%1,%2,%3}, {%4,%5,%6,%7}, {%8,%9}, {%0,%1,%2,%3};"
        : "+f"(c[0]), "+f"(c[1]), "+f"(c[2]), "+f"(c[3])
        : "r"(a[0]), "r"(a[1]), "r"(a[2]), "r"(a[3]), "r"(b0), "r"(b1));
}

__device__ __forceinline__ void load_op(const uint32_t* __restrict__ g,
                                        int rowbase, int kc,
                                        uint32_t sm_t, int tid)
{
    #pragma unroll
    for (int j = 0; j < 4; j++) {
        int idx = tid + 256 * j;
        int row = idx >> 3;
        int k4  = idx & 7;
        const void* gp = g + (size_t)(rowbase + row) * N_EMBD + kc * CBK + k4 * 4;
        uint32_t w = row * 32 + ((k4 * 4) ^ ((row & 7) * 4));
        cp16(sm_t + w * 4, gp);
    }
}

__global__ __launch_bounds__(256) void gemm_tc_kernel(
    const uint32_t* __restrict__ A, const uint32_t* __restrict__ B,
    const float* __restrict__ bias, float* __restrict__ C,
    __nv_bfloat16* __restrict__ Chi, __nv_bfloat16* __restrict__ Clo,
    int M, int N)
{
    extern __shared__ __align__(16) uint32_t gsm[];
    const uint32_t sb = smem_u32(gsm);
    const int tid  = threadIdx.x;
    const int wid  = tid >> 5;
    const int lane = tid & 31;
    const int g  = lane >> 2;
    const int tg = lane & 3;
    const int wm = wid >> 1;
    const int wn = wid & 1;
    const int m0 = blockIdx.y * CTM;
    const int n0 = blockIdx.x * CTN;
    const int xr = 4 * g;

    uint32_t sA[2] = {sb, sb + STW * 4};
    uint32_t sB[2] = {sb + 2 * STW * 4, sb + 3 * STW * 4};

    #pragma unroll
    for (int c = 0; c < 2; c++) {
        load_op(A, m0, c, sA[c], tid);
        load_op(B, n0, c, sB[c], tid);
        cp_commit();
    }

    float acc[2][8][4];
    #pragma unroll
    for (int mi = 0; mi < 2; mi++)
        #pragma unroll
        for (int ni = 0; ni < 8; ni++)
            #pragma unroll
            for (int r = 0; r < 4; r++) acc[mi][ni][r] = 0.f;

    for (int c = 0; c < NCH; c++) {
        const int s = c & 1;
        if (c == NCH - 1) asm volatile("cp.async.wait_group 0;" ::: "memory");
        else              asm volatile("cp.async.wait_group 1;" ::: "memory");
        __syncthreads();

        const uint32_t* As = gsm + (sA[s] - sb) / 4;
        const uint32_t* Bs = gsm + (sB[s] - sb) / 4;

        #pragma unroll
        for (int kk = 0; kk < 4; kk++) {
            const int k = kk * 8;
            const int x0 = (k + tg) ^ xr;
            const int x1 = (k + tg + 4) ^ xr;

            uint32_t a[2][4];
            #pragma unroll
            for (int mi = 0; mi < 2; mi++) {
                const uint32_t* base = As + (wm * 32 + mi * 16 + g) * 32;
                a[mi][0] = base[x0];
                a[mi][1] = base[256 + x0];
                a[mi][2] = base[x1];
                a[mi][3] = base[256 + x1];
            }
            #pragma unroll
            for (int ni = 0; ni < 8; ni++) {
                const uint32_t* bb = Bs + (wn * 64 + ni * 8 + g) * 32;
                uint32_t b0 = bb[x0];
                uint32_t b1 = bb[x1];
                mma_tf32(acc[0][ni], a[0], b0, b1);
                mma_tf32(acc[1][ni], a[1], b0, b1);
            }
        }
        __syncthreads();

        if (c + 2 < NCH) {
            load_op(A, m0, c + 2, sA[s], tid);
            load_op(B, n0, c + 2, sB[s], tid);
            cp_commit();
        }
    }

    #pragma unroll
    for (int mi = 0; mi < 2; mi++) {
        const int r0 = m0 + wm * 32 + mi * 16 + g;
        #pragma unroll
        for (int ni = 0; ni < 8; ni++) {
            const int col = n0 + wn * 64 + ni * 8 + 2 * tg;
            float b0v = bias[col], b1v = bias[col + 1];
            float c0 = acc[mi][ni][0] + b0v, c1 = acc[mi][ni][1] + b1v;
            float c2 = acc[mi][ni][2] + b0v, c3 = acc[mi][ni][3] + b1v;
            if (Chi) {
                uint32_t h, l;
                split_pack(c0, c1, h, l);
                *(uint32_t*)&Chi[(size_t)r0 * N + col] = h;
                *(uint32_t*)&Clo[(size_t)r0 * N + col] = l;
                split_pack(c2, c3, h, l);
                *(uint32_t*)&Chi[(size_t)(r0 + 8) * N + col] = h;
                *(uint32_t*)&Clo[(size_t)(r0 + 8) * N + col] = l;
            } else {
                *(float2*)&C[(size_t)r0 * N + col]       = make_float2(c0, c1);
                *(float2*)&C[(size_t)(r0 + 8) * N + col] = make_float2(c2, c3);
            }
        }
    }
}

// ================= tensor-core causal flash attention v4 ===================
// As round-11 v3, plus: reversed CTA order (heavy diagonal CTAs first),
// base-2 softmax (log2e folded into Q scale), epilogue writes tf32 directly.
#define ATM 128
#define ATN 64
#define SKHI  0
#define SKLO  9216
#define SVHI  18432
#define SVLO  29696
#define SSTG  40960
#define ASMEM (2 * SSTG)   // 81920

__device__ __forceinline__ void mma_bf16(float* c, const uint32_t* a,
                                         uint32_t b0, uint32_t b1) {
    asm volatile(
        "mma.sync.aligned.m16n8k16.row.col.f32.bf16.bf16.f32 "
        "{%0,%1,%2,%3}, {%4,%5,%6,%7}, {%8,%9}, {%0,%1,%2,%3};"
        : "+f"(c[0]), "+f"(c[1]), "+f"(c[2]), "+f"(c[3])
        : "r"(a[0]), "r"(a[1]), "r"(a[2]), "r"(a[3]), "r"(b0), "r"(b1));
}

__global__ __launch_bounds__(256) void attn_tc_kernel(
    const float* __restrict__ qg,
    const __nv_bfloat16* __restrict__ khi, const __nv_bfloat16* __restrict__ klo,
    const __nv_bfloat16* __restrict__ vthi, const __nv_bfloat16* __restrict__ vtlo,
    uint32_t* __restrict__ ot)
{
    extern __shared__ __align__(16) char asmem[];
    const uint32_t sb = smem_u32(asmem);
    const int tid  = threadIdx.x;
    const int wm   = tid >> 5;
    const int lane = tid & 31;
    const int g    = lane >> 2;
    const int tg   = lane & 3;
    const int q0   = (gridDim.x - 1 - blockIdx.x) * ATM;   // heavy CTAs first
    const int bh   = blockIdx.y;
    const int b    = bh >> 4;
    const int h    = bh & 15;

    const size_t bt = (size_t)b * SEQ;
    const int hc = h * HEAD_DIM;
    const size_t vtb = (size_t)bh * HEAD_DIM * SEQ;

    // --- Q fragments, scale = log2e/8 (base-2 softmax), bf16 split ---
    const float qsc = 0.125f * 1.4426950408889634f;
    uint32_t qhi[4][4], qlo[4][4];
    {
        const float* qr0 = qg + (bt + q0 + wm * 16 + g) * N_EMBD + hc;
        const float* qr1 = qr0 + 8 * N_EMBD;
        #pragma unroll
        for (int kk = 0; kk < 4; kk++) {
            float2 e[4];
            e[0] = *(const float2*)(qr0 + kk * 16 + 2 * tg);
            e[1] = *(const float2*)(qr1 + kk * 16 + 2 * tg);
            e[2] = *(const float2*)(qr0 + kk * 16 + 2 * tg + 8);
            e[3] = *(const float2*)(qr1 + kk * 16 + 2 * tg + 8);
            #pragma unroll
            for (int i = 0; i < 4; i++)
                split_pack(e[i].x * qsc, e[i].y * qsc, qhi[kk][i], qlo[kk][i]);
        }
    }

    float o_[8][4];
    #pragma unroll
    for (int ni = 0; ni < 8; ni++)
        #pragma unroll
        for (int r = 0; r < 4; r++) o_[ni][r] = 0.f;
    float m0 = -1e30f, m1 = -1e30f, l0 = 0.f, l1 = 0.f;

    const int nt = (q0 + ATM) / ATN;

    auto stage_kv = [&](int j0, uint32_t dst) {
        #pragma unroll
        for (int i = 0; i < 2; i++) {
            int idx = tid + 256 * i;
            int r   = idx >> 3;
            int seg = idx & 7;
            const __nv_bfloat16* gk = khi + (bt + j0 + r) * N_EMBD + hc + seg * 8;
            const __nv_bfloat16* gl = klo + (bt + j0 + r) * N_EMBD + hc + seg * 8;
            cp16(dst + SKHI + r * 144 + seg * 16, gk);
            cp16(dst + SKLO + r * 144 + seg * 16, gl);
        }
        #pragma unroll
        for (int i = 0; i < 2; i++) {
            int idx = tid + 256 * i;
            int d   = idx >> 3;
            int seg = idx & 7;
            const __nv_bfloat16* gh = vthi + vtb + (size_t)d * SEQ + j0 + seg * 8;
            const __nv_bfloat16* gl = vtlo + vtb + (size_t)d * SEQ + j0 + seg * 8;
            cp16(dst + SVHI + d * 176 + seg * 16, gh);
            cp16(dst + SVLO + d * 176 + seg * 16, gl);
        }
        cp_commit();
    };

    stage_kv(0, sb);

    const int row0 = q0 + wm * 16 + g;
    const int rmax = q0 + wm * 16 + 15;

    for (int t = 0; t < nt; t++) {
        const int s = t & 1;
        const int j0 = t * ATN;
        if (t + 1 < nt) {
            stage_kv(j0 + ATN, sb + (s ^ 1) * SSTG);
            asm volatile("cp.async.wait_group 1;" ::: "memory");
        } else {
            asm volatile("cp.async.wait_group 0;" ::: "memory");
        }
        __syncthreads();

        const char* stg = asmem + s * SSTG;

        if (j0 <= rmax) {
            float sc[8][4];
            #pragma unroll
            for (int ni = 0; ni < 8; ni++)
                #pragma unroll
                for (int r = 0; r < 4; r++) sc[ni][r] = 0.f;

            #pragma unroll
            for (int kk = 0; kk < 4; kk++) {
                #pragma unroll
                for (int ni = 0; ni < 8; ni++) {
                    uint32_t off = (uint32_t)((ni * 8 + g) * 144 + kk * 32 + tg * 4);
                    uint32_t h0 = *(const uint32_t*)(stg + SKHI + off);
                    uint32_t h1 = *(const uint32_t*)(stg + SKHI + off + 16);
                    uint32_t l0r = *(const uint32_t*)(stg + SKLO + off);
                    uint32_t l1r = *(const uint32_t*)(stg + SKLO + off + 16);
                    mma_bf16(sc[ni], qhi[kk], h0, h1);
                    mma_bf16(sc[ni], qlo[kk], h0, h1);
                    mma_bf16(sc[ni], qhi[kk], l0r, l1r);
                }
            }

            if (j0 + 63 > row0) {
                #pragma unroll
                for (int ni = 0; ni < 8; ni++) {
                    #pragma unroll
                    for (int e = 0; e < 2; e++) {
                        int col = j0 + ni * 8 + 2 * tg + e;
                        if (col > row0)     sc[ni][e]     = -1e30f;
                        if (col > row0 + 8) sc[ni][2 + e] = -1e30f;
                    }
                }
            }

            float mt0 = -1e30f, mt1 = -1e30f;
            #pragma unroll
            for (int ni = 0; ni < 8; ni++) {
                mt0 = fmaxf(mt0, fmaxf(sc[ni][0], sc[ni][1]));
                mt1 = fmaxf(mt1, fmaxf(sc[ni][2], sc[ni][3]));
            }
            mt0 = fmaxf(mt0, __shfl_xor_sync(0xffffffffu, mt0, 1));
            mt0 = fmaxf(mt0, __shfl_xor_sync(0xffffffffu, mt0, 2));
            mt1 = fmaxf(mt1, __shfl_xor_sync(0xffffffffu, mt1, 1));
            mt1 = fmaxf(mt1, __shfl_xor_sync(0xffffffffu, mt1, 2));
            const float mn0 = fmaxf(m0, mt0), mn1 = fmaxf(m1, mt1);
            const float r0f = exp2f(m0 - mn0), r1f = exp2f(m1 - mn1);

            float s0 = 0.f, s1 = 0.f;
            #pragma unroll
            for (int ni = 0; ni < 8; ni++) {
                sc[ni][0] = exp2f(sc[ni][0] - mn0); s0 += sc[ni][0];
                sc[ni][1] = exp2f(sc[ni][1] - mn0); s0 += sc[ni][1];
                sc[ni][2] = exp2f(sc[ni][2] - mn1); s1 += sc[ni][2];
                sc[ni][3] = exp2f(sc[ni][3] - mn1); s1 += sc[ni][3];
            }
            s0 += __shfl_xor_sync(0xffffffffu, s0, 1);
            s0 += __shfl_xor_sync(0xffffffffu, s0, 2);
            s1 += __shfl_xor_sync(0xffffffffu, s1, 1);
            s1 += __shfl_xor_sync(0xffffffffu, s1, 2);
            l0 = l0 * r0f + s0;
            l1 = l1 * r1f + s1;
            m0 = mn0; m1 = mn1;

            #pragma unroll
            for (int ni = 0; ni < 8; ni++) {
                o_[ni][0] *= r0f; o_[ni][1] *= r0f;
                o_[ni][2] *= r1f; o_[ni][3] *= r1f;
            }

            uint32_t phi[4][4], plo[4][4];
            #pragma unroll
            for (int kk = 0; kk < 4; kk++) {
                split_pack(sc[2 * kk][0],     sc[2 * kk][1],     phi[kk][0], plo[kk][0]);
                split_pack(sc[2 * kk][2],     sc[2 * kk][3],     phi[kk][1], plo[kk][1]);
                split_pack(sc[2 * kk + 1][0], sc[2 * kk + 1][1], phi[kk][2], plo[kk][2]);
                split_pack(sc[2 * kk + 1][2], sc[2 * kk + 1][3], phi[kk][3], plo[kk][3]);
            }

            #pragma unroll
            for (int kk = 0; kk < 4; kk++) {
                #pragma unroll
                for (int ni = 0; ni < 8; ni++) {
                    uint32_t off = (uint32_t)((ni * 8 + g) * 176 + kk * 32 + tg * 4);
                    uint32_t vh0 = *(const uint32_t*)(stg + SVHI + off);
                    uint32_t vh1 = *(const uint32_t*)(stg + SVHI + off + 16);
                    uint32_t vl0 = *(const uint32_t*)(stg + SVLO + off);
                    uint32_t vl1 = *(const uint32_t*)(stg + SVLO + off + 16);
                    mma_bf16(o_[ni], phi[kk], vh0, vh1);
                    mma_bf16(o_[ni], plo[kk], vh0, vh1);
                    mma_bf16(o_[ni], phi[kk], vl0, vl1);
                }
            }
        }
        __syncthreads();
    }

    // --- epilogue: normalize + write tf32 directly ---
    const float i0 = 1.f / l0, i1 = 1.f / l1;
    uint32_t* op0 = ot + (bt + q0 + wm * 16 + g) * N_EMBD + hc;
    uint32_t* op1 = op0 + 8 * N_EMBD;
    #pragma unroll
    for (int ni = 0; ni < 8; ni++) {
        uint2 w0, w1;
        asm("cvt.rna.tf32.f32 %0, %1;" : "=r"(w0.x) : "f"(o_[ni][0] * i0));
        asm("cvt.rna.tf32.f32 %0, %1;" : "=r"(w0.y) : "f"(o_[ni][1] * i0));
        asm("cvt.rna.tf32.f32 %0, %1;" : "=r"(w1.x) : "f"(o_[ni][2] * i1));
        asm("cvt.rna.tf32.f32 %0, %1;" : "=r"(w1.y) : "f"(o_[ni][3] * i1));
        *(uint2*)(op0 + ni * 8 + 2 * tg) = w0;
        *(uint2*)(op1 + ni * 8 + 2 * tg) = w1;
    }
}

// ---------------- launch ----------------
extern "C" void kernel_launch(void* const* d_in, const int* in_sizes, int n_in,
                              void* d_out, int out_size)
{
    const float* x  = (const float*)d_in[0];
    const float* Wq = (const float*)d_in[1];
    const float* bq = (const float*)d_in[2];
    const float* Wk = (const float*)d_in[3];
    const float* bk = (const float*)d_in[4];
    const float* Wv = (const float*)d_in[5];
    const float* bv = (const float*)d_in[6];
    const float* Wo = (const float*)d_in[7];
    const float* bo = (const float*)d_in[8];
    float* out = (float*)d_out;

    float *qp, *vp;
    uint32_t *xt, *wt;
    __nv_bfloat16 *khi, *klo, *vthi, *vtlo;
    cudaGetSymbolAddress((void**)&qp, g_q);
    cudaGetSymbolAddress((void**)&vp, g_v);
    cudaGetSymbolAddress((void**)&xt, g_xt);
    cudaGetSymbolAddress((void**)&wt, g_wt);
    cudaGetSymbolAddress((void**)&khi, g_khi);
    cudaGetSymbolAddress((void**)&klo, g_klo);
    cudaGetSymbolAddress((void**)&vthi, g_vthi);
    cudaGetSymbolAddress((void**)&vtlo, g_vtlo);

    cudaFuncSetAttribute(gemm_tc_kernel, cudaFuncAttributeMaxDynamicSharedMemorySize, GSMEM);
    cudaFuncSetAttribute(attn_tc_kernel, cudaFuncAttributeMaxDynamicSharedMemorySize, ASMEM);

    const int nx4 = M_TOT * N_EMBD / 4;
    const int nw4 = N_EMBD * N_EMBD / 4;

    dim3 ggrid(N_EMBD / CTN, M_TOT / CTM);   // (8, 32)

    tf32_cvt_kernel<<<nx4 / 256, 256>>>(x, xt, nx4);

    tf32_cvt_kernel<<<nw4 / 256, 256>>>(Wq, wt, nw4);
    gemm_tc_kernel<<<ggrid, 256, GSMEM>>>(xt, wt, bq, qp, nullptr, nullptr, M_TOT, N_EMBD);

    tf32_cvt_kernel<<<nw4 / 256, 256>>>(Wk, wt, nw4);
    gemm_tc_kernel<<<ggrid, 256, GSMEM>>>(xt, wt, bk, nullptr, khi, klo, M_TOT, N_EMBD);

    tf32_cvt_kernel<<<nw4 / 256, 256>>>(Wv, wt, nw4);
    gemm_tc_kernel<<<ggrid, 256, GSMEM>>>(xt, wt, bv, vp, nullptr, nullptr, M_TOT, N_EMBD);

    dim3 vtgrid(SEQ / 64, BATCH * N_HEAD);   // (32, 32)
    vtsplit_kernel<<<vtgrid, 256>>>(vp, vthi, vtlo);

    dim3 agrid(SEQ / ATM, BATCH * N_HEAD);   // (16, 32)
    attn_tc_kernel<<<agrid, 256, ASMEM>>>(qp, khi, klo, vthi, vtlo, xt);

    tf32_cvt_kernel<<<nw4 / 256, 256>>>(Wo, wt, nw4);
    gemm_tc_kernel<<<ggrid, 256, GSMEM>>>(xt, wt, bo, out, nullptr, nullptr, M_TOT, N_EMBD);
}

// round 15
// speedup vs baseline: 6.0474x; 1.0603x over previous
#include <cuda_runtime.h>
#include <cuda_bf16.h>
#include <math.h>
#include <stdint.h>

#define N_EMBD   1024
#define N_HEAD   16
#define HEAD_DIM 64
#define BATCH    2
#define SEQ      2048
#define M_TOT    (BATCH * SEQ)
#define WPLANE   (N_EMBD * N_EMBD)   // u32 per weight plane

typedef unsigned long long u64;

// ---------------- cp.async helpers ----------------
__device__ __forceinline__ uint32_t smem_u32(const void* p) {
    uint32_t a;
    asm("{ .reg .u64 t; cvta.to.shared.u64 t, %1; cvt.u32.u64 %0, t; }" : "=r"(a) : "l"(p));
    return a;
}
__device__ __forceinline__ void cp16(uint32_t s, const void* g) {
    asm volatile("cp.async.cg.shared.global [%0], [%1], 16;" :: "r"(s), "l"(g));
}
__device__ __forceinline__ void cp_commit() {
    asm volatile("cp.async.commit_group;" ::: "memory");
}

// ---------------- bf16 split/pack ----------------
__device__ __forceinline__ void split_pack(float x0, float x1, uint32_t& hi, uint32_t& lo) {
    __nv_bfloat16 h0 = __float2bfloat16_rn(x0), h1 = __float2bfloat16_rn(x1);
    __nv_bfloat16 l0 = __float2bfloat16_rn(x0 - __bfloat162float(h0));
    __nv_bfloat16 l1 = __float2bfloat16_rn(x1 - __bfloat162float(h1));
    hi = (uint32_t)__bfloat16_as_ushort(h0) | ((uint32_t)__bfloat16_as_ushort(h1) << 16);
    lo = (uint32_t)__bfloat16_as_ushort(l0) | ((uint32_t)__bfloat16_as_ushort(l1) << 16);
}

// fast truncation split for nonneg P in [0,1]: hi = top16 bits (1 PRMT),
// lo = rn-bf16x2 of exact remainder.
__device__ __forceinline__ void psplit(float x0, float x1, uint32_t& hi, uint32_t& lo) {
    uint32_t u0 = __float_as_uint(x0), u1 = __float_as_uint(x1);
    asm("prmt.b32 %0, %1, %2, 0x7632;" : "=r"(hi) : "r"(u0), "r"(u1));
    float l0 = x0 - __uint_as_float(u0 & 0xFFFF0000u);
    float l1 = x1 - __uint_as_float(u1 & 0xFFFF0000u);
    asm("cvt.rn.bf16x2.f32 %0, %1, %2;" : "=r"(lo) : "f"(l1), "f"(l0));
}

// ---------------- scratch (device globals: allocation-free) ----------------
__device__ float g_q[(size_t)M_TOT * N_EMBD];
__device__ uint32_t g_xt[(size_t)M_TOT * N_EMBD];        // tf32 activations
__device__ uint32_t g_wt[(size_t)4 * WPLANE];            // tf32 weights q,k,v,o
__device__ __nv_bfloat16 g_khi[(size_t)M_TOT * N_EMBD];  // K hi (layout of k)
__device__ __nv_bfloat16 g_klo[(size_t)M_TOT * N_EMBD];  // K lo
__device__ __nv_bfloat16 g_vthi[(size_t)M_TOT * N_EMBD]; // V^T hi [bh][dim][SEQ]
__device__ __nv_bfloat16 g_vtlo[(size_t)M_TOT * N_EMBD]; // V^T lo

// ---------------- fp32 -> tf32 (rna) pre-pass ----------------
__global__ __launch_bounds__(256) void tf32_cvt_kernel(
    const float* __restrict__ src, uint32_t* __restrict__ dst, int n4)
{
    int i = blockIdx.x * blockDim.x + threadIdx.x;
    if (i >= n4) return;
    float4 v = ((const float4*)src)[i];
    uint4 o;
    asm("cvt.rna.tf32.f32 %0, %1;" : "=r"(o.x) : "f"(v.x));
    asm("cvt.rna.tf32.f32 %0, %1;" : "=r"(o.y) : "f"(v.y));
    asm("cvt.rna.tf32.f32 %0, %1;" : "=r"(o.z) : "f"(v.z));
    asm("cvt.rna.tf32.f32 %0, %1;" : "=r"(o.w) : "f"(v.w));
    ((uint4*)dst)[i] = o;
}

// all 4 weights in one pass
__global__ __launch_bounds__(256) void wcvt4_kernel(
    const float* __restrict__ s0, const float* __restrict__ s1,
    const float* __restrict__ s2, const float* __restrict__ s3,
    uint32_t* __restrict__ dst)
{
    int i = blockIdx.x * blockDim.x + threadIdx.x;   // float4 units, 4 planes
    int plane = i >> 18;                              // WPLANE/4 = 262144
    int j = i & 0x3FFFF;
    const float* src = (plane == 0) ? s0 : (plane == 1) ? s1 : (plane == 2) ? s2 : s3;
    float4 v = ((const float4*)src)[j];
    uint4 o;
    asm("cvt.rna.tf32.f32 %0, %1;" : "=r"(o.x) : "f"(v.x));
    asm("cvt.rna.tf32.f32 %0, %1;" : "=r"(o.y) : "f"(v.y));
    asm("cvt.rna.tf32.f32 %0, %1;" : "=r"(o.z) : "f"(v.z));
    asm("cvt.rna.tf32.f32 %0, %1;" : "=r"(o.w) : "f"(v.w));
    ((uint4*)dst)[i] = o;
}

// ================= tf32 mma.sync GEMM machinery ============================
#define CTM 128
#define CTN 128
#define CBK 32
#define NCH (N_EMBD / CBK)
#define STW 4096
#define GSMEM (4 * STW * 4)

__device__ __forceinline__ void mma_tf32(float* c, const uint32_t* a,
                                         uint32_t b0, uint32_t b1) {
    asm volatile(
        "mma.sync.aligned.m16n8k8.row.col.f32.tf32.tf32.f32 "
        "{%0,%1,%2,%3}, {%4,%5,%6,%7}, {%8,%9}, {%0,%1,%2,%3};"
        : "+f"(c[0]), "+f"(c[1]), "+f"(c[2]), "+f"(c[3])
        : "r"(a[0]), "r"(a[1]), "r"(a[2]), "r"(a[3]), "r"(b0), "r"(b1));
}

__device__ __forceinline__ void load_op(const uint32_t* __restrict__ g,
                                        int rowbase, int kc,
                                        uint32_t sm_t, int tid)
{
    #pragma unroll
    for (int j = 0; j < 4; j++) {
        int idx = tid + 256 * j;
        int row = idx >> 3;
        int k4  = idx & 7;
        const void* gp = g + (size_t)(rowbase + row) * N_EMBD + kc * CBK + k4 * 4;
        uint32_t w = row * 32 + ((k4 * 4) ^ ((row & 7) * 4));
        cp16(sm_t + w * 4, gp);
    }
}

// mainloop: fills acc[2][8][4] for warp tile at (wm, wn) of (m0, n0)
__device__ __forceinline__ void gemm_mainloop(
    const uint32_t* __restrict__ A, const uint32_t* __restrict__ B,
    int m0, int n0, uint32_t sb, uint32_t* gsm_base,
    int tid, int wm, int wn, int g, int tg, float acc[2][8][4])
{
    const int xr = 4 * g;
    uint32_t sA[2] = {sb, sb + STW * 4};
    uint32_t sB[2] = {sb + 2 * STW * 4, sb + 3 * STW * 4};

    #pragma unroll
    for (int c = 0; c < 2; c++) {
        load_op(A, m0, c, sA[c], tid);
        load_op(B, n0, c, sB[c], tid);
        cp_commit();
    }

    for (int c = 0; c < NCH; c++) {
        const int s = c & 1;
        if (c == NCH - 1) asm volatile("cp.async.wait_group 0;" ::: "memory");
        else              asm volatile("cp.async.wait_group 1;" ::: "memory");
        __syncthreads();

        const uint32_t* As = gsm_base + (sA[s] - sb) / 4;
        const uint32_t* Bs = gsm_base + (sB[s] - sb) / 4;

        #pragma unroll
        for (int kk = 0; kk < 4; kk++) {
            const int k = kk * 8;
            const int x0 = (k + tg) ^ xr;
            const int x1 = (k + tg + 4) ^ xr;

            uint32_t a[2][4];
            #pragma unroll
            for (int mi = 0; mi < 2; mi++) {
                const uint32_t* base = As + (wm * 32 + mi * 16 + g) * 32;
                a[mi][0] = base[x0];
                a[mi][1] = base[256 + x0];
                a[mi][2] = base[x1];
                a[mi][3] = base[256 + x1];
            }
            #pragma unroll
            for (int ni = 0; ni < 8; ni++) {
                const uint32_t* bb = Bs + (wn * 64 + ni * 8 + g) * 32;
                uint32_t b0 = bb[x0];
                uint32_t b1 = bb[x1];
                mma_tf32(acc[0][ni], a[0], b0, b1);
                mma_tf32(acc[1][ni], a[1], b0, b1);
            }
        }
        __syncthreads();

        if (c + 2 < NCH) {
            load_op(A, m0, c + 2, sA[s], tid);
            load_op(B, n0, c + 2, sB[s], tid);
            cp_commit();
        }
    }
}

// ---- merged QKV GEMM: z=0 -> Q (f32), z=1 -> K (bf16 planes), z=2 -> V^T --
__global__ __launch_bounds__(256) void qkv_gemm_kernel(
    const uint32_t* __restrict__ xt, const uint32_t* __restrict__ wt,
    const float* __restrict__ bq, const float* __restrict__ bk,
    const float* __restrict__ bv,
    float* __restrict__ qp,
    __nv_bfloat16* __restrict__ khi, __nv_bfloat16* __restrict__ klo,
    __nv_bfloat16* __restrict__ vthi, __nv_bfloat16* __restrict__ vtlo)
{
    extern __shared__ __align__(16) uint32_t gsm[];
    const uint32_t sb = smem_u32(gsm);
    const int tid  = threadIdx.x;
    const int wid  = tid >> 5;
    const int lane = tid & 31;
    const int g  = lane >> 2;
    const int tg = lane & 3;
    const int wm = wid >> 1;
    const int wn = wid & 1;
    const int z  = blockIdx.z;

    const uint32_t* A;
    const uint32_t* B;
    int m0, n0;
    if (z == 2) {   // V transposed: A = Wv [1024 x 1024], B = x [4096 x 1024]
        A = wt + 2 * WPLANE; B = xt;
        m0 = blockIdx.x * CTM / (CTM / 128) * 0 + blockIdx.x * 128;  // dims: 8 blocks
        m0 = blockIdx.x * 128;          // but gridDim.x=8 covers only 1024 -> need y
        m0 = blockIdx.x * 128;          // (see launch: grid (8,32,3); for z=2 swap roles)
        n0 = blockIdx.y * 128;
    } else {
        A = xt; B = wt + z * WPLANE;
        m0 = blockIdx.y * CTM;
        n0 = blockIdx.x * CTN;
    }

    float acc[2][8][4];
    #pragma unroll
    for (int mi = 0; mi < 2; mi++)
        #pragma unroll
        for (int ni = 0; ni < 8; ni++)
            #pragma unroll
            for (int r = 0; r < 4; r++) acc[mi][ni][r] = 0.f;

    gemm_mainloop(A, B, m0, n0, sb, gsm, tid, wm, wn, g, tg, acc);

    if (z == 0) {
        #pragma unroll
        for (int mi = 0; mi < 2; mi++) {
            const int r0 = m0 + wm * 32 + mi * 16 + g;
            #pragma unroll
            for (int ni = 0; ni < 8; ni++) {
                const int col = n0 + wn * 64 + ni * 8 + 2 * tg;
                float b0v = bq[col], b1v = bq[col + 1];
                *(float2*)&qp[(size_t)r0 * N_EMBD + col] =
                    make_float2(acc[mi][ni][0] + b0v, acc[mi][ni][1] + b1v);
                *(float2*)&qp[(size_t)(r0 + 8) * N_EMBD + col] =
                    make_float2(acc[mi][ni][2] + b0v, acc[mi][ni][3] + b1v);
            }
        }
    } else if (z == 1) {
        #pragma unroll
        for (int mi = 0; mi < 2; mi++) {
            const int r0 = m0 + wm * 32 + mi * 16 + g;
            #pragma unroll
            for (int ni = 0; ni < 8; ni++) {
                const int col = n0 + wn * 64 + ni * 8 + 2 * tg;
                float b0v = bk[col], b1v = bk[col + 1];
                uint32_t h, l;
                split_pack(acc[mi][ni][0] + b0v, acc[mi][ni][1] + b1v, h, l);
                *(uint32_t*)&khi[(size_t)r0 * N_EMBD + col] = h;
                *(uint32_t*)&klo[(size_t)r0 * N_EMBD + col] = l;
                split_pack(acc[mi][ni][2] + b0v, acc[mi][ni][3] + b1v, h, l);
                *(uint32_t*)&khi[(size_t)(r0 + 8) * N_EMBD + col] = h;
                *(uint32_t*)&klo[(size_t)(r0 + 8) * N_EMBD + col] = l;
            }
        }
    } else {
        // C[d_out, token]; write V^T planes [bh][d][SEQ]
        #pragma unroll
        for (int mi = 0; mi < 2; mi++) {
            const int r0 = m0 + wm * 32 + mi * 16 + g;     // output dim
            const float bv0 = bv[r0], bv1 = bv[r0 + 8];
            const int h = r0 >> 6, d = r0 & 63;
            #pragma unroll
            for (int ni = 0; ni < 8; ni++) {
                const int col = n0 + wn * 64 + ni * 8 + 2 * tg;   // token
                const int b = col >> 11, t = col & 2047;
                size_t base0 = (((size_t)(b * 16 + h)) * 64 + d) * SEQ + t;
                uint32_t hv, lv;
                split_pack(acc[mi][ni][0] + bv0, acc[mi][ni][1] + bv0, hv, lv);
                *(uint32_t*)&vthi[base0] = hv;
                *(uint32_t*)&vtlo[base0] = lv;
                split_pack(acc[mi][ni][2] + bv1, acc[mi][ni][3] + bv1, hv, lv);
                *(uint32_t*)&vthi[base0 + 8 * SEQ] = hv;
                *(uint32_t*)&vtlo[base0 + 8 * SEQ] = lv;
            }
        }
    }
}

// ---- plain f32 GEMM (final O projection) ----
__global__ __launch_bounds__(256) void gemm_tc_kernel(
    const uint32_t* __restrict__ A, const uint32_t* __restrict__ B,
    const float* __restrict__ bias, float* __restrict__ C, int N)
{
    extern __shared__ __align__(16) uint32_t gsm[];
    const uint32_t sb = smem_u32(gsm);
    const int tid  = threadIdx.x;
    const int wid  = tid >> 5;
    const int lane = tid & 31;
    const int g  = lane >> 2;
    const int tg = lane & 3;
    const int wm = wid >> 1;
    const int wn = wid & 1;
    const int m0 = blockIdx.y * CTM;
    const int n0 = blockIdx.x * CTN;

    float acc[2][8][4];
    #pragma unroll
    for (int mi = 0; mi < 2; mi++)
        #pragma unroll
        for (int ni = 0; ni < 8; ni++)
            #pragma unroll
            for (int r = 0; r < 4; r++) acc[mi][ni][r] = 0.f;

    gemm_mainloop(A, B, m0, n0, sb, gsm, tid, wm, wn, g, tg, acc);

    #pragma unroll
    for (int mi = 0; mi < 2; mi++) {
        const int r0 = m0 + wm * 32 + mi * 16 + g;
        #pragma unroll
        for (int ni = 0; ni < 8; ni++) {
            const int col = n0 + wn * 64 + ni * 8 + 2 * tg;
            float b0v = bias[col], b1v = bias[col + 1];
            *(float2*)&C[(size_t)r0 * N + col] =
                make_float2(acc[mi][ni][0] + b0v, acc[mi][ni][1] + b1v);
            *(float2*)&C[(size_t)(r0 + 8) * N + col] =
                make_float2(acc[mi][ni][2] + b0v, acc[mi][ni][3] + b1v);
        }
    }
}

// ================= tensor-core causal flash attention ======================
#define ATM 128
#define ATN 64
#define SKHI  0
#define SKLO  9216
#define SVHI  18432
#define SVLO  29696
#define SSTG  40960
#define ASMEM (2 * SSTG)   // 81920

__device__ __forceinline__ void mma_bf16(float* c, const uint32_t* a,
                                         uint32_t b0, uint32_t b1) {
    asm volatile(
        "mma.sync.aligned.m16n8k16.row.col.f32.bf16.bf16.f32 "
        "{%0,%1,%2,%3}, {%4,%5,%6,%7}, {%8,%9}, {%0,%1,%2,%3};"
        : "+f"(c[0]), "+f"(c[1]), "+f"(c[2]), "+f"(c[3])
        : "r"(a[0]), "r"(a[1]), "r"(a[2]), "r"(a[3]), "r"(b0), "r"(b1));
}

__global__ __launch_bounds__(256) void attn_tc_kernel(
    const float* __restrict__ qg,
    const __nv_bfloat16* __restrict__ khi, const __nv_bfloat16* __restrict__ klo,
    const __nv_bfloat16* __restrict__ vthi, const __nv_bfloat16* __restrict__ vtlo,
    uint32_t* __restrict__ ot)
{
    extern __shared__ __align__(16) char asmem[];
    const uint32_t sb = smem_u32(asmem);
    const int tid  = threadIdx.x;
    const int wm   = tid >> 5;
    const int lane = tid & 31;
    const int g    = lane >> 2;
    const int tg   = lane & 3;
    const int q0   = (gridDim.x - 1 - blockIdx.x) * ATM;
    const int bh   = blockIdx.y;
    const int b    = bh >> 4;
    const int h    = bh & 15;

    const size_t bt = (size_t)b * SEQ;
    const int hc = h * HEAD_DIM;
    const size_t vtb = (size_t)bh * HEAD_DIM * SEQ;

    const float qsc = 0.125f * 1.4426950408889634f;
    uint32_t qhi[4][4], qlo[4][4];
    {
        const float* qr0 = qg + (bt + q0 + wm * 16 + g) * N_EMBD + hc;
        const float* qr1 = qr0 + 8 * N_EMBD;
        #pragma unroll
        for (int kk = 0; kk < 4; kk++) {
            float2 e[4];
            e[0] = *(const float2*)(qr0 + kk * 16 + 2 * tg);
            e[1] = *(const float2*)(qr1 + kk * 16 + 2 * tg);
            e[2] = *(const float2*)(qr0 + kk * 16 + 2 * tg + 8);
            e[3] = *(const float2*)(qr1 + kk * 16 + 2 * tg + 8);
            #pragma unroll
            for (int i = 0; i < 4; i++)
                split_pack(e[i].x * qsc, e[i].y * qsc, qhi[kk][i], qlo[kk][i]);
        }
    }

    float o_[8][4];
    #pragma unroll
    for (int ni = 0; ni < 8; ni++)
        #pragma unroll
        for (int r = 0; r < 4; r++) o_[ni][r] = 0.f;
    float m0 = -1e30f, m1 = -1e30f, l0 = 0.f, l1 = 0.f;

    const int nt = (q0 + ATM) / ATN;

    auto stage_kv = [&](int j0, uint32_t dst) {
        #pragma unroll
        for (int i = 0; i < 2; i++) {
            int idx = tid + 256 * i;
            int r   = idx >> 3;
            int seg = idx & 7;
            const __nv_bfloat16* gk = khi + (bt + j0 + r) * N_EMBD + hc + seg * 8;
            const __nv_bfloat16* gl = klo + (bt + j0 + r) * N_EMBD + hc + seg * 8;
            cp16(dst + SKHI + r * 144 + seg * 16, gk);
            cp16(dst + SKLO + r * 144 + seg * 16, gl);
        }
        #pragma unroll
        for (int i = 0; i < 2; i++) {
            int idx = tid + 256 * i;
            int d   = idx >> 3;
            int seg = idx & 7;
            const __nv_bfloat16* gh = vthi + vtb + (size_t)d * SEQ + j0 + seg * 8;
            const __nv_bfloat16* gl = vtlo + vtb + (size_t)d * SEQ + j0 + seg * 8;
            cp16(dst + SVHI + d * 176 + seg * 16, gh);
            cp16(dst + SVLO + d * 176 + seg * 16, gl);
        }
        cp_commit();
    };

    stage_kv(0, sb);

    const int row0 = q0 + wm * 16 + g;
    const int rmax = q0 + wm * 16 + 15;

    for (int t = 0; t < nt; t++) {
        const int s = t & 1;
        const int j0 = t * ATN;
        if (t + 1 < nt) {
            stage_kv(j0 + ATN, sb + (s ^ 1) * SSTG);
            asm volatile("cp.async.wait_group 1;" ::: "memory");
        } else {
            asm volatile("cp.async.wait_group 0;" ::: "memory");
        }
        __syncthreads();

        const char* stg = asmem + s * SSTG;

        if (j0 <= rmax) {
            float sc[8][4];
            #pragma unroll
            for (int ni = 0; ni < 8; ni++)
                #pragma unroll
                for (int r = 0; r < 4; r++) sc[ni][r] = 0.f;

            #pragma unroll
            for (int kk = 0; kk < 4; kk++) {
                #pragma unroll
                for (int ni = 0; ni < 8; ni++) {
                    uint32_t off = (uint32_t)((ni * 8 + g) * 144 + kk * 32 + tg * 4);
                    uint32_t h0 = *(const uint32_t*)(stg + SKHI + off);
                    uint32_t h1 = *(const uint32_t*)(stg + SKHI + off + 16);
                    uint32_t l0r = *(const uint32_t*)(stg + SKLO + off);
                    uint32_t l1r = *(const uint32_t*)(stg + SKLO + off + 16);
                    mma_bf16(sc[ni], qhi[kk], h0, h1);
                    mma_bf16(sc[ni], qlo[kk], h0, h1);
                    mma_bf16(sc[ni], qhi[kk], l0r, l1r);
                }
            }

            if (j0 + 63 > row0) {
                #pragma unroll
                for (int ni = 0; ni < 8; ni++) {
                    #pragma unroll
                    for (int e = 0; e < 2; e++) {
                        int col = j0 + ni * 8 + 2 * tg + e;
                        if (col > row0)     sc[ni][e]     = -1e30f;
                        if (col > row0 + 8) sc[ni][2 + e] = -1e30f;
                    }
                }
            }

            float mt0 = -1e30f, mt1 = -1e30f;
            #pragma unroll
            for (int ni = 0; ni < 8; ni++) {
                mt0 = fmaxf(mt0, fmaxf(sc[ni][0], sc[ni][1]));
                mt1 = fmaxf(mt1, fmaxf(sc[ni][2], sc[ni][3]));
            }
            mt0 = fmaxf(mt0, __shfl_xor_sync(0xffffffffu, mt0, 1));
            mt0 = fmaxf(mt0, __shfl_xor_sync(0xffffffffu, mt0, 2));
            mt1 = fmaxf(mt1, __shfl_xor_sync(0xffffffffu, mt1, 1));
            mt1 = fmaxf(mt1, __shfl_xor_sync(0xffffffffu, mt1, 2));
            const float mn0 = fmaxf(m0, mt0), mn1 = fmaxf(m1, mt1);
            const float r0f = exp2f(m0 - mn0), r1f = exp2f(m1 - mn1);

            float s0 = 0.f, s1 = 0.f;
            #pragma unroll
            for (int ni = 0; ni < 8; ni++) {
                sc[ni][0] = exp2f(sc[ni][0] - mn0); s0 += sc[ni][0];
                sc[ni][1] = exp2f(sc[ni][1] - mn0); s0 += sc[ni][1];
                sc[ni][2] = exp2f(sc[ni][2] - mn1); s1 += sc[ni][2];
                sc[ni][3] = exp2f(sc[ni][3] - mn1); s1 += sc[ni][3];
            }
            s0 += __shfl_xor_sync(0xffffffffu, s0, 1);
            s0 += __shfl_xor_sync(0xffffffffu, s0, 2);
            s1 += __shfl_xor_sync(0xffffffffu, s1, 1);
            s1 += __shfl_xor_sync(0xffffffffu, s1, 2);
            l0 = l0 * r0f + s0;
            l1 = l1 * r1f + s1;
            m0 = mn0; m1 = mn1;

            #pragma unroll
            for (int ni = 0; ni < 8; ni++) {
                o_[ni][0] *= r0f; o_[ni][1] *= r0f;
                o_[ni][2] *= r1f; o_[ni][3] *= r1f;
            }

            uint32_t phi[4][4], plo[4][4];
            #pragma unroll
            for (int kk = 0; kk < 4; kk++) {
                psplit(sc[2 * kk][0],     sc[2 * kk][1],     phi[kk][0], plo[kk][0]);
                psplit(sc[2 * kk][2],     sc[2 * kk][3],     phi[kk][1], plo[kk][1]);
                psplit(sc[2 * kk + 1][0], sc[2 * kk + 1][1], phi[kk][2], plo[kk][2]);
                psplit(sc[2 * kk + 1][2], sc[2 * kk + 1][3], phi[kk][3], plo[kk][3]);
            }

            #pragma unroll
            for (int kk = 0; kk < 4; kk++) {
                #pragma unroll
                for (int ni = 0; ni < 8; ni++) {
                    uint32_t off = (uint32_t)((ni * 8 + g) * 176 + kk * 32 + tg * 4);
                    uint32_t vh0 = *(const uint32_t*)(stg + SVHI + off);
                    uint32_t vh1 = *(const uint32_t*)(stg + SVHI + off + 16);
                    uint32_t vl0 = *(const uint32_t*)(stg + SVLO + off);
                    uint32_t vl1 = *(const uint32_t*)(stg + SVLO + off + 16);
                    mma_bf16(o_[ni], phi[kk], vh0, vh1);
                    mma_bf16(o_[ni], plo[kk], vh0, vh1);
                    mma_bf16(o_[ni], phi[kk], vl0, vl1);
                }
            }
        }
        __syncthreads();
    }

    const float i0 = 1.f / l0, i1 = 1.f / l1;
    uint32_t* op0 = ot + (bt + q0 + wm * 16 + g) * N_EMBD + hc;
    uint32_t* op1 = op0 + 8 * N_EMBD;
    #pragma unroll
    for (int ni = 0; ni < 8; ni++) {
        uint2 w0, w1;
        asm("cvt.rna.tf32.f32 %0, %1;" : "=r"(w0.x) : "f"(o_[ni][0] * i0));
        asm("cvt.rna.tf32.f32 %0, %1;" : "=r"(w0.y) : "f"(o_[ni][1] * i0));
        asm("cvt.rna.tf32.f32 %0, %1;" : "=r"(w1.x) : "f"(o_[ni][2] * i1));
        asm("cvt.rna.tf32.f32 %0, %1;" : "=r"(w1.y) : "f"(o_[ni][3] * i1));
        *(uint2*)(op0 + ni * 8 + 2 * tg) = w0;
        *(uint2*)(op1 + ni * 8 + 2 * tg) = w1;
    }
}

// ---------------- launch ----------------
extern "C" void kernel_launch(void* const* d_in, const int* in_sizes, int n_in,
                              void* d_out, int out_size)
{
    const float* x  = (const float*)d_in[0];
    const float* Wq = (const float*)d_in[1];
    const float* bq = (const float*)d_in[2];
    const float* Wk = (const float*)d_in[3];
    const float* bk = (const float*)d_in[4];
    const float* Wv = (const float*)d_in[5];
    const float* bv = (const float*)d_in[6];
    const float* Wo = (const float*)d_in[7];
    const float* bo = (const float*)d_in[8];
    float* out = (float*)d_out;

    float *qp;
    uint32_t *xt, *wt;
    __nv_bfloat16 *khi, *klo, *vthi, *vtlo;
    cudaGetSymbolAddress((void**)&qp, g_q);
    cudaGetSymbolAddress((void**)&xt, g_xt);
    cudaGetSymbolAddress((void**)&wt, g_wt);
    cudaGetSymbolAddress((void**)&khi, g_khi);
    cudaGetSymbolAddress((void**)&klo, g_klo);
    cudaGetSymbolAddress((void**)&vthi, g_vthi);
    cudaGetSymbolAddress((void**)&vtlo, g_vtlo);

    cudaFuncSetAttribute(qkv_gemm_kernel, cudaFuncAttributeMaxDynamicSharedMemorySize, GSMEM);
    cudaFuncSetAttribute(gemm_tc_kernel, cudaFuncAttributeMaxDynamicSharedMemorySize, GSMEM);
    cudaFuncSetAttribute(attn_tc_kernel, cudaFuncAttributeMaxDynamicSharedMemorySize, ASMEM);

    const int nx4 = M_TOT * N_EMBD / 4;      // 1048576

    // 1. activations -> tf32
    tf32_cvt_kernel<<<nx4 / 256, 256>>>(x, xt, nx4);
    // 2. all 4 weights -> tf32 planes
    wcvt4_kernel<<<4 * (WPLANE / 4) / 256, 256>>>(Wq, Wk, Wv, Wo, wt);

    // 3. merged Q/K/V projections (V written transposed as bf16 planes)
    dim3 qkvgrid(8, 32, 3);
    qkv_gemm_kernel<<<qkvgrid, 256, GSMEM>>>(xt, wt, bq, bk, bv,
                                             qp, khi, klo, vthi, vtlo);

    // 4. attention (writes tf32 att directly into xt)
    dim3 agrid(SEQ / ATM, BATCH * N_HEAD);   // (16, 32)
    attn_tc_kernel<<<agrid, 256, ASMEM>>>(qp, khi, klo, vthi, vtlo, xt);

    // 5. output projection
    dim3 ggrid(N_EMBD / CTN, M_TOT / CTM);   // (8, 32)
    gemm_tc_kernel<<<ggrid, 256, GSMEM>>>(xt, wt + 3 * WPLANE, bo, out, N_EMBD);
}

// round 17
// speedup vs baseline: 6.2564x; 1.0346x over previous
#include <cuda_runtime.h>
#include <cuda_bf16.h>
#include <math.h>
#include <stdint.h>

#define N_EMBD   1024
#define N_HEAD   16
#define HEAD_DIM 64
#define BATCH    2
#define SEQ      2048
#define M_TOT    (BATCH * SEQ)
#define WPLANE   (N_EMBD * N_EMBD)   // u32 per weight plane

typedef unsigned long long u64;

// ---------------- cp.async helpers ----------------
__device__ __forceinline__ uint32_t smem_u32(const void* p) {
    uint32_t a;
    asm("{ .reg .u64 t; cvta.to.shared.u64 t, %1; cvt.u32.u64 %0, t; }" : "=r"(a) : "l"(p));
    return a;
}
__device__ __forceinline__ void cp16(uint32_t s, const void* g) {
    asm volatile("cp.async.cg.shared.global [%0], [%1], 16;" :: "r"(s), "l"(g));
}
__device__ __forceinline__ void cp_commit() {
    asm volatile("cp.async.commit_group;" ::: "memory");
}

// ---------------- bf16 split/pack ----------------
__device__ __forceinline__ void split_pack(float x0, float x1, uint32_t& hi, uint32_t& lo) {
    __nv_bfloat16 h0 = __float2bfloat16_rn(x0), h1 = __float2bfloat16_rn(x1);
    __nv_bfloat16 l0 = __float2bfloat16_rn(x0 - __bfloat162float(h0));
    __nv_bfloat16 l1 = __float2bfloat16_rn(x1 - __bfloat162float(h1));
    hi = (uint32_t)__bfloat16_as_ushort(h0) | ((uint32_t)__bfloat16_as_ushort(h1) << 16);
    lo = (uint32_t)__bfloat16_as_ushort(l0) | ((uint32_t)__bfloat16_as_ushort(l1) << 16);
}

// fast truncation split for nonneg P in [0,1]
__device__ __forceinline__ void psplit(float x0, float x1, uint32_t& hi, uint32_t& lo) {
    uint32_t u0 = __float_as_uint(x0), u1 = __float_as_uint(x1);
    asm("prmt.b32 %0, %1, %2, 0x7632;" : "=r"(hi) : "r"(u0), "r"(u1));
    float l0 = x0 - __uint_as_float(u0 & 0xFFFF0000u);
    float l1 = x1 - __uint_as_float(u1 & 0xFFFF0000u);
    asm("cvt.rn.bf16x2.f32 %0, %1, %2;" : "=r"(lo) : "f"(l1), "f"(l0));
}

// ---------------- scratch (device globals: allocation-free) ----------------
__device__ float g_q[(size_t)M_TOT * N_EMBD];
__device__ uint32_t g_xt[(size_t)M_TOT * N_EMBD];
__device__ uint32_t g_wt[(size_t)4 * WPLANE];
__device__ __nv_bfloat16 g_khi[(size_t)M_TOT * N_EMBD];
__device__ __nv_bfloat16 g_klo[(size_t)M_TOT * N_EMBD];
__device__ __nv_bfloat16 g_vthi[(size_t)M_TOT * N_EMBD];
__device__ __nv_bfloat16 g_vtlo[(size_t)M_TOT * N_EMBD];

// ---------------- fp32 -> tf32 (rna) pre-pass ----------------
__global__ __launch_bounds__(256) void tf32_cvt_kernel(
    const float* __restrict__ src, uint32_t* __restrict__ dst, int n4)
{
    int i = blockIdx.x * blockDim.x + threadIdx.x;
    if (i >= n4) return;
    float4 v = ((const float4*)src)[i];
    uint4 o;
    asm("cvt.rna.tf32.f32 %0, %1;" : "=r"(o.x) : "f"(v.x));
    asm("cvt.rna.tf32.f32 %0, %1;" : "=r"(o.y) : "f"(v.y));
    asm("cvt.rna.tf32.f32 %0, %1;" : "=r"(o.z) : "f"(v.z));
    asm("cvt.rna.tf32.f32 %0, %1;" : "=r"(o.w) : "f"(v.w));
    ((uint4*)dst)[i] = o;
}

__global__ __launch_bounds__(256) void wcvt4_kernel(
    const float* __restrict__ s0, const float* __restrict__ s1,
    const float* __restrict__ s2, const float* __restrict__ s3,
    uint32_t* __restrict__ dst)
{
    int i = blockIdx.x * blockDim.x + threadIdx.x;
    int plane = i >> 18;
    int j = i & 0x3FFFF;
    const float* src = (plane == 0) ? s0 : (plane == 1) ? s1 : (plane == 2) ? s2 : s3;
    float4 v = ((const float4*)src)[j];
    uint4 o;
    asm("cvt.rna.tf32.f32 %0, %1;" : "=r"(o.x) : "f"(v.x));
    asm("cvt.rna.tf32.f32 %0, %1;" : "=r"(o.y) : "f"(v.y));
    asm("cvt.rna.tf32.f32 %0, %1;" : "=r"(o.z) : "f"(v.z));
    asm("cvt.rna.tf32.f32 %0, %1;" : "=r"(o.w) : "f"(v.w));
    ((uint4*)dst)[i] = o;
}

// ================= tf32 mma.sync GEMM machinery ============================
#define CTM 128
#define CTN 128
#define CBK 32
#define NCH (N_EMBD / CBK)
#define STW 4096
#define GSMEM (4 * STW * 4)

__device__ __forceinline__ void mma_tf32(float* c, const uint32_t* a,
                                         uint32_t b0, uint32_t b1) {
    asm volatile(
        "mma.sync.aligned.m16n8k8.row.col.f32.tf32.tf32.f32 "
        "{%0,%1,%2,%3}, {%4,%5,%6,%7}, {%8,%9}, {%0,%1,%2,%3};"
        : "+f"(c[0]), "+f"(c[1]), "+f"(c[2]), "+f"(c[3])
        : "r"(a[0]), "r"(a[1]), "r"(a[2]), "r"(a[3]), "r"(b0), "r"(b1));
}

__device__ __forceinline__ void load_op(const uint32_t* __restrict__ g,
                                        int rowbase, int kc,
                                        uint32_t sm_t, int tid)
{
    #pragma unroll
    for (int j = 0; j < 4; j++) {
        int idx = tid + 256 * j;
        int row = idx >> 3;
        int k4  = idx & 7;
        const void* gp = g + (size_t)(rowbase + row) * N_EMBD + kc * CBK + k4 * 4;
        uint32_t w = row * 32 + ((k4 * 4) ^ ((row & 7) * 4));
        cp16(sm_t + w * 4, gp);
    }
}

__device__ __forceinline__ void gemm_mainloop(
    const uint32_t* __restrict__ A, const uint32_t* __restrict__ B,
    int m0, int n0, uint32_t sb, uint32_t* gsm_base,
    int tid, int wm, int wn, int g, int tg, float acc[2][8][4])
{
    const int xr = 4 * g;
    uint32_t sA[2] = {sb, sb + STW * 4};
    uint32_t sB[2] = {sb + 2 * STW * 4, sb + 3 * STW * 4};

    #pragma unroll
    for (int c = 0; c < 2; c++) {
        load_op(A, m0, c, sA[c], tid);
        load_op(B, n0, c, sB[c], tid);
        cp_commit();
    }

    for (int c = 0; c < NCH; c++) {
        const int s = c & 1;
        if (c == NCH - 1) asm volatile("cp.async.wait_group 0;" ::: "memory");
        else              asm volatile("cp.async.wait_group 1;" ::: "memory");
        __syncthreads();

        const uint32_t* As = gsm_base + (sA[s] - sb) / 4;
        const uint32_t* Bs = gsm_base + (sB[s] - sb) / 4;

        #pragma unroll
        for (int kk = 0; kk < 4; kk++) {
            const int k = kk * 8;
            const int x0 = (k + tg) ^ xr;
            const int x1 = (k + tg + 4) ^ xr;

            uint32_t a[2][4];
            #pragma unroll
            for (int mi = 0; mi < 2; mi++) {
                const uint32_t* base = As + (wm * 32 + mi * 16 + g) * 32;
                a[mi][0] = base[x0];
                a[mi][1] = base[256 + x0];
                a[mi][2] = base[x1];
                a[mi][3] = base[256 + x1];
            }
            #pragma unroll
            for (int ni = 0; ni < 8; ni++) {
                const uint32_t* bb = Bs + (wn * 64 + ni * 8 + g) * 32;
                uint32_t b0 = bb[x0];
                uint32_t b1 = bb[x1];
                mma_tf32(acc[0][ni], a[0], b0, b1);
                mma_tf32(acc[1][ni], a[1], b0, b1);
            }
        }
        __syncthreads();

        if (c + 2 < NCH) {
            load_op(A, m0, c + 2, sA[s], tid);
            load_op(B, n0, c + 2, sB[s], tid);
            cp_commit();
        }
    }
}

// ---- merged QKV GEMM: z=0 -> Q (f32), z=1 -> K (bf16 planes), z=2 -> V^T --
__global__ __launch_bounds__(256) void qkv_gemm_kernel(
    const uint32_t* __restrict__ xt, const uint32_t* __restrict__ wt,
    const float* __restrict__ bq, const float* __restrict__ bk,
    const float* __restrict__ bv,
    float* __restrict__ qp,
    __nv_bfloat16* __restrict__ khi, __nv_bfloat16* __restrict__ klo,
    __nv_bfloat16* __restrict__ vthi, __nv_bfloat16* __restrict__ vtlo)
{
    extern __shared__ __align__(16) uint32_t gsm[];
    const uint32_t sb = smem_u32(gsm);
    const int tid  = threadIdx.x;
    const int wid  = tid >> 5;
    const int lane = tid & 31;
    const int g  = lane >> 2;
    const int tg = lane & 3;
    const int wm = wid >> 1;
    const int wn = wid & 1;
    const int z  = blockIdx.z;

    const uint32_t* A;
    const uint32_t* B;
    int m0, n0;
    if (z == 2) {   // V transposed: A = Wv, B = x
        A = wt + 2 * WPLANE; B = xt;
        m0 = blockIdx.x * 128;
        n0 = blockIdx.y * 128;
    } else {
        A = xt; B = wt + z * WPLANE;
        m0 = blockIdx.y * CTM;
        n0 = blockIdx.x * CTN;
    }

    float acc[2][8][4];
    #pragma unroll
    for (int mi = 0; mi < 2; mi++)
        #pragma unroll
        for (int ni = 0; ni < 8; ni++)
            #pragma unroll
            for (int r = 0; r < 4; r++) acc[mi][ni][r] = 0.f;

    gemm_mainloop(A, B, m0, n0, sb, gsm, tid, wm, wn, g, tg, acc);

    if (z == 0) {
        #pragma unroll
        for (int mi = 0; mi < 2; mi++) {
            const int r0 = m0 + wm * 32 + mi * 16 + g;
            #pragma unroll
            for (int ni = 0; ni < 8; ni++) {
                const int col = n0 + wn * 64 + ni * 8 + 2 * tg;
                float b0v = bq[col], b1v = bq[col + 1];
                *(float2*)&qp[(size_t)r0 * N_EMBD + col] =
                    make_float2(acc[mi][ni][0] + b0v, acc[mi][ni][1] + b1v);
                *(float2*)&qp[(size_t)(r0 + 8) * N_EMBD + col] =
                    make_float2(acc[mi][ni][2] + b0v, acc[mi][ni][3] + b1v);
            }
        }
    } else if (z == 1) {
        #pragma unroll
        for (int mi = 0; mi < 2; mi++) {
            const int r0 = m0 + wm * 32 + mi * 16 + g;
            #pragma unroll
            for (int ni = 0; ni < 8; ni++) {
                const int col = n0 + wn * 64 + ni * 8 + 2 * tg;
                float b0v = bk[col], b1v = bk[col + 1];
                uint32_t h, l;
                split_pack(acc[mi][ni][0] + b0v, acc[mi][ni][1] + b1v, h, l);
                *(uint32_t*)&khi[(size_t)r0 * N_EMBD + col] = h;
                *(uint32_t*)&klo[(size_t)r0 * N_EMBD + col] = l;
                split_pack(acc[mi][ni][2] + b0v, acc[mi][ni][3] + b1v, h, l);
                *(uint32_t*)&khi[(size_t)(r0 + 8) * N_EMBD + col] = h;
                *(uint32_t*)&klo[(size_t)(r0 + 8) * N_EMBD + col] = l;
            }
        }
    } else {
        #pragma unroll
        for (int mi = 0; mi < 2; mi++) {
            const int r0 = m0 + wm * 32 + mi * 16 + g;     // output dim
            const float bv0 = bv[r0], bv1 = bv[r0 + 8];
            const int h = r0 >> 6, d = r0 & 63;
            #pragma unroll
            for (int ni = 0; ni < 8; ni++) {
                const int col = n0 + wn * 64 + ni * 8 + 2 * tg;   // token
                const int b = col >> 11, t = col & 2047;
                size_t base0 = (((size_t)(b * 16 + h)) * 64 + d) * SEQ + t;
                uint32_t hv, lv;
                split_pack(acc[mi][ni][0] + bv0, acc[mi][ni][1] + bv0, hv, lv);
                *(uint32_t*)&vthi[base0] = hv;
                *(uint32_t*)&vtlo[base0] = lv;
                split_pack(acc[mi][ni][2] + bv1, acc[mi][ni][3] + bv1, hv, lv);
                *(uint32_t*)&vthi[base0 + 8 * SEQ] = hv;
                *(uint32_t*)&vtlo[base0 + 8 * SEQ] = lv;
            }
        }
    }
}

// ---- plain f32 GEMM (final O projection) ----
__global__ __launch_bounds__(256) void gemm_tc_kernel(
    const uint32_t* __restrict__ A, const uint32_t* __restrict__ B,
    const float* __restrict__ bias, float* __restrict__ C, int N)
{
    extern __shared__ __align__(16) uint32_t gsm[];
    const uint32_t sb = smem_u32(gsm);
    const int tid  = threadIdx.x;
    const int wid  = tid >> 5;
    const int lane = tid & 31;
    const int g  = lane >> 2;
    const int tg = lane & 3;
    const int wm = wid >> 1;
    const int wn = wid & 1;
    const int m0 = blockIdx.y * CTM;
    const int n0 = blockIdx.x * CTN;

    float acc[2][8][4];
    #pragma unroll
    for (int mi = 0; mi < 2; mi++)
        #pragma unroll
        for (int ni = 0; ni < 8; ni++)
            #pragma unroll
            for (int r = 0; r < 4; r++) acc[mi][ni][r] = 0.f;

    gemm_mainloop(A, B, m0, n0, sb, gsm, tid, wm, wn, g, tg, acc);

    #pragma unroll
    for (int mi = 0; mi < 2; mi++) {
        const int r0 = m0 + wm * 32 + mi * 16 + g;
        #pragma unroll
        for (int ni = 0; ni < 8; ni++) {
            const int col = n0 + wn * 64 + ni * 8 + 2 * tg;
            float b0v = bias[col], b1v = bias[col + 1];
            *(float2*)&C[(size_t)r0 * N + col] =
                make_float2(acc[mi][ni][0] + b0v, acc[mi][ni][1] + b1v);
            *(float2*)&C[(size_t)(r0 + 8) * N + col] =
                make_float2(acc[mi][ni][2] + b0v, acc[mi][ni][3] + b1v);
        }
    }
}

// ================= tensor-core causal flash attention ======================
// Register-capped for 2 CTAs/SM: __launch_bounds__(256, 2); P-split is
// per-kk transient (ph[4]/pl[4]) instead of persistent phi/plo[4][4].
#define ATM 128
#define ATN 64
#define SKHI  0
#define SKLO  9216
#define SVHI  18432
#define SVLO  29696
#define SSTG  40960
#define ASMEM (2 * SSTG)   // 81920

__device__ __forceinline__ void mma_bf16(float* c, const uint32_t* a,
                                         uint32_t b0, uint32_t b1) {
    asm volatile(
        "mma.sync.aligned.m16n8k16.row.col.f32.bf16.bf16.f32 "
        "{%0,%1,%2,%3}, {%4,%5,%6,%7}, {%8,%9}, {%0,%1,%2,%3};"
        : "+f"(c[0]), "+f"(c[1]), "+f"(c[2]), "+f"(c[3])
        : "r"(a[0]), "r"(a[1]), "r"(a[2]), "r"(a[3]), "r"(b0), "r"(b1));
}

__global__ __launch_bounds__(256, 2) void attn_tc_kernel(
    const float* __restrict__ qg,
    const __nv_bfloat16* __restrict__ khi, const __nv_bfloat16* __restrict__ klo,
    const __nv_bfloat16* __restrict__ vthi, const __nv_bfloat16* __restrict__ vtlo,
    uint32_t* __restrict__ ot)
{
    extern __shared__ __align__(16) char asmem[];
    const uint32_t sb = smem_u32(asmem);
    const int tid  = threadIdx.x;
    const int wm   = tid >> 5;
    const int lane = tid & 31;
    const int g    = lane >> 2;
    const int tg   = lane & 3;
    const int q0   = (gridDim.x - 1 - blockIdx.x) * ATM;
    const int bh   = blockIdx.y;
    const int b    = bh >> 4;
    const int h    = bh & 15;

    const size_t bt = (size_t)b * SEQ;
    const int hc = h * HEAD_DIM;
    const size_t vtb = (size_t)bh * HEAD_DIM * SEQ;

    const float qsc = 0.125f * 1.4426950408889634f;
    uint32_t qhi[4][4], qlo[4][4];
    {
        const float* qr0 = qg + (bt + q0 + wm * 16 + g) * N_EMBD + hc;
        const float* qr1 = qr0 + 8 * N_EMBD;
        #pragma unroll
        for (int kk = 0; kk < 4; kk++) {
            float2 e[4];
            e[0] = *(const float2*)(qr0 + kk * 16 + 2 * tg);
            e[1] = *(const float2*)(qr1 + kk * 16 + 2 * tg);
            e[2] = *(const float2*)(qr0 + kk * 16 + 2 * tg + 8);
            e[3] = *(const float2*)(qr1 + kk * 16 + 2 * tg + 8);
            #pragma unroll
            for (int i = 0; i < 4; i++)
                split_pack(e[i].x * qsc, e[i].y * qsc, qhi[kk][i], qlo[kk][i]);
        }
    }

    float o_[8][4];
    #pragma unroll
    for (int ni = 0; ni < 8; ni++)
        #pragma unroll
        for (int r = 0; r < 4; r++) o_[ni][r] = 0.f;
    float m0 = -1e30f, m1 = -1e30f, l0 = 0.f, l1 = 0.f;

    const int nt = (q0 + ATM) / ATN;

    auto stage_kv = [&](int j0, uint32_t dst) {
        #pragma unroll
        for (int i = 0; i < 2; i++) {
            int idx = tid + 256 * i;
            int r   = idx >> 3;
            int seg = idx & 7;
            const __nv_bfloat16* gk = khi + (bt + j0 + r) * N_EMBD + hc + seg * 8;
            const __nv_bfloat16* gl = klo + (bt + j0 + r) * N_EMBD + hc + seg * 8;
            cp16(dst + SKHI + r * 144 + seg * 16, gk);
            cp16(dst + SKLO + r * 144 + seg * 16, gl);
        }
        #pragma unroll
        for (int i = 0; i < 2; i++) {
            int idx = tid + 256 * i;
            int d   = idx >> 3;
            int seg = idx & 7;
            const __nv_bfloat16* gh = vthi + vtb + (size_t)d * SEQ + j0 + seg * 8;
            const __nv_bfloat16* gl = vtlo + vtb + (size_t)d * SEQ + j0 + seg * 8;
            cp16(dst + SVHI + d * 176 + seg * 16, gh);
            cp16(dst + SVLO + d * 176 + seg * 16, gl);
        }
        cp_commit();
    };

    stage_kv(0, sb);

    const int row0 = q0 + wm * 16 + g;
    const int rmax = q0 + wm * 16 + 15;

    for (int t = 0; t < nt; t++) {
        const int s = t & 1;
        const int j0 = t * ATN;
        if (t + 1 < nt) {
            stage_kv(j0 + ATN, sb + (s ^ 1) * SSTG);
            asm volatile("cp.async.wait_group 1;" ::: "memory");
        } else {
            asm volatile("cp.async.wait_group 0;" ::: "memory");
        }
        __syncthreads();

        const char* stg = asmem + s * SSTG;

        if (j0 <= rmax) {
            float sc[8][4];
            #pragma unroll
            for (int ni = 0; ni < 8; ni++)
                #pragma unroll
                for (int r = 0; r < 4; r++) sc[ni][r] = 0.f;

            #pragma unroll
            for (int kk = 0; kk < 4; kk++) {
                #pragma unroll
                for (int ni = 0; ni < 8; ni++) {
                    uint32_t off = (uint32_t)((ni * 8 + g) * 144 + kk * 32 + tg * 4);
                    uint32_t h0 = *(const uint32_t*)(stg + SKHI + off);
                    uint32_t h1 = *(const uint32_t*)(stg + SKHI + off + 16);
                    uint32_t l0r = *(const uint32_t*)(stg + SKLO + off);
                    uint32_t l1r = *(const uint32_t*)(stg + SKLO + off + 16);
                    mma_bf16(sc[ni], qhi[kk], h0, h1);
                    mma_bf16(sc[ni], qlo[kk], h0, h1);
                    mma_bf16(sc[ni], qhi[kk], l0r, l1r);
                }
            }

            if (j0 + 63 > row0) {
                #pragma unroll
                for (int ni = 0; ni < 8; ni++) {
                    #pragma unroll
                    for (int e = 0; e < 2; e++) {
                        int col = j0 + ni * 8 + 2 * tg + e;
                        if (col > row0)     sc[ni][e]     = -1e30f;
                        if (col > row0 + 8) sc[ni][2 + e] = -1e30f;
                    }
                }
            }

            float mt0 = -1e30f, mt1 = -1e30f;
            #pragma unroll
            for (int ni = 0; ni < 8; ni++) {
                mt0 = fmaxf(mt0, fmaxf(sc[ni][0], sc[ni][1]));
                mt1 = fmaxf(mt1, fmaxf(sc[ni][2], sc[ni][3]));
            }
            mt0 = fmaxf(mt0, __shfl_xor_sync(0xffffffffu, mt0, 1));
            mt0 = fmaxf(mt0, __shfl_xor_sync(0xffffffffu, mt0, 2));
            mt1 = fmaxf(mt1, __shfl_xor_sync(0xffffffffu, mt1, 1));
            mt1 = fmaxf(mt1, __shfl_xor_sync(0xffffffffu, mt1, 2));
            const float mn0 = fmaxf(m0, mt0), mn1 = fmaxf(m1, mt1);
            const float r0f = exp2f(m0 - mn0), r1f = exp2f(m1 - mn1);

            float s0 = 0.f, s1 = 0.f;
            #pragma unroll
            for (int ni = 0; ni < 8; ni++) {
                sc[ni][0] = exp2f(sc[ni][0] - mn0); s0 += sc[ni][0];
                sc[ni][1] = exp2f(sc[ni][1] - mn0); s0 += sc[ni][1];
                sc[ni][2] = exp2f(sc[ni][2] - mn1); s1 += sc[ni][2];
                sc[ni][3] = exp2f(sc[ni][3] - mn1); s1 += sc[ni][3];
            }
            s0 += __shfl_xor_sync(0xffffffffu, s0, 1);
            s0 += __shfl_xor_sync(0xffffffffu, s0, 2);
            s1 += __shfl_xor_sync(0xffffffffu, s1, 1);
            s1 += __shfl_xor_sync(0xffffffffu, s1, 2);
            l0 = l0 * r0f + s0;
            l1 = l1 * r1f + s1;
            m0 = mn0; m1 = mn1;

            #pragma unroll
            for (int ni = 0; ni < 8; ni++) {
                o_[ni][0] *= r0f; o_[ni][1] *= r0f;
                o_[ni][2] *= r1f; o_[ni][3] *= r1f;
            }

            // PV: per-kk transient P fragments (register cap for 2 CTAs/SM)
            #pragma unroll
            for (int kk = 0; kk < 4; kk++) {
                uint32_t ph[4], pl[4];
                psplit(sc[2 * kk][0],     sc[2 * kk][1],     ph[0], pl[0]);
                psplit(sc[2 * kk][2],     sc[2 * kk][3],     ph[1], pl[1]);
                psplit(sc[2 * kk + 1][0], sc[2 * kk + 1][1], ph[2], pl[2]);
                psplit(sc[2 * kk + 1][2], sc[2 * kk + 1][3], ph[3], pl[3]);
                #pragma unroll
                for (int ni = 0; ni < 8; ni++) {
                    uint32_t off = (uint32_t)((ni * 8 + g) * 176 + kk * 32 + tg * 4);
                    uint32_t vh0 = *(const uint32_t*)(stg + SVHI + off);
                    uint32_t vh1 = *(const uint32_t*)(stg + SVHI + off + 16);
                    uint32_t vl0 = *(const uint32_t*)(stg + SVLO + off);
                    uint32_t vl1 = *(const uint32_t*)(stg + SVLO + off + 16);
                    mma_bf16(o_[ni], ph, vh0, vh1);
                    mma_bf16(o_[ni], pl, vh0, vh1);
                    mma_bf16(o_[ni], ph, vl0, vl1);
                }
            }
        }
        __syncthreads();
    }

    const float i0 = 1.f / l0, i1 = 1.f / l1;
    uint32_t* op0 = ot + (bt + q0 + wm * 16 + g) * N_EMBD + hc;
    uint32_t* op1 = op0 + 8 * N_EMBD;
    #pragma unroll
    for (int ni = 0; ni < 8; ni++) {
        uint2 w0, w1;
        asm("cvt.rna.tf32.f32 %0, %1;" : "=r"(w0.x) : "f"(o_[ni][0] * i0));
        asm("cvt.rna.tf32.f32 %0, %1;" : "=r"(w0.y) : "f"(o_[ni][1] * i0));
        asm("cvt.rna.tf32.f32 %0, %1;" : "=r"(w1.x) : "f"(o_[ni][2] * i1));
        asm("cvt.rna.tf32.f32 %0, %1;" : "=r"(w1.y) : "f"(o_[ni][3] * i1));
        *(uint2*)(op0 + ni * 8 + 2 * tg) = w0;
        *(uint2*)(op1 + ni * 8 + 2 * tg) = w1;
    }
}

// ---------------- launch ----------------
extern "C" void kernel_launch(void* const* d_in, const int* in_sizes, int n_in,
                              void* d_out, int out_size)
{
    const float* x  = (const float*)d_in[0];
    const float* Wq = (const float*)d_in[1];
    const float* bq = (const float*)d_in[2];
    const float* Wk = (const float*)d_in[3];
    const float* bk = (const float*)d_in[4];
    const float* Wv = (const float*)d_in[5];
    const float* bv = (const float*)d_in[6];
    const float* Wo = (const float*)d_in[7];
    const float* bo = (const float*)d_in[8];
    float* out = (float*)d_out;

    float *qp;
    uint32_t *xt, *wt;
    __nv_bfloat16 *khi, *klo, *vthi, *vtlo;
    cudaGetSymbolAddress((void**)&qp, g_q);
    cudaGetSymbolAddress((void**)&xt, g_xt);
    cudaGetSymbolAddress((void**)&wt, g_wt);
    cudaGetSymbolAddress((void**)&khi, g_khi);
    cudaGetSymbolAddress((void**)&klo, g_klo);
    cudaGetSymbolAddress((void**)&vthi, g_vthi);
    cudaGetSymbolAddress((void**)&vtlo, g_vtlo);

    cudaFuncSetAttribute(qkv_gemm_kernel, cudaFuncAttributeMaxDynamicSharedMemorySize, GSMEM);
    cudaFuncSetAttribute(gemm_tc_kernel, cudaFuncAttributeMaxDynamicSharedMemorySize, GSMEM);
    cudaFuncSetAttribute(attn_tc_kernel, cudaFuncAttributeMaxDynamicSharedMemorySize, ASMEM);

    const int nx4 = M_TOT * N_EMBD / 4;

    tf32_cvt_kernel<<<nx4 / 256, 256>>>(x, xt, nx4);
    wcvt4_kernel<<<4 * (WPLANE / 4) / 256, 256>>>(Wq, Wk, Wv, Wo, wt);

    dim3 qkvgrid(8, 32, 3);
    qkv_gemm_kernel<<<qkvgrid, 256, GSMEM>>>(xt, wt, bq, bk, bv,
                                             qp, khi, klo, vthi, vtlo);

    dim3 agrid(SEQ / ATM, BATCH * N_HEAD);   // (16, 32)
    attn_tc_kernel<<<agrid, 256, ASMEM>>>(qp, khi, klo, vthi, vtlo, xt);

    dim3 ggrid(N_EMBD / CTN, M_TOT / CTM);   // (8, 32)
    gemm_tc_kernel<<<ggrid, 256, GSMEM>>>(xt, wt + 3 * WPLANE, bo, out, N_EMBD);
}